// round 1
// baseline (speedup 1.0000x reference)
#include <cuda_runtime.h>

static constexpr int kB  = 4;
static constexpr int kS  = 1024;
static constexpr int kDM = 1024;
static constexpr int kH  = 16;
static constexpr int kDK = 64;
static constexpr int kBH = kB * kH;   // 64
static constexpr int kM  = kB * kS;   // 4096

// ---------------- scratch (static device globals; no allocation) ----------------
__device__ float g_qh [kBH * kS * kDK];
__device__ float g_kh [kBH * kS * kDK];
__device__ float g_vh [kBH * kS * kDK];
__device__ float g_kr [kBH * kS * kDK];
__device__ float g_q1a[kBH * kS * kDK];
__device__ float g_q1 [kBH * kS * kDK];
__device__ float g_q2 [kBH * kS * kDK];
__device__ float g_vr [kBH * kS * kDK];
__device__ float g_att[kB * kS * kDM];

// ---------------------------------------------------------------------------
// Big GEMM: C[m][n] = sum_k A[m][k] * W[n][k] + bias[n]
// M=4096, N=1024, K=1024. 128x128 tile, 256 threads, 8x8 micro-tile.
// mode 0: out[m*1024 + n]            (row-major, final O projection)
// mode 1: out[((b*H+h)*S+s)*64 + d]  (head-split layout for q/k/v)
// ---------------------------------------------------------------------------
__global__ __launch_bounds__(256)
void sgemm128(const float* __restrict__ A, const float* __restrict__ W,
              const float* __restrict__ bias, float* __restrict__ out, int mode)
{
    __shared__ float As[16][128];   // [k][m]
    __shared__ float Bs[16][128];   // [k][n]
    const int t  = threadIdx.x;
    const int tx = t & 15, ty = t >> 4;
    const int m0 = blockIdx.y * 128;
    const int n0 = blockIdx.x * 128;
    const int lm = t & 127;
    const int kb = (t >> 7) * 8;

    float acc[8][8];
    #pragma unroll
    for (int i = 0; i < 8; i++)
        #pragma unroll
        for (int j = 0; j < 8; j++) acc[i][j] = 0.f;

    for (int k0 = 0; k0 < 1024; k0 += 16) {
        const float4* Ag = (const float4*)(A + (size_t)(m0 + lm) * 1024 + k0 + kb);
        const float4* Wg = (const float4*)(W + (size_t)(n0 + lm) * 1024 + k0 + kb);
        float4 a0 = Ag[0], a1 = Ag[1];
        float4 b0 = Wg[0], b1 = Wg[1];
        As[kb+0][lm]=a0.x; As[kb+1][lm]=a0.y; As[kb+2][lm]=a0.z; As[kb+3][lm]=a0.w;
        As[kb+4][lm]=a1.x; As[kb+5][lm]=a1.y; As[kb+6][lm]=a1.z; As[kb+7][lm]=a1.w;
        Bs[kb+0][lm]=b0.x; Bs[kb+1][lm]=b0.y; Bs[kb+2][lm]=b0.z; Bs[kb+3][lm]=b0.w;
        Bs[kb+4][lm]=b1.x; Bs[kb+5][lm]=b1.y; Bs[kb+6][lm]=b1.z; Bs[kb+7][lm]=b1.w;
        __syncthreads();
        #pragma unroll
        for (int kk = 0; kk < 16; kk++) {
            float af[8], bf[8];
            #pragma unroll
            for (int i = 0; i < 8; i++) af[i] = As[kk][ty + 16*i];
            #pragma unroll
            for (int j = 0; j < 8; j++) bf[j] = Bs[kk][tx + 16*j];
            #pragma unroll
            for (int i = 0; i < 8; i++)
                #pragma unroll
                for (int j = 0; j < 8; j++) acc[i][j] += af[i] * bf[j];
        }
        __syncthreads();
    }

    #pragma unroll
    for (int i = 0; i < 8; i++) {
        const int r = m0 + ty + 16*i;
        #pragma unroll
        for (int j = 0; j < 8; j++) {
            const int c = n0 + tx + 16*j;
            float v = acc[i][j] + bias[c];
            if (mode == 0) {
                out[(size_t)r * 1024 + c] = v;
            } else {
                int b = r >> 10, s = r & 1023, h = c >> 6, d = c & 63;
                out[(((size_t)(b * kH + h)) * kS + s) * kDK + d] = v;
            }
        }
    }
}

// ---------------------------------------------------------------------------
// Small linear: Y = relu(X @ W^T + b), X:[R,64], W:[64,64]. 64 rows per block.
// ---------------------------------------------------------------------------
__global__ __launch_bounds__(256)
void small_linear(const float* __restrict__ X, const float* __restrict__ W,
                  const float* __restrict__ bias, float* __restrict__ out)
{
    __shared__ float Xs[64*64];   // [k][m]
    __shared__ float Ws[64*64];   // [k][n]
    const int t  = threadIdx.x;
    const int tx = t & 15, ty = t >> 4;
    const int r0 = blockIdx.x * 64;
    const int lr = t & 63;
    const int kb = (t >> 6) * 16;

    #pragma unroll
    for (int q = 0; q < 4; q++) {
        float4 w = *(const float4*)(W + (size_t)lr * 64 + kb + 4*q);
        Ws[(kb+4*q+0)*64 + lr] = w.x;
        Ws[(kb+4*q+1)*64 + lr] = w.y;
        Ws[(kb+4*q+2)*64 + lr] = w.z;
        Ws[(kb+4*q+3)*64 + lr] = w.w;
        float4 x = *(const float4*)(X + (size_t)(r0 + lr) * 64 + kb + 4*q);
        Xs[(kb+4*q+0)*64 + lr] = x.x;
        Xs[(kb+4*q+1)*64 + lr] = x.y;
        Xs[(kb+4*q+2)*64 + lr] = x.z;
        Xs[(kb+4*q+3)*64 + lr] = x.w;
    }
    __syncthreads();

    float acc[4][4];
    #pragma unroll
    for (int i = 0; i < 4; i++)
        #pragma unroll
        for (int j = 0; j < 4; j++) acc[i][j] = 0.f;

    #pragma unroll 16
    for (int kk = 0; kk < 64; kk++) {
        float af[4], bf[4];
        #pragma unroll
        for (int i = 0; i < 4; i++) af[i] = Xs[kk*64 + ty + 16*i];
        #pragma unroll
        for (int j = 0; j < 4; j++) bf[j] = Ws[kk*64 + tx + 16*j];
        #pragma unroll
        for (int i = 0; i < 4; i++)
            #pragma unroll
            for (int j = 0; j < 4; j++) acc[i][j] += af[i] * bf[j];
    }

    #pragma unroll
    for (int i = 0; i < 4; i++) {
        const int r = r0 + ty + 16*i;
        #pragma unroll
        for (int j = 0; j < 4; j++) {
            const int c = tx + 16*j;
            float v = acc[i][j] + bias[c];
            out[(size_t)r * 64 + c] = fmaxf(v, 0.f);
        }
    }
}

// ---------------------------------------------------------------------------
// Fused flash-style attention with qv multiplier:
//   s  = q1 @ kr^T (masked), qv = q2 @ vr^T
//   out = [softmax_row(s) * qv] @ k     via online softmax
// One block per (bh, 64-row q tile). 256 threads, 4x4 micro-tiles.
// ---------------------------------------------------------------------------
__global__ __launch_bounds__(256)
void attn_kernel(const float* __restrict__ q1g, const float* __restrict__ q2g,
                 const float* __restrict__ krg, const float* __restrict__ vrg,
                 const float* __restrict__ kg,  const int* __restrict__ mask,
                 float* __restrict__ outg)
{
    extern __shared__ float sm[];
    float* q1s = sm;               // [d][r]   64*64
    float* q2s = q1s + 4096;       // [d][r]
    float* krs = q2s + 4096;       // [d][c]
    float* vrs = krs + 4096;       // [d][c]
    float* kbs = vrs + 4096;       // [kk][dim] stride 68
    float* ps  = kbs + 64*68;      // [kk][r]   stride 65

    const int t  = threadIdx.x;
    const int tx = t & 15, ty = t >> 4;
    const int bh = blockIdx.y;
    const int q0 = blockIdx.x * 64;
    const int b  = bh >> 4;        // bh / H
    const int h  = bh & 15;        // bh % H
    const int lr = t & 63;
    const int db = (t >> 6) * 16;
    const int kk_l = t >> 2;
    const int db2  = (t & 3) * 16;

    {
        const float* q1p = q1g + ((size_t)bh * kS + q0 + lr) * kDK + db;
        const float* q2p = q2g + ((size_t)bh * kS + q0 + lr) * kDK + db;
        #pragma unroll
        for (int q = 0; q < 4; q++) {
            float4 v1 = *(const float4*)(q1p + 4*q);
            float4 v2 = *(const float4*)(q2p + 4*q);
            q1s[(db+4*q+0)*64+lr]=v1.x; q1s[(db+4*q+1)*64+lr]=v1.y;
            q1s[(db+4*q+2)*64+lr]=v1.z; q1s[(db+4*q+3)*64+lr]=v1.w;
            q2s[(db+4*q+0)*64+lr]=v2.x; q2s[(db+4*q+1)*64+lr]=v2.y;
            q2s[(db+4*q+2)*64+lr]=v2.z; q2s[(db+4*q+3)*64+lr]=v2.w;
        }
    }

    float m_i[4], l_i[4], acc[4][4];
    #pragma unroll
    for (int i = 0; i < 4; i++) {
        m_i[i] = -1e30f; l_i[i] = 0.f;
        #pragma unroll
        for (int j = 0; j < 4; j++) acc[i][j] = 0.f;
    }

    for (int k0 = 0; k0 < kS; k0 += 64) {
        __syncthreads();   // protect kbs/ps from previous iteration's GEMM
        const float* krp = krg + ((size_t)bh * kS + k0 + lr) * kDK + db;
        const float* vrp = vrg + ((size_t)bh * kS + k0 + lr) * kDK + db;
        #pragma unroll
        for (int q = 0; q < 4; q++) {
            float4 v1 = *(const float4*)(krp + 4*q);
            float4 v2 = *(const float4*)(vrp + 4*q);
            krs[(db+4*q+0)*64+lr]=v1.x; krs[(db+4*q+1)*64+lr]=v1.y;
            krs[(db+4*q+2)*64+lr]=v1.z; krs[(db+4*q+3)*64+lr]=v1.w;
            vrs[(db+4*q+0)*64+lr]=v2.x; vrs[(db+4*q+1)*64+lr]=v2.y;
            vrs[(db+4*q+2)*64+lr]=v2.z; vrs[(db+4*q+3)*64+lr]=v2.w;
        }
        const float* kp = kg + ((size_t)bh * kS + k0 + kk_l) * kDK + db2;
        #pragma unroll
        for (int q = 0; q < 4; q++) {
            float4 v = *(const float4*)(kp + 4*q);
            kbs[kk_l*68 + db2 + 4*q + 0] = v.x;
            kbs[kk_l*68 + db2 + 4*q + 1] = v.y;
            kbs[kk_l*68 + db2 + 4*q + 2] = v.z;
            kbs[kk_l*68 + db2 + 4*q + 3] = v.w;
        }
        __syncthreads();

        float sv[4][4], qv[4][4];
        #pragma unroll
        for (int i = 0; i < 4; i++)
            #pragma unroll
            for (int j = 0; j < 4; j++) { sv[i][j] = 0.f; qv[i][j] = 0.f; }

        #pragma unroll 8
        for (int d = 0; d < 64; d++) {
            float a1[4], a2[4], b1[4], b2[4];
            #pragma unroll
            for (int i = 0; i < 4; i++) {
                a1[i] = q1s[d*64 + ty + 16*i];
                a2[i] = q2s[d*64 + ty + 16*i];
            }
            #pragma unroll
            for (int j = 0; j < 4; j++) {
                b1[j] = krs[d*64 + tx + 16*j];
                b2[j] = vrs[d*64 + tx + 16*j];
            }
            #pragma unroll
            for (int i = 0; i < 4; i++)
                #pragma unroll
                for (int j = 0; j < 4; j++) {
                    sv[i][j] += a1[i] * b1[j];
                    qv[i][j] += a2[i] * b2[j];
                }
        }

        // mask (reference: where mask==0 -> -1e9)
        const int* mp = mask + (size_t)b * kS * kS + (size_t)q0 * kS + k0;
        #pragma unroll
        for (int i = 0; i < 4; i++)
            #pragma unroll
            for (int j = 0; j < 4; j++)
                if (mp[(size_t)(ty + 16*i) * kS + tx + 16*j] == 0) sv[i][j] = -1.0e9f;

        // online softmax; carry p*qv into the k-GEMM
        #pragma unroll
        for (int i = 0; i < 4; i++) {
            float rmax = sv[i][0];
            #pragma unroll
            for (int j = 1; j < 4; j++) rmax = fmaxf(rmax, sv[i][j]);
            #pragma unroll
            for (int w = 8; w >= 1; w >>= 1)
                rmax = fmaxf(rmax, __shfl_xor_sync(0xffffffffu, rmax, w));
            float mnew = fmaxf(m_i[i], rmax);
            float sc = __expf(m_i[i] - mnew);
            float rsum = 0.f;
            #pragma unroll
            for (int j = 0; j < 4; j++) {
                float p = __expf(sv[i][j] - mnew);
                rsum += p;
                sv[i][j] = p * qv[i][j];
            }
            #pragma unroll
            for (int w = 8; w >= 1; w >>= 1)
                rsum += __shfl_xor_sync(0xffffffffu, rsum, w);
            l_i[i] = l_i[i] * sc + rsum;
            m_i[i] = mnew;
            #pragma unroll
            for (int j = 0; j < 4; j++) acc[i][j] *= sc;
        }

        // stage p*qv into smem [key][row] (pad 65 -> conflict-free transpose)
        #pragma unroll
        for (int i = 0; i < 4; i++)
            #pragma unroll
            for (int j = 0; j < 4; j++)
                ps[(tx + 16*j) * 65 + ty + 16*i] = sv[i][j];
        __syncthreads();

        // acc += (p*qv) @ k_block
        #pragma unroll 8
        for (int kk = 0; kk < 64; kk++) {
            float af[4], bf[4];
            #pragma unroll
            for (int i = 0; i < 4; i++) af[i] = ps[kk*65 + ty + 16*i];
            #pragma unroll
            for (int j = 0; j < 4; j++) bf[j] = kbs[kk*68 + tx + 16*j];
            #pragma unroll
            for (int i = 0; i < 4; i++)
                #pragma unroll
                for (int j = 0; j < 4; j++) acc[i][j] += af[i] * bf[j];
        }
    }

    // normalize and write to [B,S,DM] layout for the O projection
    #pragma unroll
    for (int i = 0; i < 4; i++) {
        const int r = q0 + ty + 16*i;
        const float inv = 1.0f / l_i[i];
        #pragma unroll
        for (int j = 0; j < 4; j++)
            outg[((size_t)b * kS + r) * kDM + h * kDK + tx + 16*j] = acc[i][j] * inv;
    }
}

// ---------------------------------------------------------------------------
extern "C" void kernel_launch(void* const* d_in, const int* in_sizes, int n_in,
                              void* d_out, int out_size)
{
    (void)in_sizes; (void)n_in; (void)out_size;
    const float* query = (const float*)d_in[0];
    const float* key_  = (const float*)d_in[1];
    const float* value = (const float*)d_in[2];
    const int*   mask  = (const int*)  d_in[3];
    const float* Wq  = (const float*)d_in[4];  const float* bq  = (const float*)d_in[5];
    const float* Wk  = (const float*)d_in[6];  const float* bk  = (const float*)d_in[7];
    const float* Wv  = (const float*)d_in[8];  const float* bv  = (const float*)d_in[9];
    const float* Wo  = (const float*)d_in[10]; const float* bo  = (const float*)d_in[11];
    const float* Wkl = (const float*)d_in[12]; const float* bkl = (const float*)d_in[13];
    const float* Wql = (const float*)d_in[14]; const float* bql = (const float*)d_in[15];
    const float* Wq2 = (const float*)d_in[16]; const float* bq2 = (const float*)d_in[17];
    const float* Wvl = (const float*)d_in[18]; const float* bvl = (const float*)d_in[19];
    const float* Wel = (const float*)d_in[20]; const float* bel = (const float*)d_in[21];

    float *qh, *kh, *vh, *kr, *q1a, *q1, *q2, *vr, *att;
    cudaGetSymbolAddress((void**)&qh,  g_qh);
    cudaGetSymbolAddress((void**)&kh,  g_kh);
    cudaGetSymbolAddress((void**)&vh,  g_vh);
    cudaGetSymbolAddress((void**)&kr,  g_kr);
    cudaGetSymbolAddress((void**)&q1a, g_q1a);
    cudaGetSymbolAddress((void**)&q1,  g_q1);
    cudaGetSymbolAddress((void**)&q2,  g_q2);
    cudaGetSymbolAddress((void**)&vr,  g_vr);
    cudaGetSymbolAddress((void**)&att, g_att);

    dim3 gg(8, 32);   // N/128, M/128

    // Q/K/V projections -> head-split [BH, S, DK]
    sgemm128<<<gg, 256>>>(query, Wq, bq, qh, 1);
    sgemm128<<<gg, 256>>>(key_,  Wk, bk, kh, 1);
    sgemm128<<<gg, 256>>>(value, Wv, bv, vh, 1);

    // per-head small linears (weights shared across heads)
    small_linear<<<1024, 256>>>(kh,  Wkl, bkl, kr);   // key_refine
    small_linear<<<1024, 256>>>(qh,  Wql, bql, q1a);  // q1 stage 1
    small_linear<<<1024, 256>>>(q1a, Wel, bel, q1);   // q1 stage 2
    small_linear<<<1024, 256>>>(qh,  Wq2, bq2, q2);   // q2
    small_linear<<<1024, 256>>>(vh,  Wvl, bvl, vr);   // v_refine

    // fused attention (needs ~97 KB dynamic smem)
    cudaFuncSetAttribute(attn_kernel, cudaFuncAttributeMaxDynamicSharedMemorySize, 99584);
    attn_kernel<<<dim3(16, 64), 256, 99584>>>(q1, q2, kr, vr, kh, mask, att);

    // output projection -> d_out [B*S, DM]
    sgemm128<<<gg, 256>>>(att, Wo, bo, (float*)d_out, 0);
}

// round 3
// speedup vs baseline: 1.8230x; 1.8230x over previous
#include <cuda_runtime.h>
#include <cuda_bf16.h>
#include <cstdint>

static constexpr int kB  = 4;
static constexpr int kS  = 1024;
static constexpr int kDM = 1024;
static constexpr int kH  = 16;
static constexpr int kDK = 64;
static constexpr int kBH = kB * kH;   // 64

// ---------------- scratch (static device globals; no allocation) ----------------
__device__ float g_qh [kBH * kS * kDK];
__device__ float g_kh [kBH * kS * kDK];
__device__ float g_vh [kBH * kS * kDK];
__device__ float g_kr [kBH * kS * kDK];
__device__ float g_q1a[kBH * kS * kDK];
__device__ float g_q1 [kBH * kS * kDK];
__device__ float g_q2 [kBH * kS * kDK];
__device__ float g_vr [kBH * kS * kDK];
__device__ float g_att[kB * kS * kDM];

// ---------------------------------------------------------------------------
// PTX helpers
// ---------------------------------------------------------------------------
__device__ __forceinline__ uint32_t smem_u32(const void* p) {
    uint32_t a;
    asm("{ .reg .u64 t; cvta.to.shared.u64 t, %1; cvt.u32.u64 %0, t; }" : "=r"(a) : "l"(p));
    return a;
}

__device__ __forceinline__ uint32_t pack_bf2(__nv_bfloat16 a, __nv_bfloat16 b) {
    __nv_bfloat162 t = __halves2bfloat162(a, b);
    return *reinterpret_cast<uint32_t*>(&t);
}

#if defined(__CUDA_ARCH_FEAT_SM103_ALL) || !defined(__CUDA_ARCH__)
#define HAS_TCGEN05 1
#else
#define HAS_TCGEN05 0
#endif

#if HAS_TCGEN05
__device__ __forceinline__ void mbar_wait(uint32_t mbar, uint32_t parity) {
    asm volatile(
        "{\n\t.reg .pred P;\n\t"
        "LW%=:\n\t"
        "mbarrier.try_wait.parity.acquire.cta.shared::cta.b64 P, [%0], %1;\n\t"
        "@!P bra LW%=;\n\t}"
        :: "r"(mbar), "r"(parity) : "memory");
}

// idesc: F32 accum, BF16 a/b, K-major both, M=128, N=128
static constexpr uint32_t GE_IDESC =
    (1u << 4) | (1u << 7) | (1u << 10) | ((128u / 8) << 17) | ((128u / 16) << 24);

// SW128 K-major smem descriptor base (version=1 Blackwell, LBO=1, SBO=64)
static constexpr uint64_t DESC_SW128 =
    (2ull << 61) | (1ull << 46) | (64ull << 32) | (1ull << 16);

__device__ __forceinline__ uint64_t mk_desc(uint32_t addr) {
    return DESC_SW128 | (uint64_t)((addr >> 4) & 0x3FFF);
}

__device__ __forceinline__ void mma_bf16_ss(uint32_t d, uint64_t ad, uint64_t bd, bool en) {
    uint32_t e = en ? 1u : 0u;
    asm volatile(
        "{\n\t.reg .pred p;\n\t"
        "setp.ne.u32 p, %5, 0;\n\t"
        "tcgen05.mma.cta_group::1.kind::f16 [%0], %1, %2, %3, {%4, %4, %4, %4}, p;\n\t}"
        :: "r"(d), "l"(ad), "l"(bd), "r"(GE_IDESC), "r"(0u), "r"(e) : "memory");
}

#define LDTM_X32(r, addr) \
    asm volatile( \
        "tcgen05.ld.sync.aligned.32x32b.x32.b32 " \
        "{%0, %1, %2, %3, %4, %5, %6, %7, " \
        " %8, %9, %10, %11, %12, %13, %14, %15, " \
        " %16, %17, %18, %19, %20, %21, %22, %23, " \
        " %24, %25, %26, %27, %28, %29, %30, %31}, [%32];" \
        : "=r"((r)[0]),  "=r"((r)[1]),  "=r"((r)[2]),  "=r"((r)[3]), \
          "=r"((r)[4]),  "=r"((r)[5]),  "=r"((r)[6]),  "=r"((r)[7]), \
          "=r"((r)[8]),  "=r"((r)[9]),  "=r"((r)[10]), "=r"((r)[11]), \
          "=r"((r)[12]), "=r"((r)[13]), "=r"((r)[14]), "=r"((r)[15]), \
          "=r"((r)[16]), "=r"((r)[17]), "=r"((r)[18]), "=r"((r)[19]), \
          "=r"((r)[20]), "=r"((r)[21]), "=r"((r)[22]), "=r"((r)[23]), \
          "=r"((r)[24]), "=r"((r)[25]), "=r"((r)[26]), "=r"((r)[27]), \
          "=r"((r)[28]), "=r"((r)[29]), "=r"((r)[30]), "=r"((r)[31]) \
        : "r"(addr))
#endif  // HAS_TCGEN05

// convert float4 -> bf16 hi + bf16 residual, store 8B to each smem tile
__device__ __forceinline__ void store_hilo(float4 v, uint32_t hoff, uint32_t loff) {
    __nv_bfloat16 h0 = __float2bfloat16(v.x), h1 = __float2bfloat16(v.y);
    __nv_bfloat16 h2 = __float2bfloat16(v.z), h3 = __float2bfloat16(v.w);
    float r0 = v.x - __bfloat162float(h0), r1 = v.y - __bfloat162float(h1);
    float r2 = v.z - __bfloat162float(h2), r3 = v.w - __bfloat162float(h3);
    __nv_bfloat16 l0 = __float2bfloat16(r0), l1 = __float2bfloat16(r1);
    __nv_bfloat16 l2 = __float2bfloat16(r2), l3 = __float2bfloat16(r3);
    uint32_t hp0 = pack_bf2(h0, h1), hp1 = pack_bf2(h2, h3);
    uint32_t lp0 = pack_bf2(l0, l1), lp1 = pack_bf2(l2, l3);
    asm volatile("st.shared.v2.b32 [%0], {%1, %2};" :: "r"(hoff), "r"(hp0), "r"(hp1) : "memory");
    asm volatile("st.shared.v2.b32 [%0], {%1, %2};" :: "r"(loff), "r"(lp0), "r"(lp1) : "memory");
}

// ---------------------------------------------------------------------------
// GEMM: C[m][n] = sum_k A[m][k]*W[n][k] + bias[n]
// M=4096, N=1024, K=1024. Per CTA: 128x128 tile.
// sm_103a pass: tcgen05 bf16 hi/lo split (D = Ah*Bh + Ah*Bl + Al*Bh, fp32 acc)
// other passes: FFMA fallback (same semantics, fp32)
// mode 0: out[m*1024+n]   mode 1: head-split [((b*16+h)*1024+s)*64+d]
// ---------------------------------------------------------------------------
__global__ __launch_bounds__(256)
void tc_gemm(const float* __restrict__ A, const float* __restrict__ W,
             const float* __restrict__ bias, float* __restrict__ out, int mode)
{
    extern __shared__ char dsm[];
    const int t   = threadIdx.x;
    const int m0  = blockIdx.y * 128;
    const int n0  = blockIdx.x * 128;

#if HAS_TCGEN05
    __shared__ uint32_t s_tmem;
    __shared__ __align__(8) uint64_t s_mbar;

    const uint32_t base = (smem_u32(dsm) + 1023u) & ~1023u;
    const uint32_t ah = base, al = base + 16384, bhs = base + 32768, bls = base + 49152;
    const int wid = t >> 5;

    if (wid == 0) {
        asm volatile("tcgen05.alloc.cta_group::1.sync.aligned.shared::cta.b32 [%0], %1;"
                     :: "r"(smem_u32(&s_tmem)), "r"(128u) : "memory");
        asm volatile("tcgen05.relinquish_alloc_permit.cta_group::1.sync.aligned;");
    }
    if (t == 0)
        asm volatile("mbarrier.init.shared.b64 [%0], 1;" :: "r"(smem_u32(&s_mbar)) : "memory");
    __syncthreads();
    const uint32_t tmem = s_tmem;
    const uint32_t mbar = smem_u32(&s_mbar);

    // thread mapping: rows ty+16i (i<8), float4 column c4
    const int ty = t >> 4, c4 = t & 15;
    const float* Ap = A + (size_t)(m0 + ty) * 1024 + c4 * 4;
    const float* Wp = W + (size_t)(n0 + ty) * 1024 + c4 * 4;

    int chunk = 0;
    for (int k0 = 0; k0 < 1024; k0 += 64, ++chunk) {
        // prefetch chunk into registers (overlaps previous chunk's MMAs)
        float4 av[8], wv[8];
        #pragma unroll
        for (int i = 0; i < 8; i++) {
            av[i] = *(const float4*)(Ap + (size_t)(16 * i) * 1024 + k0);
            wv[i] = *(const float4*)(Wp + (size_t)(16 * i) * 1024 + k0);
        }
        if (chunk > 0) mbar_wait(mbar, (chunk - 1) & 1);
        #pragma unroll
        for (int i = 0; i < 8; i++) {
            uint32_t off = (uint32_t)((ty + 16 * i) * 128 + c4 * 8);
            off ^= (off >> 3) & 0x70;   // SW128 swizzle
            store_hilo(av[i], ah + off, al + off);
            store_hilo(wv[i], bhs + off, bls + off);
        }
        asm volatile("fence.proxy.async.shared::cta;" ::: "memory");
        __syncthreads();
        if (t == 0) {
            const uint64_t dah = mk_desc(ah),  dal = mk_desc(al);
            const uint64_t dbh = mk_desc(bhs), dbl = mk_desc(bls);
            #pragma unroll
            for (int ks = 0; ks < 4; ks++) {    // K=16 per MMA, 4 steps over 64
                mma_bf16_ss(tmem, dah + 2 * ks, dbh + 2 * ks, !(chunk == 0 && ks == 0));
                mma_bf16_ss(tmem, dah + 2 * ks, dbl + 2 * ks, true);
                mma_bf16_ss(tmem, dal + 2 * ks, dbh + 2 * ks, true);
            }
            asm volatile(
                "tcgen05.commit.cta_group::1.mbarrier::arrive::one.shared::cluster.b64 [%0];"
                :: "r"(mbar) : "memory");
        }
    }
    mbar_wait(mbar, (16 - 1) & 1);   // final chunk parity
    __syncthreads();
    asm volatile("tcgen05.fence::after_thread_sync;" ::: "memory");

    // epilogue: warps 0..3 read their 32-lane subpartitions (rows wid*32+lane)
    if (wid < 4) {
        const int lane = t & 31;
        const int gr = m0 + wid * 32 + lane;
        for (int cb = 0; cb < 128; cb += 32) {
            uint32_t regs[32];
            LDTM_X32(regs, tmem + cb);
            asm volatile("tcgen05.wait::ld.sync.aligned;" ::: "memory");
            if (mode == 0) {
                float* op = out + (size_t)gr * 1024 + n0 + cb;
                #pragma unroll
                for (int c = 0; c < 32; c++)
                    op[c] = __uint_as_float(regs[c]) + bias[n0 + cb + c];
            } else {
                const int b = gr >> 10, s = gr & 1023;
                #pragma unroll
                for (int c = 0; c < 32; c++) {
                    const int gc = n0 + cb + c;
                    const int h = gc >> 6, d = gc & 63;
                    out[(((size_t)(b * kH + h)) * kS + s) * kDK + d] =
                        __uint_as_float(regs[c]) + bias[gc];
                }
            }
        }
    }
    __syncthreads();
    if (wid == 0)
        asm volatile("tcgen05.dealloc.cta_group::1.sync.aligned.b32 %0, %1;"
                     :: "r"(tmem), "r"(128u));

#else  // ------- FFMA fallback (non-sm_103a device pass) -------
    float* As = (float*)dsm;            // [16][128]
    float* Bs = As + 16 * 128;          // [16][128]
    const int tx = t & 15, ty = t >> 4;
    const int lm = t & 127;
    const int kb = (t >> 7) * 8;

    float acc[8][8];
    #pragma unroll
    for (int i = 0; i < 8; i++)
        #pragma unroll
        for (int j = 0; j < 8; j++) acc[i][j] = 0.f;

    for (int k0 = 0; k0 < 1024; k0 += 16) {
        const float4* Ag = (const float4*)(A + (size_t)(m0 + lm) * 1024 + k0 + kb);
        const float4* Wg = (const float4*)(W + (size_t)(n0 + lm) * 1024 + k0 + kb);
        float4 a0 = Ag[0], a1 = Ag[1];
        float4 b0 = Wg[0], b1 = Wg[1];
        As[(kb+0)*128+lm]=a0.x; As[(kb+1)*128+lm]=a0.y; As[(kb+2)*128+lm]=a0.z; As[(kb+3)*128+lm]=a0.w;
        As[(kb+4)*128+lm]=a1.x; As[(kb+5)*128+lm]=a1.y; As[(kb+6)*128+lm]=a1.z; As[(kb+7)*128+lm]=a1.w;
        Bs[(kb+0)*128+lm]=b0.x; Bs[(kb+1)*128+lm]=b0.y; Bs[(kb+2)*128+lm]=b0.z; Bs[(kb+3)*128+lm]=b0.w;
        Bs[(kb+4)*128+lm]=b1.x; Bs[(kb+5)*128+lm]=b1.y; Bs[(kb+6)*128+lm]=b1.z; Bs[(kb+7)*128+lm]=b1.w;
        __syncthreads();
        #pragma unroll
        for (int kk = 0; kk < 16; kk++) {
            float af[8], bf[8];
            #pragma unroll
            for (int i = 0; i < 8; i++) af[i] = As[kk*128 + ty + 16*i];
            #pragma unroll
            for (int j = 0; j < 8; j++) bf[j] = Bs[kk*128 + tx + 16*j];
            #pragma unroll
            for (int i = 0; i < 8; i++)
                #pragma unroll
                for (int j = 0; j < 8; j++) acc[i][j] += af[i] * bf[j];
        }
        __syncthreads();
    }

    #pragma unroll
    for (int i = 0; i < 8; i++) {
        const int r = m0 + ty + 16*i;
        #pragma unroll
        for (int j = 0; j < 8; j++) {
            const int c = n0 + tx + 16*j;
            float v = acc[i][j] + bias[c];
            if (mode == 0) {
                out[(size_t)r * 1024 + c] = v;
            } else {
                int b = r >> 10, s = r & 1023, h = c >> 6, d = c & 63;
                out[(((size_t)(b * kH + h)) * kS + s) * kDK + d] = v;
            }
        }
    }
#endif
}

// ---------------------------------------------------------------------------
// Small linear: Y = relu(X @ W^T + b), X:[R,64], W:[64,64]. 64 rows per block.
// ---------------------------------------------------------------------------
__global__ __launch_bounds__(256)
void small_linear(const float* __restrict__ X, const float* __restrict__ W,
                  const float* __restrict__ bias, float* __restrict__ out)
{
    __shared__ float Xs[64*64];   // [k][m]
    __shared__ float Ws[64*64];   // [k][n]
    const int t  = threadIdx.x;
    const int tx = t & 15, ty = t >> 4;
    const int r0 = blockIdx.x * 64;
    const int lr = t & 63;
    const int kb = (t >> 6) * 16;

    #pragma unroll
    for (int q = 0; q < 4; q++) {
        float4 w = *(const float4*)(W + (size_t)lr * 64 + kb + 4*q);
        Ws[(kb+4*q+0)*64 + lr] = w.x;
        Ws[(kb+4*q+1)*64 + lr] = w.y;
        Ws[(kb+4*q+2)*64 + lr] = w.z;
        Ws[(kb+4*q+3)*64 + lr] = w.w;
        float4 x = *(const float4*)(X + (size_t)(r0 + lr) * 64 + kb + 4*q);
        Xs[(kb+4*q+0)*64 + lr] = x.x;
        Xs[(kb+4*q+1)*64 + lr] = x.y;
        Xs[(kb+4*q+2)*64 + lr] = x.z;
        Xs[(kb+4*q+3)*64 + lr] = x.w;
    }
    __syncthreads();

    float acc[4][4];
    #pragma unroll
    for (int i = 0; i < 4; i++)
        #pragma unroll
        for (int j = 0; j < 4; j++) acc[i][j] = 0.f;

    #pragma unroll 16
    for (int kk = 0; kk < 64; kk++) {
        float af[4], bf[4];
        #pragma unroll
        for (int i = 0; i < 4; i++) af[i] = Xs[kk*64 + ty + 16*i];
        #pragma unroll
        for (int j = 0; j < 4; j++) bf[j] = Ws[kk*64 + tx + 16*j];
        #pragma unroll
        for (int i = 0; i < 4; i++)
            #pragma unroll
            for (int j = 0; j < 4; j++) acc[i][j] += af[i] * bf[j];
    }

    #pragma unroll
    for (int i = 0; i < 4; i++) {
        const int r = r0 + ty + 16*i;
        #pragma unroll
        for (int j = 0; j < 4; j++) {
            const int c = tx + 16*j;
            float v = acc[i][j] + bias[c];
            out[(size_t)r * 64 + c] = fmaxf(v, 0.f);
        }
    }
}

// ---------------------------------------------------------------------------
// Fused flash-style attention with qv multiplier:
//   s  = q1 @ kr^T (masked), qv = q2 @ vr^T
//   out = [softmax_row(s) * qv] @ k     via online softmax
// One block per (bh, 64-row q tile). 256 threads, 4x4 micro-tiles.
// ---------------------------------------------------------------------------
__global__ __launch_bounds__(256)
void attn_kernel(const float* __restrict__ q1g, const float* __restrict__ q2g,
                 const float* __restrict__ krg, const float* __restrict__ vrg,
                 const float* __restrict__ kg,  const int* __restrict__ mask,
                 float* __restrict__ outg)
{
    extern __shared__ float sm[];
    float* q1s = sm;               // [d][r]   64*64
    float* q2s = q1s + 4096;       // [d][r]
    float* krs = q2s + 4096;       // [d][c]
    float* vrs = krs + 4096;       // [d][c]
    float* kbs = vrs + 4096;       // [kk][dim] stride 68
    float* ps  = kbs + 64*68;      // [kk][r]   stride 65

    const int t  = threadIdx.x;
    const int tx = t & 15, ty = t >> 4;
    const int bh = blockIdx.y;
    const int q0 = blockIdx.x * 64;
    const int b  = bh >> 4;        // bh / H
    const int h  = bh & 15;        // bh % H
    const int lr = t & 63;
    const int db = (t >> 6) * 16;
    const int kk_l = t >> 2;
    const int db2  = (t & 3) * 16;

    {
        const float* q1p = q1g + ((size_t)bh * kS + q0 + lr) * kDK + db;
        const float* q2p = q2g + ((size_t)bh * kS + q0 + lr) * kDK + db;
        #pragma unroll
        for (int q = 0; q < 4; q++) {
            float4 v1 = *(const float4*)(q1p + 4*q);
            float4 v2 = *(const float4*)(q2p + 4*q);
            q1s[(db+4*q+0)*64+lr]=v1.x; q1s[(db+4*q+1)*64+lr]=v1.y;
            q1s[(db+4*q+2)*64+lr]=v1.z; q1s[(db+4*q+3)*64+lr]=v1.w;
            q2s[(db+4*q+0)*64+lr]=v2.x; q2s[(db+4*q+1)*64+lr]=v2.y;
            q2s[(db+4*q+2)*64+lr]=v2.z; q2s[(db+4*q+3)*64+lr]=v2.w;
        }
    }

    float m_i[4], l_i[4], acc[4][4];
    #pragma unroll
    for (int i = 0; i < 4; i++) {
        m_i[i] = -1e30f; l_i[i] = 0.f;
        #pragma unroll
        for (int j = 0; j < 4; j++) acc[i][j] = 0.f;
    }

    for (int k0 = 0; k0 < kS; k0 += 64) {
        __syncthreads();   // protect kbs/ps from previous iteration's GEMM
        const float* krp = krg + ((size_t)bh * kS + k0 + lr) * kDK + db;
        const float* vrp = vrg + ((size_t)bh * kS + k0 + lr) * kDK + db;
        #pragma unroll
        for (int q = 0; q < 4; q++) {
            float4 v1 = *(const float4*)(krp + 4*q);
            float4 v2 = *(const float4*)(vrp + 4*q);
            krs[(db+4*q+0)*64+lr]=v1.x; krs[(db+4*q+1)*64+lr]=v1.y;
            krs[(db+4*q+2)*64+lr]=v1.z; krs[(db+4*q+3)*64+lr]=v1.w;
            vrs[(db+4*q+0)*64+lr]=v2.x; vrs[(db+4*q+1)*64+lr]=v2.y;
            vrs[(db+4*q+2)*64+lr]=v2.z; vrs[(db+4*q+3)*64+lr]=v2.w;
        }
        const float* kp = kg + ((size_t)bh * kS + k0 + kk_l) * kDK + db2;
        #pragma unroll
        for (int q = 0; q < 4; q++) {
            float4 v = *(const float4*)(kp + 4*q);
            kbs[kk_l*68 + db2 + 4*q + 0] = v.x;
            kbs[kk_l*68 + db2 + 4*q + 1] = v.y;
            kbs[kk_l*68 + db2 + 4*q + 2] = v.z;
            kbs[kk_l*68 + db2 + 4*q + 3] = v.w;
        }
        __syncthreads();

        float sv[4][4], qv[4][4];
        #pragma unroll
        for (int i = 0; i < 4; i++)
            #pragma unroll
            for (int j = 0; j < 4; j++) { sv[i][j] = 0.f; qv[i][j] = 0.f; }

        #pragma unroll 8
        for (int d = 0; d < 64; d++) {
            float a1[4], a2[4], b1[4], b2[4];
            #pragma unroll
            for (int i = 0; i < 4; i++) {
                a1[i] = q1s[d*64 + ty + 16*i];
                a2[i] = q2s[d*64 + ty + 16*i];
            }
            #pragma unroll
            for (int j = 0; j < 4; j++) {
                b1[j] = krs[d*64 + tx + 16*j];
                b2[j] = vrs[d*64 + tx + 16*j];
            }
            #pragma unroll
            for (int i = 0; i < 4; i++)
                #pragma unroll
                for (int j = 0; j < 4; j++) {
                    sv[i][j] += a1[i] * b1[j];
                    qv[i][j] += a2[i] * b2[j];
                }
        }

        // mask (reference: where mask==0 -> -1e9)
        const int* mp = mask + (size_t)b * kS * kS + (size_t)q0 * kS + k0;
        #pragma unroll
        for (int i = 0; i < 4; i++)
            #pragma unroll
            for (int j = 0; j < 4; j++)
                if (mp[(size_t)(ty + 16*i) * kS + tx + 16*j] == 0) sv[i][j] = -1.0e9f;

        // online softmax; carry p*qv into the k-GEMM
        #pragma unroll
        for (int i = 0; i < 4; i++) {
            float rmax = sv[i][0];
            #pragma unroll
            for (int j = 1; j < 4; j++) rmax = fmaxf(rmax, sv[i][j]);
            #pragma unroll
            for (int w = 8; w >= 1; w >>= 1)
                rmax = fmaxf(rmax, __shfl_xor_sync(0xffffffffu, rmax, w));
            float mnew = fmaxf(m_i[i], rmax);
            float sc = __expf(m_i[i] - mnew);
            float rsum = 0.f;
            #pragma unroll
            for (int j = 0; j < 4; j++) {
                float p = __expf(sv[i][j] - mnew);
                rsum += p;
                sv[i][j] = p * qv[i][j];
            }
            #pragma unroll
            for (int w = 8; w >= 1; w >>= 1)
                rsum += __shfl_xor_sync(0xffffffffu, rsum, w);
            l_i[i] = l_i[i] * sc + rsum;
            m_i[i] = mnew;
            #pragma unroll
            for (int j = 0; j < 4; j++) acc[i][j] *= sc;
        }

        // stage p*qv into smem [key][row] (pad 65 -> conflict-free transpose)
        #pragma unroll
        for (int i = 0; i < 4; i++)
            #pragma unroll
            for (int j = 0; j < 4; j++)
                ps[(tx + 16*j) * 65 + ty + 16*i] = sv[i][j];
        __syncthreads();

        // acc += (p*qv) @ k_block
        #pragma unroll 8
        for (int kk = 0; kk < 64; kk++) {
            float af[4], bf[4];
            #pragma unroll
            for (int i = 0; i < 4; i++) af[i] = ps[kk*65 + ty + 16*i];
            #pragma unroll
            for (int j = 0; j < 4; j++) bf[j] = kbs[kk*68 + tx + 16*j];
            #pragma unroll
            for (int i = 0; i < 4; i++)
                #pragma unroll
                for (int j = 0; j < 4; j++) acc[i][j] += af[i] * bf[j];
        }
    }

    // normalize and write to [B,S,DM] layout for the O projection
    #pragma unroll
    for (int i = 0; i < 4; i++) {
        const int r = q0 + ty + 16*i;
        const float inv = 1.0f / l_i[i];
        #pragma unroll
        for (int j = 0; j < 4; j++)
            outg[((size_t)b * kS + r) * kDM + h * kDK + tx + 16*j] = acc[i][j] * inv;
    }
}

// ---------------------------------------------------------------------------
extern "C" void kernel_launch(void* const* d_in, const int* in_sizes, int n_in,
                              void* d_out, int out_size)
{
    (void)in_sizes; (void)n_in; (void)out_size;
    const float* query = (const float*)d_in[0];
    const float* key_  = (const float*)d_in[1];
    const float* value = (const float*)d_in[2];
    const int*   mask  = (const int*)  d_in[3];
    const float* Wq  = (const float*)d_in[4];  const float* bq  = (const float*)d_in[5];
    const float* Wk  = (const float*)d_in[6];  const float* bk  = (const float*)d_in[7];
    const float* Wv  = (const float*)d_in[8];  const float* bv  = (const float*)d_in[9];
    const float* Wo  = (const float*)d_in[10]; const float* bo  = (const float*)d_in[11];
    const float* Wkl = (const float*)d_in[12]; const float* bkl = (const float*)d_in[13];
    const float* Wql = (const float*)d_in[14]; const float* bql = (const float*)d_in[15];
    const float* Wq2 = (const float*)d_in[16]; const float* bq2 = (const float*)d_in[17];
    const float* Wvl = (const float*)d_in[18]; const float* bvl = (const float*)d_in[19];
    const float* Wel = (const float*)d_in[20]; const float* bel = (const float*)d_in[21];

    float *qh, *kh, *vh, *kr, *q1a, *q1, *q2, *vr, *att;
    cudaGetSymbolAddress((void**)&qh,  g_qh);
    cudaGetSymbolAddress((void**)&kh,  g_kh);
    cudaGetSymbolAddress((void**)&vh,  g_vh);
    cudaGetSymbolAddress((void**)&kr,  g_kr);
    cudaGetSymbolAddress((void**)&q1a, g_q1a);
    cudaGetSymbolAddress((void**)&q1,  g_q1);
    cudaGetSymbolAddress((void**)&q2,  g_q2);
    cudaGetSymbolAddress((void**)&vr,  g_vr);
    cudaGetSymbolAddress((void**)&att, g_att);

    const int GEMM_SMEM = 66560;   // 1024 align slack + 4 x 16KB bf16 tiles
    cudaFuncSetAttribute(tc_gemm, cudaFuncAttributeMaxDynamicSharedMemorySize, GEMM_SMEM);

    dim3 gg(8, 32);   // N/128, M/128

    // Q/K/V projections -> head-split [BH, S, DK]
    tc_gemm<<<gg, 256, GEMM_SMEM>>>(query, Wq, bq, qh, 1);
    tc_gemm<<<gg, 256, GEMM_SMEM>>>(key_,  Wk, bk, kh, 1);
    tc_gemm<<<gg, 256, GEMM_SMEM>>>(value, Wv, bv, vh, 1);

    // per-head small linears (weights shared across heads)
    small_linear<<<1024, 256>>>(kh,  Wkl, bkl, kr);   // key_refine
    small_linear<<<1024, 256>>>(qh,  Wql, bql, q1a);  // q1 stage 1
    small_linear<<<1024, 256>>>(q1a, Wel, bel, q1);   // q1 stage 2
    small_linear<<<1024, 256>>>(qh,  Wq2, bq2, q2);   // q2
    small_linear<<<1024, 256>>>(vh,  Wvl, bvl, vr);   // v_refine

    // fused attention (needs ~97 KB dynamic smem)
    cudaFuncSetAttribute(attn_kernel, cudaFuncAttributeMaxDynamicSharedMemorySize, 99584);
    attn_kernel<<<dim3(16, 64), 256, 99584>>>(q1, q2, kr, vr, kh, mask, att);

    // output projection -> d_out [B*S, DM]
    tc_gemm<<<gg, 256, GEMM_SMEM>>>(att, Wo, bo, (float*)d_out, 0);
}

// round 4
// speedup vs baseline: 3.1550x; 1.7307x over previous
#include <cuda_runtime.h>
#include <cuda_bf16.h>
#include <cstdint>

static constexpr int kB  = 4;
static constexpr int kS  = 1024;
static constexpr int kDM = 1024;
static constexpr int kH  = 16;
static constexpr int kDK = 64;
static constexpr int kBH = kB * kH;   // 64

// ---------------- scratch (static device globals; no allocation) ----------------
__device__ float g_qh [kBH * kS * kDK];
__device__ float g_kh [kBH * kS * kDK];
__device__ float g_vh [kBH * kS * kDK];
__device__ float g_kr [kBH * kS * kDK];
__device__ float g_q1a[kBH * kS * kDK];
__device__ float g_q1 [kBH * kS * kDK];
__device__ float g_q2 [kBH * kS * kDK];
__device__ float g_vr [kBH * kS * kDK];
__device__ float g_att[kB * kS * kDM];

// ---------------------------------------------------------------------------
// PTX helpers
// ---------------------------------------------------------------------------
__device__ __forceinline__ uint32_t smem_u32(const void* p) {
    uint32_t a;
    asm("{ .reg .u64 t; cvta.to.shared.u64 t, %1; cvt.u32.u64 %0, t; }" : "=r"(a) : "l"(p));
    return a;
}

__device__ __forceinline__ uint32_t pack_bf2(__nv_bfloat16 a, __nv_bfloat16 b) {
    __nv_bfloat162 t = __halves2bfloat162(a, b);
    return *reinterpret_cast<uint32_t*>(&t);
}

__device__ __forceinline__ uint32_t sw128(uint32_t o) { return o ^ ((o >> 3) & 0x70); }

#if defined(__CUDA_ARCH_FEAT_SM103_ALL) || !defined(__CUDA_ARCH__)
#define HAS_TCGEN05 1
#else
#define HAS_TCGEN05 0
#endif

#if HAS_TCGEN05
__device__ __forceinline__ void mbar_wait(uint32_t mbar, uint32_t parity) {
    asm volatile(
        "{\n\t.reg .pred P;\n\t"
        "LW%=:\n\t"
        "mbarrier.try_wait.parity.acquire.cta.shared::cta.b64 P, [%0], %1;\n\t"
        "@!P bra LW%=;\n\t}"
        :: "r"(mbar), "r"(parity) : "memory");
}

// idesc: F32 accum, BF16 a/b, K-major both
static constexpr uint32_t GE_IDESC =           // M=128, N=128
    (1u << 4) | (1u << 7) | (1u << 10) | ((128u / 8) << 17) | ((128u / 16) << 24);
static constexpr uint32_t AT_IDESC =           // M=128, N=64
    (1u << 4) | (1u << 7) | (1u << 10) | ((64u / 8) << 17) | ((128u / 16) << 24);

// SW128 K-major smem descriptor base (version=1 Blackwell, LBO=1, SBO=64)
static constexpr uint64_t DESC_SW128 =
    (2ull << 61) | (1ull << 46) | (64ull << 32) | (1ull << 16);

__device__ __forceinline__ uint64_t mk_desc(uint32_t addr) {
    return DESC_SW128 | (uint64_t)((addr >> 4) & 0x3FFF);
}

__device__ __forceinline__ void mma_ss(uint32_t d, uint64_t ad, uint64_t bd,
                                       uint32_t idesc, bool en) {
    uint32_t e = en ? 1u : 0u;
    asm volatile(
        "{\n\t.reg .pred p;\n\t"
        "setp.ne.u32 p, %5, 0;\n\t"
        "tcgen05.mma.cta_group::1.kind::f16 [%0], %1, %2, %3, {%4, %4, %4, %4}, p;\n\t}"
        :: "r"(d), "l"(ad), "l"(bd), "r"(idesc), "r"(0u), "r"(e) : "memory");
}

#define LDTM_X32(r, addr) \
    asm volatile( \
        "tcgen05.ld.sync.aligned.32x32b.x32.b32 " \
        "{%0, %1, %2, %3, %4, %5, %6, %7, " \
        " %8, %9, %10, %11, %12, %13, %14, %15, " \
        " %16, %17, %18, %19, %20, %21, %22, %23, " \
        " %24, %25, %26, %27, %28, %29, %30, %31}, [%32];" \
        : "=r"((r)[0]),  "=r"((r)[1]),  "=r"((r)[2]),  "=r"((r)[3]), \
          "=r"((r)[4]),  "=r"((r)[5]),  "=r"((r)[6]),  "=r"((r)[7]), \
          "=r"((r)[8]),  "=r"((r)[9]),  "=r"((r)[10]), "=r"((r)[11]), \
          "=r"((r)[12]), "=r"((r)[13]), "=r"((r)[14]), "=r"((r)[15]), \
          "=r"((r)[16]), "=r"((r)[17]), "=r"((r)[18]), "=r"((r)[19]), \
          "=r"((r)[20]), "=r"((r)[21]), "=r"((r)[22]), "=r"((r)[23]), \
          "=r"((r)[24]), "=r"((r)[25]), "=r"((r)[26]), "=r"((r)[27]), \
          "=r"((r)[28]), "=r"((r)[29]), "=r"((r)[30]), "=r"((r)[31]) \
        : "r"(addr))
#endif  // HAS_TCGEN05

// convert float4 -> bf16 hi + bf16 residual, store 8B to each smem tile
__device__ __forceinline__ void store_hilo(float4 v, uint32_t hoff, uint32_t loff) {
    __nv_bfloat16 h0 = __float2bfloat16(v.x), h1 = __float2bfloat16(v.y);
    __nv_bfloat16 h2 = __float2bfloat16(v.z), h3 = __float2bfloat16(v.w);
    float r0 = v.x - __bfloat162float(h0), r1 = v.y - __bfloat162float(h1);
    float r2 = v.z - __bfloat162float(h2), r3 = v.w - __bfloat162float(h3);
    __nv_bfloat16 l0 = __float2bfloat16(r0), l1 = __float2bfloat16(r1);
    __nv_bfloat16 l2 = __float2bfloat16(r2), l3 = __float2bfloat16(r3);
    uint32_t hp0 = pack_bf2(h0, h1), hp1 = pack_bf2(h2, h3);
    uint32_t lp0 = pack_bf2(l0, l1), lp1 = pack_bf2(l2, l3);
    asm volatile("st.shared.v2.b32 [%0], {%1, %2};" :: "r"(hoff), "r"(hp0), "r"(hp1) : "memory");
    asm volatile("st.shared.v2.b32 [%0], {%1, %2};" :: "r"(loff), "r"(lp0), "r"(lp1) : "memory");
}

// two floats -> one bf16x2 hi + one bf16x2 residual, 4B each
__device__ __forceinline__ void store_hilo4(float a, float b, uint32_t hoff, uint32_t loff) {
    __nv_bfloat16 ha = __float2bfloat16(a), hb = __float2bfloat16(b);
    float ra = a - __bfloat162float(ha), rb = b - __bfloat162float(hb);
    uint32_t hp = pack_bf2(ha, hb);
    uint32_t lp = pack_bf2(__float2bfloat16(ra), __float2bfloat16(rb));
    asm volatile("st.shared.b32 [%0], %1;" :: "r"(hoff), "r"(hp) : "memory");
    asm volatile("st.shared.b32 [%0], %1;" :: "r"(loff), "r"(lp) : "memory");
}

// ---------------------------------------------------------------------------
// GEMM: C[m][n] = sum_k A[m][k]*W[n][k] + bias[n]   (as in R3; tcgen05 hi/lo)
// ---------------------------------------------------------------------------
__global__ __launch_bounds__(256)
void tc_gemm(const float* __restrict__ A, const float* __restrict__ W,
             const float* __restrict__ bias, float* __restrict__ out, int mode)
{
    extern __shared__ char dsm[];
    const int t   = threadIdx.x;
    const int m0  = blockIdx.y * 128;
    const int n0  = blockIdx.x * 128;

#if HAS_TCGEN05
    __shared__ uint32_t s_tmem;
    __shared__ __align__(8) uint64_t s_mbar;

    const uint32_t base = (smem_u32(dsm) + 1023u) & ~1023u;
    const uint32_t ah = base, al = base + 16384, bhs = base + 32768, bls = base + 49152;
    const int wid = t >> 5;

    if (wid == 0) {
        asm volatile("tcgen05.alloc.cta_group::1.sync.aligned.shared::cta.b32 [%0], %1;"
                     :: "r"(smem_u32(&s_tmem)), "r"(128u) : "memory");
        asm volatile("tcgen05.relinquish_alloc_permit.cta_group::1.sync.aligned;");
    }
    if (t == 0)
        asm volatile("mbarrier.init.shared.b64 [%0], 1;" :: "r"(smem_u32(&s_mbar)) : "memory");
    __syncthreads();
    const uint32_t tmem = s_tmem;
    const uint32_t mbar = smem_u32(&s_mbar);

    const int ty = t >> 4, c4 = t & 15;
    const float* Ap = A + (size_t)(m0 + ty) * 1024 + c4 * 4;
    const float* Wp = W + (size_t)(n0 + ty) * 1024 + c4 * 4;

    int chunk = 0;
    for (int k0 = 0; k0 < 1024; k0 += 64, ++chunk) {
        float4 av[8], wv[8];
        #pragma unroll
        for (int i = 0; i < 8; i++) {
            av[i] = *(const float4*)(Ap + (size_t)(16 * i) * 1024 + k0);
            wv[i] = *(const float4*)(Wp + (size_t)(16 * i) * 1024 + k0);
        }
        if (chunk > 0) mbar_wait(mbar, (chunk - 1) & 1);
        #pragma unroll
        for (int i = 0; i < 8; i++) {
            uint32_t off = sw128((uint32_t)((ty + 16 * i) * 128 + c4 * 8));
            store_hilo(av[i], ah + off, al + off);
            store_hilo(wv[i], bhs + off, bls + off);
        }
        asm volatile("fence.proxy.async.shared::cta;" ::: "memory");
        __syncthreads();
        if (t == 0) {
            const uint64_t dah = mk_desc(ah),  dal = mk_desc(al);
            const uint64_t dbh = mk_desc(bhs), dbl = mk_desc(bls);
            #pragma unroll
            for (int ks = 0; ks < 4; ks++) {
                mma_ss(tmem, dah + 2 * ks, dbh + 2 * ks, GE_IDESC, !(chunk == 0 && ks == 0));
                mma_ss(tmem, dah + 2 * ks, dbl + 2 * ks, GE_IDESC, true);
                mma_ss(tmem, dal + 2 * ks, dbh + 2 * ks, GE_IDESC, true);
            }
            asm volatile(
                "tcgen05.commit.cta_group::1.mbarrier::arrive::one.shared::cluster.b64 [%0];"
                :: "r"(mbar) : "memory");
        }
    }
    mbar_wait(mbar, (16 - 1) & 1);
    __syncthreads();
    asm volatile("tcgen05.fence::after_thread_sync;" ::: "memory");

    if (wid < 4) {
        const int lane = t & 31;
        const int gr = m0 + wid * 32 + lane;
        for (int cb = 0; cb < 128; cb += 32) {
            uint32_t regs[32];
            LDTM_X32(regs, tmem + cb);
            asm volatile("tcgen05.wait::ld.sync.aligned;" ::: "memory");
            if (mode == 0) {
                float* op = out + (size_t)gr * 1024 + n0 + cb;
                #pragma unroll
                for (int c = 0; c < 32; c++)
                    op[c] = __uint_as_float(regs[c]) + bias[n0 + cb + c];
            } else {
                const int b = gr >> 10, s = gr & 1023;
                #pragma unroll
                for (int c = 0; c < 32; c++) {
                    const int gc = n0 + cb + c;
                    const int h = gc >> 6, d = gc & 63;
                    out[(((size_t)(b * kH + h)) * kS + s) * kDK + d] =
                        __uint_as_float(regs[c]) + bias[gc];
                }
            }
        }
    }
    __syncthreads();
    if (wid == 0)
        asm volatile("tcgen05.dealloc.cta_group::1.sync.aligned.b32 %0, %1;"
                     :: "r"(tmem), "r"(128u));

#else  // ------- FFMA fallback (non-sm_103a device pass; never runs on GB300) -------
    float* As = (float*)dsm;
    float* Bs = As + 16 * 128;
    const int tx = t & 15, ty = t >> 4;
    const int lm = t & 127;
    const int kb = (t >> 7) * 8;

    float acc[8][8];
    #pragma unroll
    for (int i = 0; i < 8; i++)
        #pragma unroll
        for (int j = 0; j < 8; j++) acc[i][j] = 0.f;

    for (int k0 = 0; k0 < 1024; k0 += 16) {
        const float4* Ag = (const float4*)(A + (size_t)(m0 + lm) * 1024 + k0 + kb);
        const float4* Wg = (const float4*)(W + (size_t)(n0 + lm) * 1024 + k0 + kb);
        float4 a0 = Ag[0], a1 = Ag[1];
        float4 b0 = Wg[0], b1 = Wg[1];
        As[(kb+0)*128+lm]=a0.x; As[(kb+1)*128+lm]=a0.y; As[(kb+2)*128+lm]=a0.z; As[(kb+3)*128+lm]=a0.w;
        As[(kb+4)*128+lm]=a1.x; As[(kb+5)*128+lm]=a1.y; As[(kb+6)*128+lm]=a1.z; As[(kb+7)*128+lm]=a1.w;
        Bs[(kb+0)*128+lm]=b0.x; Bs[(kb+1)*128+lm]=b0.y; Bs[(kb+2)*128+lm]=b0.z; Bs[(kb+3)*128+lm]=b0.w;
        Bs[(kb+4)*128+lm]=b1.x; Bs[(kb+5)*128+lm]=b1.y; Bs[(kb+6)*128+lm]=b1.z; Bs[(kb+7)*128+lm]=b1.w;
        __syncthreads();
        #pragma unroll
        for (int kk = 0; kk < 16; kk++) {
            float af[8], bf[8];
            #pragma unroll
            for (int i = 0; i < 8; i++) af[i] = As[kk*128 + ty + 16*i];
            #pragma unroll
            for (int j = 0; j < 8; j++) bf[j] = Bs[kk*128 + tx + 16*j];
            #pragma unroll
            for (int i = 0; i < 8; i++)
                #pragma unroll
                for (int j = 0; j < 8; j++) acc[i][j] += af[i] * bf[j];
        }
        __syncthreads();
    }

    #pragma unroll
    for (int i = 0; i < 8; i++) {
        const int r = m0 + ty + 16*i;
        #pragma unroll
        for (int j = 0; j < 8; j++) {
            const int c = n0 + tx + 16*j;
            float v = acc[i][j] + bias[c];
            if (mode == 0) {
                out[(size_t)r * 1024 + c] = v;
            } else {
                int b = r >> 10, s = r & 1023, h = c >> 6, d = c & 63;
                out[(((size_t)(b * kH + h)) * kS + s) * kDK + d] = v;
            }
        }
    }
#endif
}

// ---------------------------------------------------------------------------
// Small linear: Y = relu(X @ W^T + b), X:[R,64], W:[64,64]. 64 rows per block.
// ---------------------------------------------------------------------------
__global__ __launch_bounds__(256)
void small_linear(const float* __restrict__ X, const float* __restrict__ W,
                  const float* __restrict__ bias, float* __restrict__ out)
{
    __shared__ float Xs[64*64];
    __shared__ float Ws[64*64];
    const int t  = threadIdx.x;
    const int tx = t & 15, ty = t >> 4;
    const int r0 = blockIdx.x * 64;
    const int lr = t & 63;
    const int kb = (t >> 6) * 16;

    #pragma unroll
    for (int q = 0; q < 4; q++) {
        float4 w = *(const float4*)(W + (size_t)lr * 64 + kb + 4*q);
        Ws[(kb+4*q+0)*64 + lr] = w.x;
        Ws[(kb+4*q+1)*64 + lr] = w.y;
        Ws[(kb+4*q+2)*64 + lr] = w.z;
        Ws[(kb+4*q+3)*64 + lr] = w.w;
        float4 x = *(const float4*)(X + (size_t)(r0 + lr) * 64 + kb + 4*q);
        Xs[(kb+4*q+0)*64 + lr] = x.x;
        Xs[(kb+4*q+1)*64 + lr] = x.y;
        Xs[(kb+4*q+2)*64 + lr] = x.z;
        Xs[(kb+4*q+3)*64 + lr] = x.w;
    }
    __syncthreads();

    float acc[4][4];
    #pragma unroll
    for (int i = 0; i < 4; i++)
        #pragma unroll
        for (int j = 0; j < 4; j++) acc[i][j] = 0.f;

    #pragma unroll 16
    for (int kk = 0; kk < 64; kk++) {
        float af[4], bf[4];
        #pragma unroll
        for (int i = 0; i < 4; i++) af[i] = Xs[kk*64 + ty + 16*i];
        #pragma unroll
        for (int j = 0; j < 4; j++) bf[j] = Ws[kk*64 + tx + 16*j];
        #pragma unroll
        for (int i = 0; i < 4; i++)
            #pragma unroll
            for (int j = 0; j < 4; j++) acc[i][j] += af[i] * bf[j];
    }

    #pragma unroll
    for (int i = 0; i < 4; i++) {
        const int r = r0 + ty + 16*i;
        #pragma unroll
        for (int j = 0; j < 4; j++) {
            const int c = tx + 16*j;
            float v = acc[i][j] + bias[c];
            out[(size_t)r * 64 + c] = fmaxf(v, 0.f);
        }
    }
}

// ---------------------------------------------------------------------------
// tcgen05 fused attention:
//   S = q1 @ kr^T (masked), QV = q2 @ vr^T, out = softmax(S)*QV @ k
// One CTA per (bh, 128-row q tile); 128 threads; each thread owns one S row.
// All three GEMMs on tensor cores with bf16 hi/lo split; online softmax in
// registers; PK result read back per 64-key block and accumulated in regs.
// ---------------------------------------------------------------------------
__global__ __launch_bounds__(128)
void attn_tc(const float* __restrict__ q1g, const float* __restrict__ q2g,
             const float* __restrict__ krg, const float* __restrict__ vrg,
             const float* __restrict__ kg,  const int* __restrict__ mask,
             float* __restrict__ outg)
{
    const int t  = threadIdx.x;
    const int bh = blockIdx.y;
    const int q0 = blockIdx.x * 128;
    const int b  = bh >> 4, h = bh & 15;

#if HAS_TCGEN05
    extern __shared__ char dsm[];
    __shared__ uint32_t s_tmem;
    __shared__ __align__(8) uint64_t s_mb[2];

    const uint32_t base = (smem_u32(dsm) + 1023u) & ~1023u;
    const uint32_t q1hS = base,           q1lS = base + 16384;
    const uint32_t q2hS = base + 32768,   q2lS = base + 49152;
    const uint32_t krhS = base + 65536,   krlS = krhS + 8192;
    const uint32_t vrhS = krlS + 8192,    vrlS = vrhS + 8192;
    const uint32_t kthS = vrlS + 8192,    ktlS = kthS + 8192;
    const uint32_t phS  = ktlS + 8192,    plS  = phS + 16384;

    const int wid = t >> 5;
    if (wid == 0) {
        asm volatile("tcgen05.alloc.cta_group::1.sync.aligned.shared::cta.b32 [%0], %1;"
                     :: "r"(smem_u32(&s_tmem)), "r"(256u) : "memory");
        asm volatile("tcgen05.relinquish_alloc_permit.cta_group::1.sync.aligned;");
    }
    if (t == 0) {
        asm volatile("mbarrier.init.shared.b64 [%0], 1;" :: "r"(smem_u32(&s_mb[0])) : "memory");
        asm volatile("mbarrier.init.shared.b64 [%0], 1;" :: "r"(smem_u32(&s_mb[1])) : "memory");
    }
    __syncthreads();
    const uint32_t tmem  = s_tmem;
    const uint32_t mb_sq = smem_u32(&s_mb[0]), mb_pk = smem_u32(&s_mb[1]);
    const uint32_t TS = tmem, TQV = tmem + 64, TPK = tmem + 128;

    // load this CTA's q1/q2 rows once (row t), convert to hi/lo bf16
    {
        const float* p1 = q1g + ((size_t)bh * kS + q0 + t) * kDK;
        const float* p2 = q2g + ((size_t)bh * kS + q0 + t) * kDK;
        #pragma unroll
        for (int c4 = 0; c4 < 16; c4++) {
            uint32_t off = sw128((uint32_t)(t * 128 + c4 * 8));
            store_hilo(((const float4*)p1)[c4], q1hS + off, q1lS + off);
            store_hilo(((const float4*)p2)[c4], q2hS + off, q2lS + off);
        }
    }

    float out[64];
    #pragma unroll
    for (int c = 0; c < 64; c++) out[c] = 0.f;
    float m_i = -1e30f, l_i = 0.f;

    const int rr = t & 63, hf = t >> 6;

    for (int blk = 0; blk < 16; blk++) {
        const int k0 = blk * 64;

        // convert kr, vr (row rr, column half hf)
        const float* krp = krg + ((size_t)bh * kS + k0 + rr) * kDK + hf * 32;
        const float* vrp = vrg + ((size_t)bh * kS + k0 + rr) * kDK + hf * 32;
        #pragma unroll
        for (int i = 0; i < 8; i++) {
            uint32_t off = sw128((uint32_t)(rr * 128 + (hf * 8 + i) * 8));
            store_hilo(((const float4*)krp)[i], krhS + off, krlS + off);
            store_hilo(((const float4*)vrp)[i], vrhS + off, vrlS + off);
        }
        // k transposed: kT[d=rr][key], key pairs kp
        #pragma unroll
        for (int i = 0; i < 16; i++) {
            int kp = hf * 16 + i;
            float a = kg[((size_t)bh * kS + k0 + 2 * kp)     * kDK + rr];
            float c = kg[((size_t)bh * kS + k0 + 2 * kp + 1) * kDK + rr];
            uint32_t off = sw128((uint32_t)(rr * 128 + kp * 4));
            store_hilo4(a, c, kthS + off, ktlS + off);
        }
        asm volatile("fence.proxy.async.shared::cta;" ::: "memory");
        __syncthreads();

        if (t == 0) {
            const uint64_t a1h = mk_desc(q1hS), a1l = mk_desc(q1lS);
            const uint64_t a2h = mk_desc(q2hS), a2l = mk_desc(q2lS);
            const uint64_t bkh = mk_desc(krhS), bkl = mk_desc(krlS);
            const uint64_t bvh = mk_desc(vrhS), bvl = mk_desc(vrlS);
            #pragma unroll
            for (int ks = 0; ks < 4; ks++) {
                mma_ss(TS,  a1h + 2*ks, bkh + 2*ks, AT_IDESC, ks > 0);
                mma_ss(TS,  a1h + 2*ks, bkl + 2*ks, AT_IDESC, true);
                mma_ss(TS,  a1l + 2*ks, bkh + 2*ks, AT_IDESC, true);
                mma_ss(TQV, a2h + 2*ks, bvh + 2*ks, AT_IDESC, ks > 0);
                mma_ss(TQV, a2h + 2*ks, bvl + 2*ks, AT_IDESC, true);
                mma_ss(TQV, a2l + 2*ks, bvh + 2*ks, AT_IDESC, true);
            }
            asm volatile(
                "tcgen05.commit.cta_group::1.mbarrier::arrive::one.shared::cluster.b64 [%0];"
                :: "r"(mb_sq) : "memory");
        }
        mbar_wait(mb_sq, blk & 1);
        asm volatile("tcgen05.fence::after_thread_sync;" ::: "memory");

        // read S row (thread t owns TMEM row t)
        uint32_t sr[64];
        LDTM_X32(sr, TS);
        LDTM_X32(sr + 32, TS + 32);
        asm volatile("tcgen05.wait::ld.sync.aligned;" ::: "memory");

        // mask (reference: where mask==0 -> -1e9)
        const int4* mp = (const int4*)(mask + (size_t)b * kS * kS + (size_t)(q0 + t) * kS + k0);
        #pragma unroll
        for (int j4 = 0; j4 < 16; j4++) {
            int4 mv = mp[j4];
            if (mv.x == 0) sr[4*j4+0] = __float_as_uint(-1.0e9f);
            if (mv.y == 0) sr[4*j4+1] = __float_as_uint(-1.0e9f);
            if (mv.z == 0) sr[4*j4+2] = __float_as_uint(-1.0e9f);
            if (mv.w == 0) sr[4*j4+3] = __float_as_uint(-1.0e9f);
        }

        float rmax = -1e30f;
        #pragma unroll
        for (int j = 0; j < 64; j++) rmax = fmaxf(rmax, __uint_as_float(sr[j]));
        const float mnew = fmaxf(m_i, rmax);
        const float sc   = __expf(m_i - mnew);
        float rsum = 0.f;

        // p = exp(s - mnew); P~ = p * qv  (stash P~ back into sr)
        #pragma unroll
        for (int half = 0; half < 2; half++) {
            uint32_t qr[32];
            LDTM_X32(qr, TQV + 32 * half);
            asm volatile("tcgen05.wait::ld.sync.aligned;" ::: "memory");
            #pragma unroll
            for (int j = 0; j < 32; j++) {
                float p = __expf(__uint_as_float(sr[32*half + j]) - mnew);
                rsum += p;
                sr[32*half + j] = __float_as_uint(p * __uint_as_float(qr[j]));
            }
        }
        m_i = mnew;
        l_i = l_i * sc + rsum;

        // store P~ hi/lo (row t, key pairs)
        #pragma unroll
        for (int j = 0; j < 32; j++) {
            uint32_t off = sw128((uint32_t)(t * 128 + j * 4));
            store_hilo4(__uint_as_float(sr[2*j]), __uint_as_float(sr[2*j+1]),
                        phS + off, plS + off);
        }
        #pragma unroll
        for (int c = 0; c < 64; c++) out[c] *= sc;

        asm volatile("fence.proxy.async.shared::cta;" ::: "memory");
        __syncthreads();

        if (t == 0) {
            const uint64_t aph = mk_desc(phS), apl = mk_desc(plS);
            const uint64_t bth = mk_desc(kthS), btl = mk_desc(ktlS);
            #pragma unroll
            for (int ks = 0; ks < 4; ks++) {
                mma_ss(TPK, aph + 2*ks, bth + 2*ks, AT_IDESC, ks > 0);
                mma_ss(TPK, aph + 2*ks, btl + 2*ks, AT_IDESC, true);
                mma_ss(TPK, apl + 2*ks, bth + 2*ks, AT_IDESC, true);
            }
            asm volatile(
                "tcgen05.commit.cta_group::1.mbarrier::arrive::one.shared::cluster.b64 [%0];"
                :: "r"(mb_pk) : "memory");
        }
        mbar_wait(mb_pk, blk & 1);
        asm volatile("tcgen05.fence::after_thread_sync;" ::: "memory");

        #pragma unroll
        for (int half = 0; half < 2; half++) {
            uint32_t pr[32];
            LDTM_X32(pr, TPK + 32 * half);
            asm volatile("tcgen05.wait::ld.sync.aligned;" ::: "memory");
            #pragma unroll
            for (int j = 0; j < 32; j++)
                out[32*half + j] += __uint_as_float(pr[j]);
        }
        asm volatile("tcgen05.fence::before_thread_sync;" ::: "memory");
    }

    // normalize + write row (b, q0+t), head h
    const float inv = 1.0f / l_i;
    float4* op = (float4*)(outg + ((size_t)b * kS + q0 + t) * kDM + h * 64);
    #pragma unroll
    for (int c4 = 0; c4 < 16; c4++) {
        float4 v;
        v.x = out[4*c4+0] * inv; v.y = out[4*c4+1] * inv;
        v.z = out[4*c4+2] * inv; v.w = out[4*c4+3] * inv;
        op[c4] = v;
    }
    __syncthreads();
    if (wid == 0)
        asm volatile("tcgen05.dealloc.cta_group::1.sync.aligned.b32 %0, %1;"
                     :: "r"(tmem), "r"(256u));

#else  // ------- naive FFMA fallback (never runs on GB300) -------
    const float* p1 = q1g + ((size_t)bh * kS + q0 + t) * kDK;
    const float* p2 = q2g + ((size_t)bh * kS + q0 + t) * kDK;
    float q1r[64], q2r[64], out[64];
    for (int d = 0; d < 64; d++) { q1r[d] = p1[d]; q2r[d] = p2[d]; out[d] = 0.f; }
    float m_i = -1e30f, l_i = 0.f;
    for (int j = 0; j < kS; j++) {
        const float* krj = krg + ((size_t)bh * kS + j) * kDK;
        const float* vrj = vrg + ((size_t)bh * kS + j) * kDK;
        float s = 0.f, qv = 0.f;
        for (int d = 0; d < 64; d++) { s += q1r[d] * krj[d]; qv += q2r[d] * vrj[d]; }
        if (mask[(size_t)b * kS * kS + (size_t)(q0 + t) * kS + j] == 0) s = -1.0e9f;
        float mnew = fmaxf(m_i, s);
        float scv = __expf(m_i - mnew), p = __expf(s - mnew);
        const float* kj = kg + ((size_t)bh * kS + j) * kDK;
        for (int d = 0; d < 64; d++) out[d] = out[d] * scv + p * qv * kj[d];
        l_i = l_i * scv + p;
        m_i = mnew;
    }
    const float inv = 1.0f / l_i;
    for (int d = 0; d < 64; d++)
        outg[((size_t)b * kS + q0 + t) * kDM + h * 64 + d] = out[d] * inv;
#endif
}

// ---------------------------------------------------------------------------
extern "C" void kernel_launch(void* const* d_in, const int* in_sizes, int n_in,
                              void* d_out, int out_size)
{
    (void)in_sizes; (void)n_in; (void)out_size;
    const float* query = (const float*)d_in[0];
    const float* key_  = (const float*)d_in[1];
    const float* value = (const float*)d_in[2];
    const int*   mask  = (const int*)  d_in[3];
    const float* Wq  = (const float*)d_in[4];  const float* bq  = (const float*)d_in[5];
    const float* Wk  = (const float*)d_in[6];  const float* bk  = (const float*)d_in[7];
    const float* Wv  = (const float*)d_in[8];  const float* bv  = (const float*)d_in[9];
    const float* Wo  = (const float*)d_in[10]; const float* bo  = (const float*)d_in[11];
    const float* Wkl = (const float*)d_in[12]; const float* bkl = (const float*)d_in[13];
    const float* Wql = (const float*)d_in[14]; const float* bql = (const float*)d_in[15];
    const float* Wq2 = (const float*)d_in[16]; const float* bq2 = (const float*)d_in[17];
    const float* Wvl = (const float*)d_in[18]; const float* bvl = (const float*)d_in[19];
    const float* Wel = (const float*)d_in[20]; const float* bel = (const float*)d_in[21];

    float *qh, *kh, *vh, *kr, *q1a, *q1, *q2, *vr, *att;
    cudaGetSymbolAddress((void**)&qh,  g_qh);
    cudaGetSymbolAddress((void**)&kh,  g_kh);
    cudaGetSymbolAddress((void**)&vh,  g_vh);
    cudaGetSymbolAddress((void**)&kr,  g_kr);
    cudaGetSymbolAddress((void**)&q1a, g_q1a);
    cudaGetSymbolAddress((void**)&q1,  g_q1);
    cudaGetSymbolAddress((void**)&q2,  g_q2);
    cudaGetSymbolAddress((void**)&vr,  g_vr);
    cudaGetSymbolAddress((void**)&att, g_att);

    const int GEMM_SMEM = 66560;
    cudaFuncSetAttribute(tc_gemm, cudaFuncAttributeMaxDynamicSharedMemorySize, GEMM_SMEM);

    dim3 gg(8, 32);

    // Q/K/V projections -> head-split [BH, S, DK]
    tc_gemm<<<gg, 256, GEMM_SMEM>>>(query, Wq, bq, qh, 1);
    tc_gemm<<<gg, 256, GEMM_SMEM>>>(key_,  Wk, bk, kh, 1);
    tc_gemm<<<gg, 256, GEMM_SMEM>>>(value, Wv, bv, vh, 1);

    // per-head small linears
    small_linear<<<1024, 256>>>(kh,  Wkl, bkl, kr);   // key_refine
    small_linear<<<1024, 256>>>(qh,  Wql, bql, q1a);  // q1 stage 1
    small_linear<<<1024, 256>>>(q1a, Wel, bel, q1);   // q1 stage 2
    small_linear<<<1024, 256>>>(qh,  Wq2, bq2, q2);   // q2
    small_linear<<<1024, 256>>>(vh,  Wvl, bvl, vr);   // v_refine

    // tcgen05 fused attention (145 KB dynamic smem)
    const int ATT_SMEM = 148480;
    cudaFuncSetAttribute(attn_tc, cudaFuncAttributeMaxDynamicSharedMemorySize, ATT_SMEM);
    attn_tc<<<dim3(8, 64), 128, ATT_SMEM>>>(q1, q2, kr, vr, kh, mask, att);

    // output projection -> d_out
    tc_gemm<<<gg, 256, GEMM_SMEM>>>(att, Wo, bo, (float*)d_out, 0);
}

// round 6
// speedup vs baseline: 3.7402x; 1.1855x over previous
#include <cuda_runtime.h>
#include <cuda_bf16.h>
#include <cstdint>

static constexpr int kB  = 4;
static constexpr int kS  = 1024;
static constexpr int kDM = 1024;
static constexpr int kH  = 16;
static constexpr int kDK = 64;
static constexpr int kBH = kB * kH;   // 64

// ---------------- scratch (static device globals; no allocation) ----------------
__device__ float g_qh [kBH * kS * kDK];
__device__ float g_kh [kBH * kS * kDK];
__device__ float g_vh [kBH * kS * kDK];
__device__ float g_kr [kBH * kS * kDK];
__device__ float g_q1 [kBH * kS * kDK];
__device__ float g_q2 [kBH * kS * kDK];
__device__ float g_vr [kBH * kS * kDK];
__device__ float g_att[kB * kS * kDM];

// ---------------------------------------------------------------------------
// PTX helpers
// ---------------------------------------------------------------------------
__device__ __forceinline__ uint32_t smem_u32(const void* p) {
    uint32_t a;
    asm("{ .reg .u64 t; cvta.to.shared.u64 t, %1; cvt.u32.u64 %0, t; }" : "=r"(a) : "l"(p));
    return a;
}

__device__ __forceinline__ uint32_t pack_bf2(__nv_bfloat16 a, __nv_bfloat16 b) {
    __nv_bfloat162 t = __halves2bfloat162(a, b);
    return *reinterpret_cast<uint32_t*>(&t);
}

__device__ __forceinline__ uint32_t sw128(uint32_t o) { return o ^ ((o >> 3) & 0x70); }

#if defined(__CUDA_ARCH_FEAT_SM103_ALL) || !defined(__CUDA_ARCH__)
#define HAS_TCGEN05 1
#else
#define HAS_TCGEN05 0
#endif

#if HAS_TCGEN05
__device__ __forceinline__ void mbar_wait(uint32_t mbar, uint32_t parity) {
    asm volatile(
        "{\n\t.reg .pred P;\n\t"
        "LW%=:\n\t"
        "mbarrier.try_wait.parity.acquire.cta.shared::cta.b64 P, [%0], %1;\n\t"
        "@!P bra LW%=;\n\t}"
        :: "r"(mbar), "r"(parity) : "memory");
}

// idesc: F32 accum, BF16 a/b, K-major both
static constexpr uint32_t GE_IDESC =           // M=128, N=128
    (1u << 4) | (1u << 7) | (1u << 10) | ((128u / 8) << 17) | ((128u / 16) << 24);
static constexpr uint32_t AT_IDESC =           // M=128, N=64
    (1u << 4) | (1u << 7) | (1u << 10) | ((64u / 8) << 17) | ((128u / 16) << 24);

// SW128 K-major smem descriptor base (version=1 Blackwell, LBO=1, SBO=64)
static constexpr uint64_t DESC_SW128 =
    (2ull << 61) | (1ull << 46) | (64ull << 32) | (1ull << 16);

__device__ __forceinline__ uint64_t mk_desc(uint32_t addr) {
    return DESC_SW128 | (uint64_t)((addr >> 4) & 0x3FFF);
}

// SS form (A in smem)
__device__ __forceinline__ void mma_ss(uint32_t d, uint64_t ad, uint64_t bd,
                                       uint32_t idesc, bool en) {
    uint32_t e = en ? 1u : 0u;
    asm volatile(
        "{\n\t.reg .pred p;\n\t"
        "setp.ne.u32 p, %5, 0;\n\t"
        "tcgen05.mma.cta_group::1.kind::f16 [%0], %1, %2, %3, {%4, %4, %4, %4}, p;\n\t}"
        :: "r"(d), "l"(ad), "l"(bd), "r"(idesc), "r"(0u), "r"(e) : "memory");
}

// TS form (A in TMEM)
__device__ __forceinline__ void mma_ts(uint32_t d, uint32_t at, uint64_t bd,
                                       uint32_t idesc, bool en) {
    uint32_t e = en ? 1u : 0u;
    asm volatile(
        "{\n\t.reg .pred p;\n\t"
        "setp.ne.u32 p, %5, 0;\n\t"
        "tcgen05.mma.cta_group::1.kind::f16 [%0], [%1], %2, %3, {%4, %4, %4, %4}, p;\n\t}"
        :: "r"(d), "r"(at), "l"(bd), "r"(idesc), "r"(0u), "r"(e) : "memory");
}

#define LDTM_X32(r, addr) \
    asm volatile( \
        "tcgen05.ld.sync.aligned.32x32b.x32.b32 " \
        "{%0, %1, %2, %3, %4, %5, %6, %7, " \
        " %8, %9, %10, %11, %12, %13, %14, %15, " \
        " %16, %17, %18, %19, %20, %21, %22, %23, " \
        " %24, %25, %26, %27, %28, %29, %30, %31}, [%32];" \
        : "=r"((r)[0]),  "=r"((r)[1]),  "=r"((r)[2]),  "=r"((r)[3]), \
          "=r"((r)[4]),  "=r"((r)[5]),  "=r"((r)[6]),  "=r"((r)[7]), \
          "=r"((r)[8]),  "=r"((r)[9]),  "=r"((r)[10]), "=r"((r)[11]), \
          "=r"((r)[12]), "=r"((r)[13]), "=r"((r)[14]), "=r"((r)[15]), \
          "=r"((r)[16]), "=r"((r)[17]), "=r"((r)[18]), "=r"((r)[19]), \
          "=r"((r)[20]), "=r"((r)[21]), "=r"((r)[22]), "=r"((r)[23]), \
          "=r"((r)[24]), "=r"((r)[25]), "=r"((r)[26]), "=r"((r)[27]), \
          "=r"((r)[28]), "=r"((r)[29]), "=r"((r)[30]), "=r"((r)[31]) \
        : "r"(addr))

#define TSTM_X32(addr, r) \
    asm volatile( \
        "tcgen05.st.sync.aligned.32x32b.x32.b32 [%0], " \
        "{%1, %2, %3, %4, %5, %6, %7, %8, " \
        " %9, %10, %11, %12, %13, %14, %15, %16, " \
        " %17, %18, %19, %20, %21, %22, %23, %24, " \
        " %25, %26, %27, %28, %29, %30, %31, %32};" \
        :: "r"(addr), \
           "r"((r)[0]),  "r"((r)[1]),  "r"((r)[2]),  "r"((r)[3]), \
           "r"((r)[4]),  "r"((r)[5]),  "r"((r)[6]),  "r"((r)[7]), \
           "r"((r)[8]),  "r"((r)[9]),  "r"((r)[10]), "r"((r)[11]), \
           "r"((r)[12]), "r"((r)[13]), "r"((r)[14]), "r"((r)[15]), \
           "r"((r)[16]), "r"((r)[17]), "r"((r)[18]), "r"((r)[19]), \
           "r"((r)[20]), "r"((r)[21]), "r"((r)[22]), "r"((r)[23]), \
           "r"((r)[24]), "r"((r)[25]), "r"((r)[26]), "r"((r)[27]), \
           "r"((r)[28]), "r"((r)[29]), "r"((r)[30]), "r"((r)[31]) \
        : "memory")
#endif  // HAS_TCGEN05

// convert float4 -> bf16 hi + bf16 residual, store 8B to each smem tile
__device__ __forceinline__ void store_hilo(float4 v, uint32_t hoff, uint32_t loff) {
    __nv_bfloat16 h0 = __float2bfloat16(v.x), h1 = __float2bfloat16(v.y);
    __nv_bfloat16 h2 = __float2bfloat16(v.z), h3 = __float2bfloat16(v.w);
    float r0 = v.x - __bfloat162float(h0), r1 = v.y - __bfloat162float(h1);
    float r2 = v.z - __bfloat162float(h2), r3 = v.w - __bfloat162float(h3);
    __nv_bfloat16 l0 = __float2bfloat16(r0), l1 = __float2bfloat16(r1);
    __nv_bfloat16 l2 = __float2bfloat16(r2), l3 = __float2bfloat16(r3);
    uint32_t hp0 = pack_bf2(h0, h1), hp1 = pack_bf2(h2, h3);
    uint32_t lp0 = pack_bf2(l0, l1), lp1 = pack_bf2(l2, l3);
    asm volatile("st.shared.v2.b32 [%0], {%1, %2};" :: "r"(hoff), "r"(hp0), "r"(hp1) : "memory");
    asm volatile("st.shared.v2.b32 [%0], {%1, %2};" :: "r"(loff), "r"(lp0), "r"(lp1) : "memory");
}

// two floats -> one bf16x2 hi + one bf16x2 residual, 4B each
__device__ __forceinline__ void store_hilo4(float a, float b, uint32_t hoff, uint32_t loff) {
    __nv_bfloat16 ha = __float2bfloat16(a), hb = __float2bfloat16(b);
    float ra = a - __bfloat162float(ha), rb = b - __bfloat162float(hb);
    uint32_t hp = pack_bf2(ha, hb);
    uint32_t lp = pack_bf2(__float2bfloat16(ra), __float2bfloat16(rb));
    asm volatile("st.shared.b32 [%0], %1;" :: "r"(hoff), "r"(hp) : "memory");
    asm volatile("st.shared.b32 [%0], %1;" :: "r"(loff), "r"(lp) : "memory");
}

// ---------------------------------------------------------------------------
// GEMM: C[m][n] = sum_k A[m][k]*W[n][k] + bias[n]   (tcgen05 bf16 hi/lo)
// ---------------------------------------------------------------------------
__global__ __launch_bounds__(256)
void tc_gemm(const float* __restrict__ A, const float* __restrict__ W,
             const float* __restrict__ bias, float* __restrict__ out, int mode)
{
    extern __shared__ char dsm[];
    const int t   = threadIdx.x;
    const int m0  = blockIdx.y * 128;
    const int n0  = blockIdx.x * 128;

#if HAS_TCGEN05
    __shared__ uint32_t s_tmem;
    __shared__ __align__(8) uint64_t s_mbar;

    const uint32_t base = (smem_u32(dsm) + 1023u) & ~1023u;
    const uint32_t ah = base, al = base + 16384, bhs = base + 32768, bls = base + 49152;
    const int wid = t >> 5;

    if (wid == 0) {
        asm volatile("tcgen05.alloc.cta_group::1.sync.aligned.shared::cta.b32 [%0], %1;"
                     :: "r"(smem_u32(&s_tmem)), "r"(128u) : "memory");
        asm volatile("tcgen05.relinquish_alloc_permit.cta_group::1.sync.aligned;");
    }
    if (t == 0)
        asm volatile("mbarrier.init.shared.b64 [%0], 1;" :: "r"(smem_u32(&s_mbar)) : "memory");
    __syncthreads();
    const uint32_t tmem = s_tmem;
    const uint32_t mbar = smem_u32(&s_mbar);

    const int ty = t >> 4, c4 = t & 15;
    const float* Ap = A + (size_t)(m0 + ty) * 1024 + c4 * 4;
    const float* Wp = W + (size_t)(n0 + ty) * 1024 + c4 * 4;

    int chunk = 0;
    for (int k0 = 0; k0 < 1024; k0 += 64, ++chunk) {
        float4 av[8], wv[8];
        #pragma unroll
        for (int i = 0; i < 8; i++) {
            av[i] = *(const float4*)(Ap + (size_t)(16 * i) * 1024 + k0);
            wv[i] = *(const float4*)(Wp + (size_t)(16 * i) * 1024 + k0);
        }
        if (chunk > 0) mbar_wait(mbar, (chunk - 1) & 1);
        #pragma unroll
        for (int i = 0; i < 8; i++) {
            uint32_t off = sw128((uint32_t)((ty + 16 * i) * 128 + c4 * 8));
            store_hilo(av[i], ah + off, al + off);
            store_hilo(wv[i], bhs + off, bls + off);
        }
        asm volatile("fence.proxy.async.shared::cta;" ::: "memory");
        __syncthreads();
        if (t == 0) {
            const uint64_t dah = mk_desc(ah),  dal = mk_desc(al);
            const uint64_t dbh = mk_desc(bhs), dbl = mk_desc(bls);
            #pragma unroll
            for (int ks = 0; ks < 4; ks++) {
                mma_ss(tmem, dah + 2 * ks, dbh + 2 * ks, GE_IDESC, !(chunk == 0 && ks == 0));
                mma_ss(tmem, dah + 2 * ks, dbl + 2 * ks, GE_IDESC, true);
                mma_ss(tmem, dal + 2 * ks, dbh + 2 * ks, GE_IDESC, true);
            }
            asm volatile(
                "tcgen05.commit.cta_group::1.mbarrier::arrive::one.shared::cluster.b64 [%0];"
                :: "r"(mbar) : "memory");
        }
    }
    mbar_wait(mbar, (16 - 1) & 1);
    __syncthreads();
    asm volatile("tcgen05.fence::after_thread_sync;" ::: "memory");

    if (wid < 4) {
        const int lane = t & 31;
        const int gr = m0 + wid * 32 + lane;
        for (int cb = 0; cb < 128; cb += 32) {
            uint32_t regs[32];
            LDTM_X32(regs, tmem + cb);
            asm volatile("tcgen05.wait::ld.sync.aligned;" ::: "memory");
            if (mode == 0) {
                float* op = out + (size_t)gr * 1024 + n0 + cb;
                #pragma unroll
                for (int c = 0; c < 32; c++)
                    op[c] = __uint_as_float(regs[c]) + bias[n0 + cb + c];
            } else {
                const int b = gr >> 10, s = gr & 1023;
                #pragma unroll
                for (int c = 0; c < 32; c++) {
                    const int gc = n0 + cb + c;
                    const int h = gc >> 6, d = gc & 63;
                    out[(((size_t)(b * kH + h)) * kS + s) * kDK + d] =
                        __uint_as_float(regs[c]) + bias[gc];
                }
            }
        }
    }
    __syncthreads();
    if (wid == 0)
        asm volatile("tcgen05.dealloc.cta_group::1.sync.aligned.b32 %0, %1;"
                     :: "r"(tmem), "r"(128u));

#else  // ------- FFMA fallback (non-sm_103a device pass; never runs on GB300) -------
    float* As = (float*)dsm;
    float* Bs = As + 16 * 128;
    const int tx = t & 15, ty = t >> 4;
    const int lm = t & 127;
    const int kb = (t >> 7) * 8;

    float acc[8][8];
    #pragma unroll
    for (int i = 0; i < 8; i++)
        #pragma unroll
        for (int j = 0; j < 8; j++) acc[i][j] = 0.f;

    for (int k0 = 0; k0 < 1024; k0 += 16) {
        const float4* Ag = (const float4*)(A + (size_t)(m0 + lm) * 1024 + k0 + kb);
        const float4* Wg = (const float4*)(W + (size_t)(n0 + lm) * 1024 + k0 + kb);
        float4 a0 = Ag[0], a1 = Ag[1];
        float4 b0 = Wg[0], b1 = Wg[1];
        As[(kb+0)*128+lm]=a0.x; As[(kb+1)*128+lm]=a0.y; As[(kb+2)*128+lm]=a0.z; As[(kb+3)*128+lm]=a0.w;
        As[(kb+4)*128+lm]=a1.x; As[(kb+5)*128+lm]=a1.y; As[(kb+6)*128+lm]=a1.z; As[(kb+7)*128+lm]=a1.w;
        Bs[(kb+0)*128+lm]=b0.x; Bs[(kb+1)*128+lm]=b0.y; Bs[(kb+2)*128+lm]=b0.z; Bs[(kb+3)*128+lm]=b0.w;
        Bs[(kb+4)*128+lm]=b1.x; Bs[(kb+5)*128+lm]=b1.y; Bs[(kb+6)*128+lm]=b1.z; Bs[(kb+7)*128+lm]=b1.w;
        __syncthreads();
        #pragma unroll
        for (int kk = 0; kk < 16; kk++) {
            float af[8], bf[8];
            #pragma unroll
            for (int i = 0; i < 8; i++) af[i] = As[kk*128 + ty + 16*i];
            #pragma unroll
            for (int j = 0; j < 8; j++) bf[j] = Bs[kk*128 + tx + 16*j];
            #pragma unroll
            for (int i = 0; i < 8; i++)
                #pragma unroll
                for (int j = 0; j < 8; j++) acc[i][j] += af[i] * bf[j];
        }
        __syncthreads();
    }

    #pragma unroll
    for (int i = 0; i < 8; i++) {
        const int r = m0 + ty + 16*i;
        #pragma unroll
        for (int j = 0; j < 8; j++) {
            const int c = n0 + tx + 16*j;
            float v = acc[i][j] + bias[c];
            if (mode == 0) {
                out[(size_t)r * 1024 + c] = v;
            } else {
                int b = r >> 10, s = r & 1023, h = c >> 6, d = c & 63;
                out[(((size_t)(b * kH + h)) * kS + s) * kDK + d] = v;
            }
        }
    }
#endif
}

// ---------------------------------------------------------------------------
// Fused q-chain: q1 = relu(relu(q@Wql+b)@Wel+b), q2 = relu(q@Wq2+b)
// Reads qh once; q1a intermediate stays in smem. 64 rows per block.
// ---------------------------------------------------------------------------
__global__ __launch_bounds__(256)
void fused_q(const float* __restrict__ X,
             const float* __restrict__ Wql, const float* __restrict__ bql,
             const float* __restrict__ Wel, const float* __restrict__ bel,
             const float* __restrict__ Wq2, const float* __restrict__ bq2,
             float* __restrict__ q1, float* __restrict__ q2)
{
    extern __shared__ float fs[];
    float* Xs = fs;             // [k][m] 64x64
    float* Ys = Xs + 4096;      // [k][m] stride 65 (q1a)
    float* W1 = Ys + 64 * 65;   // Wql [k][n]
    float* W2 = W1 + 4096;      // Wel
    float* W3 = W2 + 4096;      // Wq2

    const int t  = threadIdx.x;
    const int tx = t & 15, ty = t >> 4;
    const int r0 = blockIdx.x * 64;
    const int lr = t & 63;
    const int kb = (t >> 6) * 16;

    #pragma unroll
    for (int q = 0; q < 4; q++) {
        float4 w1 = *(const float4*)(Wql + (size_t)lr * 64 + kb + 4*q);
        float4 w2 = *(const float4*)(Wel + (size_t)lr * 64 + kb + 4*q);
        float4 w3 = *(const float4*)(Wq2 + (size_t)lr * 64 + kb + 4*q);
        W1[(kb+4*q+0)*64+lr]=w1.x; W1[(kb+4*q+1)*64+lr]=w1.y; W1[(kb+4*q+2)*64+lr]=w1.z; W1[(kb+4*q+3)*64+lr]=w1.w;
        W2[(kb+4*q+0)*64+lr]=w2.x; W2[(kb+4*q+1)*64+lr]=w2.y; W2[(kb+4*q+2)*64+lr]=w2.z; W2[(kb+4*q+3)*64+lr]=w2.w;
        W3[(kb+4*q+0)*64+lr]=w3.x; W3[(kb+4*q+1)*64+lr]=w3.y; W3[(kb+4*q+2)*64+lr]=w3.z; W3[(kb+4*q+3)*64+lr]=w3.w;
        float4 x = *(const float4*)(X + (size_t)(r0 + lr) * 64 + kb + 4*q);
        Xs[(kb+4*q+0)*64+lr]=x.x; Xs[(kb+4*q+1)*64+lr]=x.y; Xs[(kb+4*q+2)*64+lr]=x.z; Xs[(kb+4*q+3)*64+lr]=x.w;
    }
    __syncthreads();

    // stage 1: q1a = relu(X @ Wql^T + bql) -> Ys [k][m]
    {
        float acc[4][4];
        #pragma unroll
        for (int i = 0; i < 4; i++)
            #pragma unroll
            for (int j = 0; j < 4; j++) acc[i][j] = 0.f;
        #pragma unroll 16
        for (int kk = 0; kk < 64; kk++) {
            float af[4], bf[4];
            #pragma unroll
            for (int i = 0; i < 4; i++) af[i] = Xs[kk*64 + ty + 16*i];
            #pragma unroll
            for (int j = 0; j < 4; j++) bf[j] = W1[kk*64 + tx + 16*j];
            #pragma unroll
            for (int i = 0; i < 4; i++)
                #pragma unroll
                for (int j = 0; j < 4; j++) acc[i][j] += af[i] * bf[j];
        }
        #pragma unroll
        for (int i = 0; i < 4; i++)
            #pragma unroll
            for (int j = 0; j < 4; j++) {
                float v = fmaxf(acc[i][j] + bql[tx + 16*j], 0.f);
                Ys[(tx + 16*j) * 65 + ty + 16*i] = v;
            }
    }
    __syncthreads();

    // stage 2: q1 = relu(q1a @ Wel^T + bel) -> global
    {
        float acc[4][4];
        #pragma unroll
        for (int i = 0; i < 4; i++)
            #pragma unroll
            for (int j = 0; j < 4; j++) acc[i][j] = 0.f;
        #pragma unroll 16
        for (int kk = 0; kk < 64; kk++) {
            float af[4], bf[4];
            #pragma unroll
            for (int i = 0; i < 4; i++) af[i] = Ys[kk*65 + ty + 16*i];
            #pragma unroll
            for (int j = 0; j < 4; j++) bf[j] = W2[kk*64 + tx + 16*j];
            #pragma unroll
            for (int i = 0; i < 4; i++)
                #pragma unroll
                for (int j = 0; j < 4; j++) acc[i][j] += af[i] * bf[j];
        }
        #pragma unroll
        for (int i = 0; i < 4; i++)
            #pragma unroll
            for (int j = 0; j < 4; j++)
                q1[(size_t)(r0 + ty + 16*i) * 64 + tx + 16*j] =
                    fmaxf(acc[i][j] + bel[tx + 16*j], 0.f);
    }

    // stage 3: q2 = relu(X @ Wq2^T + bq2) -> global
    {
        float acc[4][4];
        #pragma unroll
        for (int i = 0; i < 4; i++)
            #pragma unroll
            for (int j = 0; j < 4; j++) acc[i][j] = 0.f;
        #pragma unroll 16
        for (int kk = 0; kk < 64; kk++) {
            float af[4], bf[4];
            #pragma unroll
            for (int i = 0; i < 4; i++) af[i] = Xs[kk*64 + ty + 16*i];
            #pragma unroll
            for (int j = 0; j < 4; j++) bf[j] = W3[kk*64 + tx + 16*j];
            #pragma unroll
            for (int i = 0; i < 4; i++)
                #pragma unroll
                for (int j = 0; j < 4; j++) acc[i][j] += af[i] * bf[j];
        }
        #pragma unroll
        for (int i = 0; i < 4; i++)
            #pragma unroll
            for (int j = 0; j < 4; j++)
                q2[(size_t)(r0 + ty + 16*i) * 64 + tx + 16*j] =
                    fmaxf(acc[i][j] + bq2[tx + 16*j], 0.f);
    }
}

// ---------------------------------------------------------------------------
// Fused kv: kr = relu(kh@Wkl+b), vr = relu(vh@Wvl+b). 64 rows per block.
// ---------------------------------------------------------------------------
__global__ __launch_bounds__(256)
void fused_kv(const float* __restrict__ Kh, const float* __restrict__ Vh,
              const float* __restrict__ Wkl, const float* __restrict__ bkl,
              const float* __restrict__ Wvl, const float* __restrict__ bvl,
              float* __restrict__ kr, float* __restrict__ vr)
{
    extern __shared__ float fs[];
    float* Xs = fs;             // [k][m]
    float* W1 = Xs + 4096;      // Wkl [k][n]
    float* W2 = W1 + 4096;      // Wvl

    const int t  = threadIdx.x;
    const int tx = t & 15, ty = t >> 4;
    const int r0 = blockIdx.x * 64;
    const int lr = t & 63;
    const int kb = (t >> 6) * 16;

    #pragma unroll
    for (int q = 0; q < 4; q++) {
        float4 w1 = *(const float4*)(Wkl + (size_t)lr * 64 + kb + 4*q);
        float4 w2 = *(const float4*)(Wvl + (size_t)lr * 64 + kb + 4*q);
        W1[(kb+4*q+0)*64+lr]=w1.x; W1[(kb+4*q+1)*64+lr]=w1.y; W1[(kb+4*q+2)*64+lr]=w1.z; W1[(kb+4*q+3)*64+lr]=w1.w;
        W2[(kb+4*q+0)*64+lr]=w2.x; W2[(kb+4*q+1)*64+lr]=w2.y; W2[(kb+4*q+2)*64+lr]=w2.z; W2[(kb+4*q+3)*64+lr]=w2.w;
    }

    #pragma unroll
    for (int pass = 0; pass < 2; pass++) {
        const float* src = pass == 0 ? Kh : Vh;
        float* dst       = pass == 0 ? kr : vr;
        const float* Wsm = pass == 0 ? W1 : W2;
        const float* bb  = pass == 0 ? bkl : bvl;

        __syncthreads();
        #pragma unroll
        for (int q = 0; q < 4; q++) {
            float4 x = *(const float4*)(src + (size_t)(r0 + lr) * 64 + kb + 4*q);
            Xs[(kb+4*q+0)*64+lr]=x.x; Xs[(kb+4*q+1)*64+lr]=x.y;
            Xs[(kb+4*q+2)*64+lr]=x.z; Xs[(kb+4*q+3)*64+lr]=x.w;
        }
        __syncthreads();

        float acc[4][4];
        #pragma unroll
        for (int i = 0; i < 4; i++)
            #pragma unroll
            for (int j = 0; j < 4; j++) acc[i][j] = 0.f;
        #pragma unroll 16
        for (int kk = 0; kk < 64; kk++) {
            float af[4], bf[4];
            #pragma unroll
            for (int i = 0; i < 4; i++) af[i] = Xs[kk*64 + ty + 16*i];
            #pragma unroll
            for (int j = 0; j < 4; j++) bf[j] = Wsm[kk*64 + tx + 16*j];
            #pragma unroll
            for (int i = 0; i < 4; i++)
                #pragma unroll
                for (int j = 0; j < 4; j++) acc[i][j] += af[i] * bf[j];
        }
        #pragma unroll
        for (int i = 0; i < 4; i++)
            #pragma unroll
            for (int j = 0; j < 4; j++)
                dst[(size_t)(r0 + ty + 16*i) * 64 + tx + 16*j] =
                    fmaxf(acc[i][j] + bb[tx + 16*j], 0.f);
    }
}

// ---------------------------------------------------------------------------
// tcgen05 fused attention, v2: q1/q2 live in TMEM (TS-form MMA), S and PK
// share TMEM cols, smem down to 80KB -> 2 CTAs/SM.
// TMEM layout (256 cols): Q1H@0 Q1L@32 Q2H@64 Q2L@96 TQV@128 TSP@192
// ---------------------------------------------------------------------------
__global__ __launch_bounds__(128, 2)
void attn_tc(const float* __restrict__ q1g, const float* __restrict__ q2g,
             const float* __restrict__ krg, const float* __restrict__ vrg,
             const float* __restrict__ kg,  const int* __restrict__ mask,
             float* __restrict__ outg)
{
    const int t  = threadIdx.x;
    const int bh = blockIdx.y;
    const int q0 = blockIdx.x * 128;
    const int b  = bh >> 4, h = bh & 15;

#if HAS_TCGEN05
    extern __shared__ char dsm[];
    __shared__ uint32_t s_tmem;
    __shared__ __align__(8) uint64_t s_mb[2];

    const uint32_t base = (smem_u32(dsm) + 1023u) & ~1023u;
    const uint32_t krhS = base,         krlS = base + 8192;
    const uint32_t vrhS = base + 16384, vrlS = base + 24576;
    const uint32_t kthS = base + 32768, ktlS = base + 40960;
    const uint32_t phS  = base + 49152, plS  = base + 65536;

    const int wid = t >> 5;
    if (wid == 0) {
        asm volatile("tcgen05.alloc.cta_group::1.sync.aligned.shared::cta.b32 [%0], %1;"
                     :: "r"(smem_u32(&s_tmem)), "r"(256u) : "memory");
        asm volatile("tcgen05.relinquish_alloc_permit.cta_group::1.sync.aligned;");
    }
    if (t == 0) {
        asm volatile("mbarrier.init.shared.b64 [%0], 1;" :: "r"(smem_u32(&s_mb[0])) : "memory");
        asm volatile("mbarrier.init.shared.b64 [%0], 1;" :: "r"(smem_u32(&s_mb[1])) : "memory");
    }
    __syncthreads();
    const uint32_t tmem  = s_tmem;
    const uint32_t mb_sq = smem_u32(&s_mb[0]), mb_pk = smem_u32(&s_mb[1]);
    const uint32_t Q1H = tmem, Q1L = tmem + 32, Q2H = tmem + 64, Q2L = tmem + 96;
    const uint32_t TQV = tmem + 128, TSP = tmem + 192;
    const uint32_t warp_off = (uint32_t)(t >> 5) << 21;

    // load q1/q2 rows (row t) into TMEM as bf16x2 hi/lo
    {
        const float* p1 = q1g + ((size_t)bh * kS + q0 + t) * kDK;
        const float* p2 = q2g + ((size_t)bh * kS + q0 + t) * kDK;
        uint32_t hi[32], lo[32];
        #pragma unroll
        for (int c4 = 0; c4 < 16; c4++) {
            float4 v = ((const float4*)p1)[c4];
            __nv_bfloat16 h0=__float2bfloat16(v.x), h1=__float2bfloat16(v.y);
            __nv_bfloat16 h2=__float2bfloat16(v.z), h3=__float2bfloat16(v.w);
            hi[2*c4]   = pack_bf2(h0, h1);
            hi[2*c4+1] = pack_bf2(h2, h3);
            lo[2*c4]   = pack_bf2(__float2bfloat16(v.x-__bfloat162float(h0)),
                                  __float2bfloat16(v.y-__bfloat162float(h1)));
            lo[2*c4+1] = pack_bf2(__float2bfloat16(v.z-__bfloat162float(h2)),
                                  __float2bfloat16(v.w-__bfloat162float(h3)));
        }
        TSTM_X32(Q1H + warp_off, hi);
        TSTM_X32(Q1L + warp_off, lo);
        #pragma unroll
        for (int c4 = 0; c4 < 16; c4++) {
            float4 v = ((const float4*)p2)[c4];
            __nv_bfloat16 h0=__float2bfloat16(v.x), h1=__float2bfloat16(v.y);
            __nv_bfloat16 h2=__float2bfloat16(v.z), h3=__float2bfloat16(v.w);
            hi[2*c4]   = pack_bf2(h0, h1);
            hi[2*c4+1] = pack_bf2(h2, h3);
            lo[2*c4]   = pack_bf2(__float2bfloat16(v.x-__bfloat162float(h0)),
                                  __float2bfloat16(v.y-__bfloat162float(h1)));
            lo[2*c4+1] = pack_bf2(__float2bfloat16(v.z-__bfloat162float(h2)),
                                  __float2bfloat16(v.w-__bfloat162float(h3)));
        }
        TSTM_X32(Q2H + warp_off, hi);
        TSTM_X32(Q2L + warp_off, lo);
        asm volatile("tcgen05.wait::st.sync.aligned;" ::: "memory");
    }
    asm volatile("tcgen05.fence::before_thread_sync;" ::: "memory");
    __syncthreads();

    float out[64];
    #pragma unroll
    for (int c = 0; c < 64; c++) out[c] = 0.f;
    float m_i = -1e30f, l_i = 0.f;

    const int rr = t & 63, hf = t >> 6;

    for (int blk = 0; blk < 16; blk++) {
        const int k0 = blk * 64;

        // convert kr, vr (row rr, column half hf)
        const float* krp = krg + ((size_t)bh * kS + k0 + rr) * kDK + hf * 32;
        const float* vrp = vrg + ((size_t)bh * kS + k0 + rr) * kDK + hf * 32;
        #pragma unroll
        for (int i = 0; i < 8; i++) {
            uint32_t off = sw128((uint32_t)(rr * 128 + (hf * 8 + i) * 8));
            store_hilo(((const float4*)krp)[i], krhS + off, krlS + off);
            store_hilo(((const float4*)vrp)[i], vrhS + off, vrlS + off);
        }
        // k transposed: kT[d=rr][key pairs kp]
        #pragma unroll
        for (int i = 0; i < 16; i++) {
            int kp = hf * 16 + i;
            float a = kg[((size_t)bh * kS + k0 + 2 * kp)     * kDK + rr];
            float c = kg[((size_t)bh * kS + k0 + 2 * kp + 1) * kDK + rr];
            uint32_t off = sw128((uint32_t)(rr * 128 + kp * 4));
            store_hilo4(a, c, kthS + off, ktlS + off);
        }
        asm volatile("fence.proxy.async.shared::cta;" ::: "memory");
        __syncthreads();

        if (t == 0) {
            asm volatile("tcgen05.fence::after_thread_sync;" ::: "memory");
            const uint64_t bkh = mk_desc(krhS), bkl = mk_desc(krlS);
            const uint64_t bvh = mk_desc(vrhS), bvl = mk_desc(vrlS);
            #pragma unroll
            for (int ks = 0; ks < 4; ks++) {
                mma_ts(TSP, Q1H + ks*8, bkh + 2*ks, AT_IDESC, ks > 0);
                mma_ts(TSP, Q1H + ks*8, bkl + 2*ks, AT_IDESC, true);
                mma_ts(TSP, Q1L + ks*8, bkh + 2*ks, AT_IDESC, true);
                mma_ts(TQV, Q2H + ks*8, bvh + 2*ks, AT_IDESC, ks > 0);
                mma_ts(TQV, Q2H + ks*8, bvl + 2*ks, AT_IDESC, true);
                mma_ts(TQV, Q2L + ks*8, bvh + 2*ks, AT_IDESC, true);
            }
            asm volatile(
                "tcgen05.commit.cta_group::1.mbarrier::arrive::one.shared::cluster.b64 [%0];"
                :: "r"(mb_sq) : "memory");
        }
        mbar_wait(mb_sq, blk & 1);
        asm volatile("tcgen05.fence::after_thread_sync;" ::: "memory");

        // read S row (thread t owns TMEM row t)
        uint32_t sr[64];
        LDTM_X32(sr, TSP);
        LDTM_X32(sr + 32, TSP + 32);
        asm volatile("tcgen05.wait::ld.sync.aligned;" ::: "memory");

        // mask (reference: where mask==0 -> -1e9)
        const int4* mp = (const int4*)(mask + (size_t)b * kS * kS + (size_t)(q0 + t) * kS + k0);
        #pragma unroll
        for (int j4 = 0; j4 < 16; j4++) {
            int4 mv = mp[j4];
            if (mv.x == 0) sr[4*j4+0] = __float_as_uint(-1.0e9f);
            if (mv.y == 0) sr[4*j4+1] = __float_as_uint(-1.0e9f);
            if (mv.z == 0) sr[4*j4+2] = __float_as_uint(-1.0e9f);
            if (mv.w == 0) sr[4*j4+3] = __float_as_uint(-1.0e9f);
        }

        float rmax = -1e30f;
        #pragma unroll
        for (int j = 0; j < 64; j++) rmax = fmaxf(rmax, __uint_as_float(sr[j]));
        const float mnew = fmaxf(m_i, rmax);
        const float sc   = __expf(m_i - mnew);
        float rsum = 0.f;

        // p = exp(s - mnew); P~ = p * qv (stash back into sr)
        #pragma unroll
        for (int half = 0; half < 2; half++) {
            uint32_t qr[32];
            LDTM_X32(qr, TQV + 32 * half);
            asm volatile("tcgen05.wait::ld.sync.aligned;" ::: "memory");
            #pragma unroll
            for (int j = 0; j < 32; j++) {
                float p = __expf(__uint_as_float(sr[32*half + j]) - mnew);
                rsum += p;
                sr[32*half + j] = __float_as_uint(p * __uint_as_float(qr[j]));
            }
        }
        m_i = mnew;
        l_i = l_i * sc + rsum;

        // store P~ hi/lo (row t, key pairs)
        #pragma unroll
        for (int j = 0; j < 32; j++) {
            uint32_t off = sw128((uint32_t)(t * 128 + j * 4));
            store_hilo4(__uint_as_float(sr[2*j]), __uint_as_float(sr[2*j+1]),
                        phS + off, plS + off);
        }
        #pragma unroll
        for (int c = 0; c < 64; c++) out[c] *= sc;

        asm volatile("tcgen05.fence::before_thread_sync;" ::: "memory");
        asm volatile("fence.proxy.async.shared::cta;" ::: "memory");
        __syncthreads();

        if (t == 0) {
            asm volatile("tcgen05.fence::after_thread_sync;" ::: "memory");
            const uint64_t aph = mk_desc(phS), apl = mk_desc(plS);
            const uint64_t bth = mk_desc(kthS), btl = mk_desc(ktlS);
            #pragma unroll
            for (int ks = 0; ks < 4; ks++) {
                mma_ss(TSP, aph + 2*ks, bth + 2*ks, AT_IDESC, ks > 0);
                mma_ss(TSP, aph + 2*ks, btl + 2*ks, AT_IDESC, true);
                mma_ss(TSP, apl + 2*ks, bth + 2*ks, AT_IDESC, true);
            }
            asm volatile(
                "tcgen05.commit.cta_group::1.mbarrier::arrive::one.shared::cluster.b64 [%0];"
                :: "r"(mb_pk) : "memory");
        }
        mbar_wait(mb_pk, blk & 1);
        asm volatile("tcgen05.fence::after_thread_sync;" ::: "memory");

        #pragma unroll
        for (int half = 0; half < 2; half++) {
            uint32_t pr[32];
            LDTM_X32(pr, TSP + 32 * half);
            asm volatile("tcgen05.wait::ld.sync.aligned;" ::: "memory");
            #pragma unroll
            for (int j = 0; j < 32; j++)
                out[32*half + j] += __uint_as_float(pr[j]);
        }
        asm volatile("tcgen05.fence::before_thread_sync;" ::: "memory");
    }

    // normalize + write row (b, q0+t), head h
    const float inv = 1.0f / l_i;
    float4* op = (float4*)(outg + ((size_t)b * kS + q0 + t) * kDM + h * 64);
    #pragma unroll
    for (int c4 = 0; c4 < 16; c4++) {
        float4 v;
        v.x = out[4*c4+0] * inv; v.y = out[4*c4+1] * inv;
        v.z = out[4*c4+2] * inv; v.w = out[4*c4+3] * inv;
        op[c4] = v;
    }
    __syncthreads();
    if (wid == 0)
        asm volatile("tcgen05.dealloc.cta_group::1.sync.aligned.b32 %0, %1;"
                     :: "r"(tmem), "r"(256u));

#else  // ------- naive FFMA fallback (never runs on GB300) -------
    const float* p1 = q1g + ((size_t)bh * kS + q0 + t) * kDK;
    const float* p2 = q2g + ((size_t)bh * kS + q0 + t) * kDK;
    float q1r[64], q2r[64], out[64];
    for (int d = 0; d < 64; d++) { q1r[d] = p1[d]; q2r[d] = p2[d]; out[d] = 0.f; }
    float m_i = -1e30f, l_i = 0.f;
    for (int j = 0; j < kS; j++) {
        const float* krj = krg + ((size_t)bh * kS + j) * kDK;
        const float* vrj = vrg + ((size_t)bh * kS + j) * kDK;
        float s = 0.f, qv = 0.f;
        for (int d = 0; d < 64; d++) { s += q1r[d] * krj[d]; qv += q2r[d] * vrj[d]; }
        if (mask[(size_t)b * kS * kS + (size_t)(q0 + t) * kS + j] == 0) s = -1.0e9f;
        float mnew = fmaxf(m_i, s);
        float scv = __expf(m_i - mnew), p = __expf(s - mnew);
        const float* kj = kg + ((size_t)bh * kS + j) * kDK;
        for (int d = 0; d < 64; d++) out[d] = out[d] * scv + p * qv * kj[d];
        l_i = l_i * scv + p;
        m_i = mnew;
    }
    const float inv = 1.0f / l_i;
    for (int d = 0; d < 64; d++)
        outg[((size_t)b * kS + q0 + t) * kDM + h * 64 + d] = out[d] * inv;
#endif
}

// ---------------------------------------------------------------------------
extern "C" void kernel_launch(void* const* d_in, const int* in_sizes, int n_in,
                              void* d_out, int out_size)
{
    (void)in_sizes; (void)n_in; (void)out_size;
    const float* query = (const float*)d_in[0];
    const float* key_  = (const float*)d_in[1];
    const float* value = (const float*)d_in[2];
    const int*   mask  = (const int*)  d_in[3];
    const float* Wq  = (const float*)d_in[4];  const float* bq  = (const float*)d_in[5];
    const float* Wk  = (const float*)d_in[6];  const float* bk  = (const float*)d_in[7];
    const float* Wv  = (const float*)d_in[8];  const float* bv  = (const float*)d_in[9];
    const float* Wo  = (const float*)d_in[10]; const float* bo  = (const float*)d_in[11];
    const float* Wkl = (const float*)d_in[12]; const float* bkl = (const float*)d_in[13];
    const float* Wql = (const float*)d_in[14]; const float* bql = (const float*)d_in[15];
    const float* Wq2 = (const float*)d_in[16]; const float* bq2 = (const float*)d_in[17];
    const float* Wvl = (const float*)d_in[18]; const float* bvl = (const float*)d_in[19];
    const float* Wel = (const float*)d_in[20]; const float* bel = (const float*)d_in[21];

    float *qh, *kh, *vh, *kr, *q1, *q2, *vr, *att;
    cudaGetSymbolAddress((void**)&qh,  g_qh);
    cudaGetSymbolAddress((void**)&kh,  g_kh);
    cudaGetSymbolAddress((void**)&vh,  g_vh);
    cudaGetSymbolAddress((void**)&kr,  g_kr);
    cudaGetSymbolAddress((void**)&q1,  g_q1);
    cudaGetSymbolAddress((void**)&q2,  g_q2);
    cudaGetSymbolAddress((void**)&vr,  g_vr);
    cudaGetSymbolAddress((void**)&att, g_att);

    const int GEMM_SMEM = 66560;
    cudaFuncSetAttribute(tc_gemm, cudaFuncAttributeMaxDynamicSharedMemorySize, GEMM_SMEM);

    dim3 gg(8, 32);

    // Q/K/V projections -> head-split [BH, S, DK]
    tc_gemm<<<gg, 256, GEMM_SMEM>>>(query, Wq, bq, qh, 1);
    tc_gemm<<<gg, 256, GEMM_SMEM>>>(key_,  Wk, bk, kh, 1);
    tc_gemm<<<gg, 256, GEMM_SMEM>>>(value, Wv, bv, vh, 1);

    // fused small linears
    const int FQ_SMEM = (4096 + 64*65 + 3*4096) * 4;   // 82176
    const int FK_SMEM = (4096 + 2*4096) * 4;           // 49152
    cudaFuncSetAttribute(fused_q,  cudaFuncAttributeMaxDynamicSharedMemorySize, FQ_SMEM);
    cudaFuncSetAttribute(fused_kv, cudaFuncAttributeMaxDynamicSharedMemorySize, FK_SMEM);
    fused_kv<<<1024, 256, FK_SMEM>>>(kh, vh, Wkl, bkl, Wvl, bvl, kr, vr);
    fused_q <<<1024, 256, FQ_SMEM>>>(qh, Wql, bql, Wel, bel, Wq2, bq2, q1, q2);

    // tcgen05 fused attention (80KB smem + align slack -> 2 CTAs/SM)
    const int ATT_SMEM = 81920 + 1024;
    cudaFuncSetAttribute(attn_tc, cudaFuncAttributeMaxDynamicSharedMemorySize, ATT_SMEM);
    attn_tc<<<dim3(8, 64), 128, ATT_SMEM>>>(q1, q2, kr, vr, kh, mask, att);

    // output projection -> d_out
    tc_gemm<<<gg, 256, GEMM_SMEM>>>(att, Wo, bo, (float*)d_out, 0);
}

// round 9
// speedup vs baseline: 3.9377x; 1.0528x over previous
#include <cuda_runtime.h>
#include <cuda_bf16.h>
#include <cstdint>

static constexpr int kB  = 4;
static constexpr int kS  = 1024;
static constexpr int kDM = 1024;
static constexpr int kH  = 16;
static constexpr int kDK = 64;
static constexpr int kBH = kB * kH;   // 64

// ---------------- scratch (static device globals; no allocation) ----------------
__device__ float g_qh [kBH * kS * kDK];
__device__ float g_kh [kBH * kS * kDK];
__device__ float g_vh [kBH * kS * kDK];
__device__ float g_att[kB * kS * kDM];

// bf16 tile buffers (SW128 tile-image layout, [bh][blk16][4096])
__device__ __nv_bfloat16 g_krh[kBH * 16 * 4096];
__device__ __nv_bfloat16 g_krl[kBH * 16 * 4096];
__device__ __nv_bfloat16 g_vrh[kBH * 16 * 4096];
__device__ __nv_bfloat16 g_kth[kBH * 16 * 4096];
__device__ __nv_bfloat16 g_ktl[kBH * 16 * 4096];
// bf16 linear [bh][s][d]
__device__ __nv_bfloat16 g_q1h[kBH * kS * kDK];
__device__ __nv_bfloat16 g_q1l[kBH * kS * kDK];
__device__ __nv_bfloat16 g_q2h[kBH * kS * kDK];
__device__ __nv_bfloat16 g_q2l[kBH * kS * kDK];

// ---------------------------------------------------------------------------
// helpers
// ---------------------------------------------------------------------------
__device__ __forceinline__ uint32_t smem_u32(const void* p) {
    uint32_t a;
    asm("{ .reg .u64 t; cvta.to.shared.u64 t, %1; cvt.u32.u64 %0, t; }" : "=r"(a) : "l"(p));
    return a;
}
__device__ __forceinline__ uint32_t pack_bf2(__nv_bfloat16 a, __nv_bfloat16 b) {
    __nv_bfloat162 t = __halves2bfloat162(a, b);
    return *reinterpret_cast<uint32_t*>(&t);
}
__device__ __forceinline__ uint32_t sw128(uint32_t o) { return o ^ ((o >> 3) & 0x70); }

#if defined(__CUDA_ARCH_FEAT_SM103_ALL) || !defined(__CUDA_ARCH__)
#define HAS_TCGEN05 1
#else
#define HAS_TCGEN05 0
#endif

#if HAS_TCGEN05
__device__ __forceinline__ void mbar_wait(uint32_t mbar, uint32_t parity) {
    asm volatile(
        "{\n\t.reg .pred P;\n\t"
        "LW%=:\n\t"
        "mbarrier.try_wait.parity.acquire.cta.shared::cta.b64 P, [%0], %1;\n\t"
        "@!P bra LW%=;\n\t}"
        :: "r"(mbar), "r"(parity) : "memory");
}

static constexpr uint32_t GE_IDESC =           // M=128, N=128
    (1u << 4) | (1u << 7) | (1u << 10) | ((128u / 8) << 17) | ((128u / 16) << 24);
static constexpr uint32_t AT_IDESC =           // M=128, N=64
    (1u << 4) | (1u << 7) | (1u << 10) | ((64u / 8) << 17) | ((128u / 16) << 24);

static constexpr uint64_t DESC_SW128 =
    (2ull << 61) | (1ull << 46) | (64ull << 32) | (1ull << 16);

__device__ __forceinline__ uint64_t mk_desc(uint32_t addr) {
    return DESC_SW128 | (uint64_t)((addr >> 4) & 0x3FFF);
}

__device__ __forceinline__ void mma_ss(uint32_t d, uint64_t ad, uint64_t bd,
                                       uint32_t idesc, bool en) {
    uint32_t e = en ? 1u : 0u;
    asm volatile(
        "{\n\t.reg .pred p;\n\t"
        "setp.ne.u32 p, %5, 0;\n\t"
        "tcgen05.mma.cta_group::1.kind::f16 [%0], %1, %2, %3, {%4, %4, %4, %4}, p;\n\t}"
        :: "r"(d), "l"(ad), "l"(bd), "r"(idesc), "r"(0u), "r"(e) : "memory");
}
__device__ __forceinline__ void mma_ts(uint32_t d, uint32_t at, uint64_t bd,
                                       uint32_t idesc, bool en) {
    uint32_t e = en ? 1u : 0u;
    asm volatile(
        "{\n\t.reg .pred p;\n\t"
        "setp.ne.u32 p, %5, 0;\n\t"
        "tcgen05.mma.cta_group::1.kind::f16 [%0], [%1], %2, %3, {%4, %4, %4, %4}, p;\n\t}"
        :: "r"(d), "r"(at), "l"(bd), "r"(idesc), "r"(0u), "r"(e) : "memory");
}

__device__ __forceinline__ void bulk_cp(uint32_t smem_dst, const void* gsrc,
                                        uint32_t bytes, uint32_t mbar) {
    asm volatile(
        "cp.async.bulk.shared::cta.global.mbarrier::complete_tx::bytes [%0], [%1], %2, [%3];"
        :: "r"(smem_dst), "l"(gsrc), "r"(bytes), "r"(mbar) : "memory");
}
__device__ __forceinline__ void mbar_expect(uint32_t mbar, uint32_t bytes) {
    asm volatile("mbarrier.arrive.expect_tx.shared.b64 _, [%0], %1;"
                 :: "r"(mbar), "r"(bytes) : "memory");
}

#define LDTM_X32(r, addr) \
    asm volatile( \
        "tcgen05.ld.sync.aligned.32x32b.x32.b32 " \
        "{%0, %1, %2, %3, %4, %5, %6, %7, " \
        " %8, %9, %10, %11, %12, %13, %14, %15, " \
        " %16, %17, %18, %19, %20, %21, %22, %23, " \
        " %24, %25, %26, %27, %28, %29, %30, %31}, [%32];" \
        : "=r"((r)[0]),  "=r"((r)[1]),  "=r"((r)[2]),  "=r"((r)[3]), \
          "=r"((r)[4]),  "=r"((r)[5]),  "=r"((r)[6]),  "=r"((r)[7]), \
          "=r"((r)[8]),  "=r"((r)[9]),  "=r"((r)[10]), "=r"((r)[11]), \
          "=r"((r)[12]), "=r"((r)[13]), "=r"((r)[14]), "=r"((r)[15]), \
          "=r"((r)[16]), "=r"((r)[17]), "=r"((r)[18]), "=r"((r)[19]), \
          "=r"((r)[20]), "=r"((r)[21]), "=r"((r)[22]), "=r"((r)[23]), \
          "=r"((r)[24]), "=r"((r)[25]), "=r"((r)[26]), "=r"((r)[27]), \
          "=r"((r)[28]), "=r"((r)[29]), "=r"((r)[30]), "=r"((r)[31]) \
        : "r"(addr))

#define TSTM_X32(addr, r) \
    asm volatile( \
        "tcgen05.st.sync.aligned.32x32b.x32.b32 [%0], " \
        "{%1, %2, %3, %4, %5, %6, %7, %8, " \
        " %9, %10, %11, %12, %13, %14, %15, %16, " \
        " %17, %18, %19, %20, %21, %22, %23, %24, " \
        " %25, %26, %27, %28, %29, %30, %31, %32};" \
        :: "r"(addr), \
           "r"((r)[0]),  "r"((r)[1]),  "r"((r)[2]),  "r"((r)[3]), \
           "r"((r)[4]),  "r"((r)[5]),  "r"((r)[6]),  "r"((r)[7]), \
           "r"((r)[8]),  "r"((r)[9]),  "r"((r)[10]), "r"((r)[11]), \
           "r"((r)[12]), "r"((r)[13]), "r"((r)[14]), "r"((r)[15]), \
           "r"((r)[16]), "r"((r)[17]), "r"((r)[18]), "r"((r)[19]), \
           "r"((r)[20]), "r"((r)[21]), "r"((r)[22]), "r"((r)[23]), \
           "r"((r)[24]), "r"((r)[25]), "r"((r)[26]), "r"((r)[27]), \
           "r"((r)[28]), "r"((r)[29]), "r"((r)[30]), "r"((r)[31]) \
        : "memory")
#endif  // HAS_TCGEN05

// convert float4 -> bf16 hi + bf16 residual, store 8B to each smem tile
__device__ __forceinline__ void store_hilo(float4 v, uint32_t hoff, uint32_t loff) {
    __nv_bfloat16 h0 = __float2bfloat16(v.x), h1 = __float2bfloat16(v.y);
    __nv_bfloat16 h2 = __float2bfloat16(v.z), h3 = __float2bfloat16(v.w);
    float r0 = v.x - __bfloat162float(h0), r1 = v.y - __bfloat162float(h1);
    float r2 = v.z - __bfloat162float(h2), r3 = v.w - __bfloat162float(h3);
    uint32_t hp0 = pack_bf2(h0, h1), hp1 = pack_bf2(h2, h3);
    uint32_t lp0 = pack_bf2(__float2bfloat16(r0), __float2bfloat16(r1));
    uint32_t lp1 = pack_bf2(__float2bfloat16(r2), __float2bfloat16(r3));
    asm volatile("st.shared.v2.b32 [%0], {%1, %2};" :: "r"(hoff), "r"(hp0), "r"(hp1) : "memory");
    asm volatile("st.shared.v2.b32 [%0], {%1, %2};" :: "r"(loff), "r"(lp0), "r"(lp1) : "memory");
}

// pack 8 floats -> uint4 of bf16 hi; and uint4 of residual lo
__device__ __forceinline__ uint4 pack_hi8(const float* f) {
    uint4 u;
    u.x = pack_bf2(__float2bfloat16(f[0]), __float2bfloat16(f[1]));
    u.y = pack_bf2(__float2bfloat16(f[2]), __float2bfloat16(f[3]));
    u.z = pack_bf2(__float2bfloat16(f[4]), __float2bfloat16(f[5]));
    u.w = pack_bf2(__float2bfloat16(f[6]), __float2bfloat16(f[7]));
    return u;
}
__device__ __forceinline__ uint4 pack_lo8(const float* f) {
    float r[8];
    #pragma unroll
    for (int i = 0; i < 8; i++)
        r[i] = f[i] - __bfloat162float(__float2bfloat16(f[i]));
    return pack_hi8(r);
}

// ---------------------------------------------------------------------------
// tc_gemm: C = A*W^T + bias, tcgen05 hi/lo
// ---------------------------------------------------------------------------
__global__ __launch_bounds__(256)
void tc_gemm(const float* __restrict__ A, const float* __restrict__ W,
             const float* __restrict__ bias, float* __restrict__ out, int mode)
{
    extern __shared__ char dsm[];
    const int t   = threadIdx.x;
    const int m0  = blockIdx.y * 128;
    const int n0  = blockIdx.x * 128;

#if HAS_TCGEN05
    __shared__ uint32_t s_tmem;
    __shared__ __align__(8) uint64_t s_mbar;

    const uint32_t base = (smem_u32(dsm) + 1023u) & ~1023u;
    const uint32_t ah = base, al = base + 16384, bhs = base + 32768, bls = base + 49152;
    const int wid = t >> 5;

    if (wid == 0) {
        asm volatile("tcgen05.alloc.cta_group::1.sync.aligned.shared::cta.b32 [%0], %1;"
                     :: "r"(smem_u32(&s_tmem)), "r"(128u) : "memory");
        asm volatile("tcgen05.relinquish_alloc_permit.cta_group::1.sync.aligned;");
    }
    if (t == 0)
        asm volatile("mbarrier.init.shared.b64 [%0], 1;" :: "r"(smem_u32(&s_mbar)) : "memory");
    __syncthreads();
    const uint32_t tmem = s_tmem;
    const uint32_t mbar = smem_u32(&s_mbar);

    const int ty = t >> 4, c4 = t & 15;
    const float* Ap = A + (size_t)(m0 + ty) * 1024 + c4 * 4;
    const float* Wp = W + (size_t)(n0 + ty) * 1024 + c4 * 4;

    int chunk = 0;
    for (int k0 = 0; k0 < 1024; k0 += 64, ++chunk) {
        float4 av[8], wv[8];
        #pragma unroll
        for (int i = 0; i < 8; i++) {
            av[i] = *(const float4*)(Ap + (size_t)(16 * i) * 1024 + k0);
            wv[i] = *(const float4*)(Wp + (size_t)(16 * i) * 1024 + k0);
        }
        if (chunk > 0) mbar_wait(mbar, (chunk - 1) & 1);
        #pragma unroll
        for (int i = 0; i < 8; i++) {
            uint32_t off = sw128((uint32_t)((ty + 16 * i) * 128 + c4 * 8));
            store_hilo(av[i], ah + off, al + off);
            store_hilo(wv[i], bhs + off, bls + off);
        }
        asm volatile("fence.proxy.async.shared::cta;" ::: "memory");
        __syncthreads();
        if (t == 0) {
            const uint64_t dah = mk_desc(ah),  dal = mk_desc(al);
            const uint64_t dbh = mk_desc(bhs), dbl = mk_desc(bls);
            #pragma unroll
            for (int ks = 0; ks < 4; ks++) {
                mma_ss(tmem, dah + 2 * ks, dbh + 2 * ks, GE_IDESC, !(chunk == 0 && ks == 0));
                mma_ss(tmem, dah + 2 * ks, dbl + 2 * ks, GE_IDESC, true);
                mma_ss(tmem, dal + 2 * ks, dbh + 2 * ks, GE_IDESC, true);
            }
            asm volatile(
                "tcgen05.commit.cta_group::1.mbarrier::arrive::one.shared::cluster.b64 [%0];"
                :: "r"(mbar) : "memory");
        }
    }
    mbar_wait(mbar, (16 - 1) & 1);
    __syncthreads();
    asm volatile("tcgen05.fence::after_thread_sync;" ::: "memory");

    if (wid < 4) {
        const int lane = t & 31;
        const int gr = m0 + wid * 32 + lane;
        for (int cb = 0; cb < 128; cb += 32) {
            uint32_t regs[32];
            LDTM_X32(regs, tmem + cb);
            asm volatile("tcgen05.wait::ld.sync.aligned;" ::: "memory");
            if (mode == 0) {
                float* op = out + (size_t)gr * 1024 + n0 + cb;
                #pragma unroll
                for (int c = 0; c < 32; c++)
                    op[c] = __uint_as_float(regs[c]) + bias[n0 + cb + c];
            } else {
                const int b = gr >> 10, s = gr & 1023;
                #pragma unroll
                for (int c = 0; c < 32; c++) {
                    const int gc = n0 + cb + c;
                    const int h = gc >> 6, d = gc & 63;
                    out[(((size_t)(b * kH + h)) * kS + s) * kDK + d] =
                        __uint_as_float(regs[c]) + bias[gc];
                }
            }
        }
    }
    __syncthreads();
    if (wid == 0)
        asm volatile("tcgen05.dealloc.cta_group::1.sync.aligned.b32 %0, %1;"
                     :: "r"(tmem), "r"(128u));
#else
    float* As = (float*)dsm;
    float* Bs = As + 16 * 128;
    const int tx = t & 15, ty = t >> 4;
    const int lm = t & 127;
    const int kb = (t >> 7) * 8;
    float acc[8][8];
    #pragma unroll
    for (int i = 0; i < 8; i++)
        #pragma unroll
        for (int j = 0; j < 8; j++) acc[i][j] = 0.f;
    for (int k0 = 0; k0 < 1024; k0 += 16) {
        const float4* Ag = (const float4*)(A + (size_t)(m0 + lm) * 1024 + k0 + kb);
        const float4* Wg = (const float4*)(W + (size_t)(n0 + lm) * 1024 + k0 + kb);
        float4 a0 = Ag[0], a1 = Ag[1];
        float4 b0 = Wg[0], b1 = Wg[1];
        As[(kb+0)*128+lm]=a0.x; As[(kb+1)*128+lm]=a0.y; As[(kb+2)*128+lm]=a0.z; As[(kb+3)*128+lm]=a0.w;
        As[(kb+4)*128+lm]=a1.x; As[(kb+5)*128+lm]=a1.y; As[(kb+6)*128+lm]=a1.z; As[(kb+7)*128+lm]=a1.w;
        Bs[(kb+0)*128+lm]=b0.x; Bs[(kb+1)*128+lm]=b0.y; Bs[(kb+2)*128+lm]=b0.z; Bs[(kb+3)*128+lm]=b0.w;
        Bs[(kb+4)*128+lm]=b1.x; Bs[(kb+5)*128+lm]=b1.y; Bs[(kb+6)*128+lm]=b1.z; Bs[(kb+7)*128+lm]=b1.w;
        __syncthreads();
        #pragma unroll
        for (int kk = 0; kk < 16; kk++) {
            float af[8], bf[8];
            #pragma unroll
            for (int i = 0; i < 8; i++) af[i] = As[kk*128 + ty + 16*i];
            #pragma unroll
            for (int j = 0; j < 8; j++) bf[j] = Bs[kk*128 + tx + 16*j];
            #pragma unroll
            for (int i = 0; i < 8; i++)
                #pragma unroll
                for (int j = 0; j < 8; j++) acc[i][j] += af[i] * bf[j];
        }
        __syncthreads();
    }
    #pragma unroll
    for (int i = 0; i < 8; i++) {
        const int r = m0 + ty + 16*i;
        #pragma unroll
        for (int j = 0; j < 8; j++) {
            const int c = n0 + tx + 16*j;
            float v = acc[i][j] + bias[c];
            if (mode == 0) out[(size_t)r * 1024 + c] = v;
            else {
                int b = r >> 10, s = r & 1023, h = c >> 6, d = c & 63;
                out[(((size_t)(b * kH + h)) * kS + s) * kDK + d] = v;
            }
        }
    }
#endif
}

// ---------------------------------------------------------------------------
// conv_kv: kr tiles (hi/lo), vr tiles (hi), kT tiles (hi/lo)
// ---------------------------------------------------------------------------
__global__ __launch_bounds__(256)
void conv_kv(const float* __restrict__ Kh, const float* __restrict__ Vh,
             const float* __restrict__ Wkl, const float* __restrict__ bkl,
             const float* __restrict__ Wvl, const float* __restrict__ bvl,
             __nv_bfloat16* __restrict__ krh, __nv_bfloat16* __restrict__ krl,
             __nv_bfloat16* __restrict__ vrh,
             __nv_bfloat16* __restrict__ kth, __nv_bfloat16* __restrict__ ktl)
{
    extern __shared__ float fs[];
    float* W1 = fs;
    float* W2 = W1 + 4096;
    float* Xs = W2 + 4096;
    float* St = Xs + 4096;

    const int t  = threadIdx.x;
    const int tx = t & 15, ty = t >> 4;
    const int r0 = blockIdx.x * 64;
    const int lr = t & 63;
    const int kb = (t >> 6) * 16;
    const int bh = r0 >> 10, blkid = (r0 >> 6) & 15;
    const size_t tbase = ((size_t)bh * 16 + blkid) * 4096;
    const int wr = t >> 2, wq = t & 3;

    #pragma unroll
    for (int q = 0; q < 4; q++) {
        float4 w1 = *(const float4*)(Wkl + (size_t)lr * 64 + kb + 4*q);
        float4 w2 = *(const float4*)(Wvl + (size_t)lr * 64 + kb + 4*q);
        W1[(kb+4*q+0)*64+lr]=w1.x; W1[(kb+4*q+1)*64+lr]=w1.y; W1[(kb+4*q+2)*64+lr]=w1.z; W1[(kb+4*q+3)*64+lr]=w1.w;
        W2[(kb+4*q+0)*64+lr]=w2.x; W2[(kb+4*q+1)*64+lr]=w2.y; W2[(kb+4*q+2)*64+lr]=w2.z; W2[(kb+4*q+3)*64+lr]=w2.w;
    }

    // ---- pass 0: Kh -> kT tiles + kr tiles ----
    #pragma unroll
    for (int q = 0; q < 4; q++) {
        float4 x = *(const float4*)(Kh + (size_t)(r0 + lr) * 64 + kb + 4*q);
        Xs[(kb+4*q+0)*64+lr]=x.x; Xs[(kb+4*q+1)*64+lr]=x.y;
        Xs[(kb+4*q+2)*64+lr]=x.z; Xs[(kb+4*q+3)*64+lr]=x.w;
    }
    __syncthreads();

    {
        const int d = t & 63, seg = t >> 6;
        float f[16];
        #pragma unroll
        for (int i = 0; i < 16; i++) f[i] = Xs[d * 64 + seg * 16 + i];
        uint32_t o0 = (uint32_t)(d * 128 + seg * 32);
        uint32_t s0 = sw128(o0), s1 = sw128(o0 + 16);
        char* th = (char*)(kth + tbase);
        char* tl = (char*)(ktl + tbase);
        *(uint4*)(th + s0) = pack_hi8(f);     *(uint4*)(th + s1) = pack_hi8(f + 8);
        *(uint4*)(tl + s0) = pack_lo8(f);     *(uint4*)(tl + s1) = pack_lo8(f + 8);
    }

    {
        float acc[4][4];
        #pragma unroll
        for (int i = 0; i < 4; i++)
            #pragma unroll
            for (int j = 0; j < 4; j++) acc[i][j] = 0.f;
        #pragma unroll 16
        for (int kk = 0; kk < 64; kk++) {
            float af[4], bf[4];
            #pragma unroll
            for (int i = 0; i < 4; i++) af[i] = Xs[kk*64 + ty + 16*i];
            #pragma unroll
            for (int j = 0; j < 4; j++) bf[j] = W1[kk*64 + tx + 16*j];
            #pragma unroll
            for (int i = 0; i < 4; i++)
                #pragma unroll
                for (int j = 0; j < 4; j++) acc[i][j] += af[i] * bf[j];
        }
        #pragma unroll
        for (int i = 0; i < 4; i++)
            #pragma unroll
            for (int j = 0; j < 4; j++)
                St[(ty + 16*i) * 64 + tx + 16*j] = fmaxf(acc[i][j] + bkl[tx + 16*j], 0.f);
    }
    __syncthreads();
    {
        float f[16];
        #pragma unroll
        for (int i = 0; i < 16; i++) f[i] = St[wr * 64 + wq * 16 + i];
        uint32_t o0 = (uint32_t)(wr * 128 + wq * 32);
        uint32_t s0 = sw128(o0), s1 = sw128(o0 + 16);
        char* th = (char*)(krh + tbase);
        char* tl = (char*)(krl + tbase);
        *(uint4*)(th + s0) = pack_hi8(f);     *(uint4*)(th + s1) = pack_hi8(f + 8);
        *(uint4*)(tl + s0) = pack_lo8(f);     *(uint4*)(tl + s1) = pack_lo8(f + 8);
    }
    __syncthreads();

    // ---- pass 1: Vh -> vrh tiles ----
    #pragma unroll
    for (int q = 0; q < 4; q++) {
        float4 x = *(const float4*)(Vh + (size_t)(r0 + lr) * 64 + kb + 4*q);
        Xs[(kb+4*q+0)*64+lr]=x.x; Xs[(kb+4*q+1)*64+lr]=x.y;
        Xs[(kb+4*q+2)*64+lr]=x.z; Xs[(kb+4*q+3)*64+lr]=x.w;
    }
    __syncthreads();
    {
        float acc[4][4];
        #pragma unroll
        for (int i = 0; i < 4; i++)
            #pragma unroll
            for (int j = 0; j < 4; j++) acc[i][j] = 0.f;
        #pragma unroll 16
        for (int kk = 0; kk < 64; kk++) {
            float af[4], bf[4];
            #pragma unroll
            for (int i = 0; i < 4; i++) af[i] = Xs[kk*64 + ty + 16*i];
            #pragma unroll
            for (int j = 0; j < 4; j++) bf[j] = W2[kk*64 + tx + 16*j];
            #pragma unroll
            for (int i = 0; i < 4; i++)
                #pragma unroll
                for (int j = 0; j < 4; j++) acc[i][j] += af[i] * bf[j];
        }
        #pragma unroll
        for (int i = 0; i < 4; i++)
            #pragma unroll
            for (int j = 0; j < 4; j++)
                St[(ty + 16*i) * 64 + tx + 16*j] = fmaxf(acc[i][j] + bvl[tx + 16*j], 0.f);
    }
    __syncthreads();
    {
        float f[16];
        #pragma unroll
        for (int i = 0; i < 16; i++) f[i] = St[wr * 64 + wq * 16 + i];
        uint32_t o0 = (uint32_t)(wr * 128 + wq * 32);
        uint32_t s0 = sw128(o0), s1 = sw128(o0 + 16);
        char* th = (char*)(vrh + tbase);
        *(uint4*)(th + s0) = pack_hi8(f);     *(uint4*)(th + s1) = pack_hi8(f + 8);
    }
}

// ---------------------------------------------------------------------------
// fused_q: q1 -> q1h/q1l, q2 -> q2h/q2l (linear bf16)
// ---------------------------------------------------------------------------
__global__ __launch_bounds__(256)
void fused_q(const float* __restrict__ X,
             const float* __restrict__ Wql, const float* __restrict__ bql,
             const float* __restrict__ Wel, const float* __restrict__ bel,
             const float* __restrict__ Wq2, const float* __restrict__ bq2,
             __nv_bfloat16* __restrict__ q1h, __nv_bfloat16* __restrict__ q1l,
             __nv_bfloat16* __restrict__ q2h, __nv_bfloat16* __restrict__ q2l)
{
    extern __shared__ float fs[];
    float* Xs = fs;
    float* Ys = Xs + 4096;
    float* W1 = Ys + 64 * 65;
    float* W2 = W1 + 4096;
    float* W3 = W2 + 4096;
    float* St = W3 + 4096;

    const int t  = threadIdx.x;
    const int tx = t & 15, ty = t >> 4;
    const int r0 = blockIdx.x * 64;
    const int lr = t & 63;
    const int kb = (t >> 6) * 16;
    const int wr = t >> 2, wq = t & 3;

    #pragma unroll
    for (int q = 0; q < 4; q++) {
        float4 w1 = *(const float4*)(Wql + (size_t)lr * 64 + kb + 4*q);
        float4 w2 = *(const float4*)(Wel + (size_t)lr * 64 + kb + 4*q);
        float4 w3 = *(const float4*)(Wq2 + (size_t)lr * 64 + kb + 4*q);
        W1[(kb+4*q+0)*64+lr]=w1.x; W1[(kb+4*q+1)*64+lr]=w1.y; W1[(kb+4*q+2)*64+lr]=w1.z; W1[(kb+4*q+3)*64+lr]=w1.w;
        W2[(kb+4*q+0)*64+lr]=w2.x; W2[(kb+4*q+1)*64+lr]=w2.y; W2[(kb+4*q+2)*64+lr]=w2.z; W2[(kb+4*q+3)*64+lr]=w2.w;
        W3[(kb+4*q+0)*64+lr]=w3.x; W3[(kb+4*q+1)*64+lr]=w3.y; W3[(kb+4*q+2)*64+lr]=w3.z; W3[(kb+4*q+3)*64+lr]=w3.w;
        float4 x = *(const float4*)(X + (size_t)(r0 + lr) * 64 + kb + 4*q);
        Xs[(kb+4*q+0)*64+lr]=x.x; Xs[(kb+4*q+1)*64+lr]=x.y; Xs[(kb+4*q+2)*64+lr]=x.z; Xs[(kb+4*q+3)*64+lr]=x.w;
    }
    __syncthreads();

    // stage 1: q1a -> Ys
    {
        float acc[4][4];
        #pragma unroll
        for (int i = 0; i < 4; i++)
            #pragma unroll
            for (int j = 0; j < 4; j++) acc[i][j] = 0.f;
        #pragma unroll 16
        for (int kk = 0; kk < 64; kk++) {
            float af[4], bf[4];
            #pragma unroll
            for (int i = 0; i < 4; i++) af[i] = Xs[kk*64 + ty + 16*i];
            #pragma unroll
            for (int j = 0; j < 4; j++) bf[j] = W1[kk*64 + tx + 16*j];
            #pragma unroll
            for (int i = 0; i < 4; i++)
                #pragma unroll
                for (int j = 0; j < 4; j++) acc[i][j] += af[i] * bf[j];
        }
        #pragma unroll
        for (int i = 0; i < 4; i++)
            #pragma unroll
            for (int j = 0; j < 4; j++)
                Ys[(tx + 16*j) * 65 + ty + 16*i] = fmaxf(acc[i][j] + bql[tx + 16*j], 0.f);
    }

    // q2 -> St -> q2h/q2l
    {
        float acc[4][4];
        #pragma unroll
        for (int i = 0; i < 4; i++)
            #pragma unroll
            for (int j = 0; j < 4; j++) acc[i][j] = 0.f;
        #pragma unroll 16
        for (int kk = 0; kk < 64; kk++) {
            float af[4], bf[4];
            #pragma unroll
            for (int i = 0; i < 4; i++) af[i] = Xs[kk*64 + ty + 16*i];
            #pragma unroll
            for (int j = 0; j < 4; j++) bf[j] = W3[kk*64 + tx + 16*j];
            #pragma unroll
            for (int i = 0; i < 4; i++)
                #pragma unroll
                for (int j = 0; j < 4; j++) acc[i][j] += af[i] * bf[j];
        }
        __syncthreads();
        #pragma unroll
        for (int i = 0; i < 4; i++)
            #pragma unroll
            for (int j = 0; j < 4; j++)
                St[(ty + 16*i) * 64 + tx + 16*j] = fmaxf(acc[i][j] + bq2[tx + 16*j], 0.f);
    }
    __syncthreads();
    {
        float f[16];
        #pragma unroll
        for (int i = 0; i < 16; i++) f[i] = St[wr * 64 + wq * 16 + i];
        uint4* dh = (uint4*)(q2h + (size_t)(r0 + wr) * 64 + wq * 16);
        uint4* dl = (uint4*)(q2l + (size_t)(r0 + wr) * 64 + wq * 16);
        dh[0] = pack_hi8(f); dh[1] = pack_hi8(f + 8);
        dl[0] = pack_lo8(f); dl[1] = pack_lo8(f + 8);
    }
    __syncthreads();

    // q1 from Ys -> St -> q1h/q1l
    {
        float acc[4][4];
        #pragma unroll
        for (int i = 0; i < 4; i++)
            #pragma unroll
            for (int j = 0; j < 4; j++) acc[i][j] = 0.f;
        #pragma unroll 16
        for (int kk = 0; kk < 64; kk++) {
            float af[4], bf[4];
            #pragma unroll
            for (int i = 0; i < 4; i++) af[i] = Ys[kk*65 + ty + 16*i];
            #pragma unroll
            for (int j = 0; j < 4; j++) bf[j] = W2[kk*64 + tx + 16*j];
            #pragma unroll
            for (int i = 0; i < 4; i++)
                #pragma unroll
                for (int j = 0; j < 4; j++) acc[i][j] += af[i] * bf[j];
        }
        #pragma unroll
        for (int i = 0; i < 4; i++)
            #pragma unroll
            for (int j = 0; j < 4; j++)
                St[(ty + 16*i) * 64 + tx + 16*j] = fmaxf(acc[i][j] + bel[tx + 16*j], 0.f);
    }
    __syncthreads();
    {
        float f[16];
        #pragma unroll
        for (int i = 0; i < 16; i++) f[i] = St[wr * 64 + wq * 16 + i];
        uint4* dh = (uint4*)(q1h + (size_t)(r0 + wr) * 64 + wq * 16);
        uint4* dl = (uint4*)(q1l + (size_t)(r0 + wr) * 64 + wq * 16);
        dh[0] = pack_hi8(f); dh[1] = pack_hi8(f + 8);
        dl[0] = pack_lo8(f); dl[1] = pack_lo8(f + 8);
    }
}

// ---------------------------------------------------------------------------
// attn v4: pipelined tcgen05 attention, restored precision.
// TMEM (256): Q1H@0 Q1L@32 Q2H@64 Q2L@96 | TQV@128 | TS/TPK@192
// smem: 2 stages x {krh,krl,vrh,kth,ktl} (40KB) + Ph 16KB + Pl 16KB = 112KB
// ---------------------------------------------------------------------------
__global__ __launch_bounds__(128, 2)
void attn_tc(const __nv_bfloat16* __restrict__ q1h, const __nv_bfloat16* __restrict__ q1l,
             const __nv_bfloat16* __restrict__ q2h, const __nv_bfloat16* __restrict__ q2l,
             const __nv_bfloat16* __restrict__ krh, const __nv_bfloat16* __restrict__ krl,
             const __nv_bfloat16* __restrict__ vrh,
             const __nv_bfloat16* __restrict__ kth, const __nv_bfloat16* __restrict__ ktl,
             const int* __restrict__ mask, float* __restrict__ outg)
{
    const int t  = threadIdx.x;
    const int bh = blockIdx.y;
    const int q0 = blockIdx.x * 128;
    const int b  = bh >> 4, h = bh & 15;

#if HAS_TCGEN05
    extern __shared__ char dsm[];
    __shared__ uint32_t s_tmem;
    __shared__ __align__(8) uint64_t s_mb[4];   // 0:sq 1:pk 2:ld0 3:ld1

    const uint32_t base = (smem_u32(dsm) + 1023u) & ~1023u;
    const uint32_t stg[2] = { base, base + 40960 };
    const uint32_t Ps = base + 81920;
    const uint32_t Pl = base + 98304;

    const int wid = t >> 5;
    if (wid == 0) {
        asm volatile("tcgen05.alloc.cta_group::1.sync.aligned.shared::cta.b32 [%0], %1;"
                     :: "r"(smem_u32(&s_tmem)), "r"(256u) : "memory");
        asm volatile("tcgen05.relinquish_alloc_permit.cta_group::1.sync.aligned;");
    }
    if (t == 0) {
        #pragma unroll
        for (int i = 0; i < 4; i++)
            asm volatile("mbarrier.init.shared.b64 [%0], 1;"
                         :: "r"(smem_u32(&s_mb[i])) : "memory");
    }
    __syncthreads();
    const uint32_t tmem = s_tmem;
    const uint32_t mb_sq = smem_u32(&s_mb[0]), mb_pk = smem_u32(&s_mb[1]);
    const uint32_t mb_ld[2] = { smem_u32(&s_mb[2]), smem_u32(&s_mb[3]) };
    const uint32_t Q1H = tmem, Q1L = tmem + 32, Q2H = tmem + 64, Q2L = tmem + 96;
    const uint32_t TQV = tmem + 128, TS = tmem + 192;
    const uint32_t warp_off = (uint32_t)(t >> 5) << 21;

    const size_t tb = (size_t)bh * 16;

    // kick off bulk loads for blk 0 and 1
    if (t == 0) {
        asm volatile("fence.proxy.async.shared::cta;" ::: "memory");
        #pragma unroll
        for (int s = 0; s < 2; s++) {
            mbar_expect(mb_ld[s], 40960);
            const size_t off = (tb + s) * 4096;
            bulk_cp(stg[s] + 0,     (const char*)(krh + off), 8192, mb_ld[s]);
            bulk_cp(stg[s] + 8192,  (const char*)(krl + off), 8192, mb_ld[s]);
            bulk_cp(stg[s] + 16384, (const char*)(vrh + off), 8192, mb_ld[s]);
            bulk_cp(stg[s] + 24576, (const char*)(kth + off), 8192, mb_ld[s]);
            bulk_cp(stg[s] + 32768, (const char*)(ktl + off), 8192, mb_ld[s]);
        }
    }

    // upload q rows (row t) to TMEM: q1h/q1l/q2h/q2l
    {
        uint32_t r[32];
        const uint4* p = (const uint4*)(q1h + ((size_t)bh * kS + q0 + t) * kDK);
        #pragma unroll
        for (int i = 0; i < 8; i++) { uint4 v = p[i];
            r[4*i]=v.x; r[4*i+1]=v.y; r[4*i+2]=v.z; r[4*i+3]=v.w; }
        TSTM_X32(Q1H + warp_off, r);
        p = (const uint4*)(q1l + ((size_t)bh * kS + q0 + t) * kDK);
        #pragma unroll
        for (int i = 0; i < 8; i++) { uint4 v = p[i];
            r[4*i]=v.x; r[4*i+1]=v.y; r[4*i+2]=v.z; r[4*i+3]=v.w; }
        TSTM_X32(Q1L + warp_off, r);
        p = (const uint4*)(q2h + ((size_t)bh * kS + q0 + t) * kDK);
        #pragma unroll
        for (int i = 0; i < 8; i++) { uint4 v = p[i];
            r[4*i]=v.x; r[4*i+1]=v.y; r[4*i+2]=v.z; r[4*i+3]=v.w; }
        TSTM_X32(Q2H + warp_off, r);
        p = (const uint4*)(q2l + ((size_t)bh * kS + q0 + t) * kDK);
        #pragma unroll
        for (int i = 0; i < 8; i++) { uint4 v = p[i];
            r[4*i]=v.x; r[4*i+1]=v.y; r[4*i+2]=v.z; r[4*i+3]=v.w; }
        TSTM_X32(Q2L + warp_off, r);
        asm volatile("tcgen05.wait::st.sync.aligned;" ::: "memory");
    }
    asm volatile("tcgen05.fence::before_thread_sync;" ::: "memory");
    __syncthreads();

    // issue S/QV for blk 0
    if (t == 0) {
        asm volatile("tcgen05.fence::after_thread_sync;" ::: "memory");
        mbar_wait(mb_ld[0], 0);
        const uint64_t dkh = mk_desc(stg[0]), dkl = mk_desc(stg[0] + 8192);
        const uint64_t dvh = mk_desc(stg[0] + 16384);
        #pragma unroll
        for (int ks = 0; ks < 4; ks++) {
            mma_ts(TS,  Q1H + ks*8, dkh + 2*ks, AT_IDESC, ks > 0);
            mma_ts(TS,  Q1H + ks*8, dkl + 2*ks, AT_IDESC, true);
            mma_ts(TS,  Q1L + ks*8, dkh + 2*ks, AT_IDESC, true);
            mma_ts(TQV, Q2H + ks*8, dvh + 2*ks, AT_IDESC, ks > 0);
            mma_ts(TQV, Q2L + ks*8, dvh + 2*ks, AT_IDESC, true);
        }
        asm volatile(
            "tcgen05.commit.cta_group::1.mbarrier::arrive::one.shared::cluster.b64 [%0];"
            :: "r"(mb_sq) : "memory");
    }

    float out[64];
    #pragma unroll
    for (int c = 0; c < 64; c++) out[c] = 0.f;
    float m_i = -1e30f, l_i = 0.f;

    for (int blk = 0; blk < 16; blk++) {
        const int st = blk & 1;
        const int k0 = blk * 64;

        mbar_wait(mb_sq, blk & 1);
        asm volatile("tcgen05.fence::after_thread_sync;" ::: "memory");

        uint32_t sr[64];
        LDTM_X32(sr, TS);
        LDTM_X32(sr + 32, TS + 32);
        asm volatile("tcgen05.wait::ld.sync.aligned;" ::: "memory");

        // mask
        const int4* mp = (const int4*)(mask + (size_t)b * kS * kS + (size_t)(q0 + t) * kS + k0);
        #pragma unroll
        for (int j4 = 0; j4 < 16; j4++) {
            int4 mv = mp[j4];
            if (mv.x == 0) sr[4*j4+0] = __float_as_uint(-1.0e9f);
            if (mv.y == 0) sr[4*j4+1] = __float_as_uint(-1.0e9f);
            if (mv.z == 0) sr[4*j4+2] = __float_as_uint(-1.0e9f);
            if (mv.w == 0) sr[4*j4+3] = __float_as_uint(-1.0e9f);
        }

        float rmax = -1e30f;
        #pragma unroll
        for (int j = 0; j < 64; j++) rmax = fmaxf(rmax, __uint_as_float(sr[j]));
        const float mnew = fmaxf(m_i, rmax);
        const float sc   = __expf(m_i - mnew);
        float rsum = 0.f;

        #pragma unroll
        for (int half = 0; half < 2; half++) {
            uint32_t qr[32];
            LDTM_X32(qr, TQV + 32 * half);
            asm volatile("tcgen05.wait::ld.sync.aligned;" ::: "memory");
            #pragma unroll
            for (int j = 0; j < 32; j++) {
                float p = __expf(__uint_as_float(sr[32*half + j]) - mnew);
                rsum += p;
                sr[32*half + j] = __float_as_uint(p * __uint_as_float(qr[j]));
            }
        }
        m_i = mnew;
        l_i = l_i * sc + rsum;

        // P hi/lo -> smem, 16B chunks per tile
        #pragma unroll
        for (int c = 0; c < 8; c++) {
            float f[8];
            #pragma unroll
            for (int j = 0; j < 8; j++) f[j] = __uint_as_float(sr[8*c + j]);
            uint4 uh = pack_hi8(f);
            uint4 ul = pack_lo8(f);
            uint32_t off = sw128((uint32_t)(t * 128 + c * 16));
            asm volatile("st.shared.v4.b32 [%0], {%1,%2,%3,%4};"
                         :: "r"(Ps + off), "r"(uh.x), "r"(uh.y), "r"(uh.z), "r"(uh.w) : "memory");
            asm volatile("st.shared.v4.b32 [%0], {%1,%2,%3,%4};"
                         :: "r"(Pl + off), "r"(ul.x), "r"(ul.y), "r"(ul.z), "r"(ul.w) : "memory");
        }
        #pragma unroll
        for (int c = 0; c < 64; c++) out[c] *= sc;

        asm volatile("tcgen05.fence::before_thread_sync;" ::: "memory");
        asm volatile("fence.proxy.async.shared::cta;" ::: "memory");
        __syncthreads();

        if (t == 0) {
            asm volatile("tcgen05.fence::after_thread_sync;" ::: "memory");
            const uint64_t dPh = mk_desc(Ps), dPl = mk_desc(Pl);
            const uint64_t dth = mk_desc(stg[st] + 24576), dtl = mk_desc(stg[st] + 32768);
            #pragma unroll
            for (int ks = 0; ks < 4; ks++) {
                mma_ss(TS, dPh + 2*ks, dth + 2*ks, AT_IDESC, ks > 0);
                mma_ss(TS, dPh + 2*ks, dtl + 2*ks, AT_IDESC, true);
                mma_ss(TS, dPl + 2*ks, dth + 2*ks, AT_IDESC, true);
            }
            asm volatile(
                "tcgen05.commit.cta_group::1.mbarrier::arrive::one.shared::cluster.b64 [%0];"
                :: "r"(mb_pk) : "memory");
        }
        mbar_wait(mb_pk, blk & 1);
        asm volatile("tcgen05.fence::after_thread_sync;" ::: "memory");

        uint32_t pr[64];
        LDTM_X32(pr, TS);
        LDTM_X32(pr + 32, TS + 32);
        asm volatile("tcgen05.wait::ld.sync.aligned;" ::: "memory");
        asm volatile("tcgen05.fence::before_thread_sync;" ::: "memory");
        __syncthreads();

        if (t == 0) {
            // refill this stage for blk+2
            if (blk + 2 < 16) {
                mbar_expect(mb_ld[st], 40960);
                const size_t off = (tb + blk + 2) * 4096;
                bulk_cp(stg[st] + 0,     (const char*)(krh + off), 8192, mb_ld[st]);
                bulk_cp(stg[st] + 8192,  (const char*)(krl + off), 8192, mb_ld[st]);
                bulk_cp(stg[st] + 16384, (const char*)(vrh + off), 8192, mb_ld[st]);
                bulk_cp(stg[st] + 24576, (const char*)(kth + off), 8192, mb_ld[st]);
                bulk_cp(stg[st] + 32768, (const char*)(ktl + off), 8192, mb_ld[st]);
            }
            // issue S/QV for blk+1
            if (blk + 1 < 16) {
                asm volatile("tcgen05.fence::after_thread_sync;" ::: "memory");
                mbar_wait(mb_ld[1 - st], ((blk + 1) >> 1) & 1);
                const uint32_t sb = stg[1 - st];
                const uint64_t dkh = mk_desc(sb), dkl = mk_desc(sb + 8192);
                const uint64_t dvh = mk_desc(sb + 16384);
                #pragma unroll
                for (int ks = 0; ks < 4; ks++) {
                    mma_ts(TS,  Q1H + ks*8, dkh + 2*ks, AT_IDESC, ks > 0);
                    mma_ts(TS,  Q1H + ks*8, dkl + 2*ks, AT_IDESC, true);
                    mma_ts(TS,  Q1L + ks*8, dkh + 2*ks, AT_IDESC, true);
                    mma_ts(TQV, Q2H + ks*8, dvh + 2*ks, AT_IDESC, ks > 0);
                    mma_ts(TQV, Q2L + ks*8, dvh + 2*ks, AT_IDESC, true);
                }
                asm volatile(
                    "tcgen05.commit.cta_group::1.mbarrier::arrive::one.shared::cluster.b64 [%0];"
                    :: "r"(mb_sq) : "memory");
            }
        }

        #pragma unroll
        for (int j = 0; j < 64; j++) out[j] += __uint_as_float(pr[j]);
    }

    const float inv = 1.0f / l_i;
    float4* op = (float4*)(outg + ((size_t)b * kS + q0 + t) * kDM + h * 64);
    #pragma unroll
    for (int c4 = 0; c4 < 16; c4++) {
        float4 v;
        v.x = out[4*c4+0] * inv; v.y = out[4*c4+1] * inv;
        v.z = out[4*c4+2] * inv; v.w = out[4*c4+3] * inv;
        op[c4] = v;
    }
    __syncthreads();
    if (wid == 0)
        asm volatile("tcgen05.dealloc.cta_group::1.sync.aligned.b32 %0, %1;"
                     :: "r"(tmem), "r"(256u));

#else  // ------- FFMA fallback (never runs on GB300) -------
    float q1r[64], q2r[64], out[64];
    for (int d = 0; d < 64; d++) {
        size_t idx = ((size_t)bh * kS + q0 + t) * kDK + d;
        q1r[d] = __bfloat162float(q1h[idx]) + __bfloat162float(q1l[idx]);
        q2r[d] = __bfloat162float(q2h[idx]) + __bfloat162float(q2l[idx]);
        out[d] = 0.f;
    }
    float m_i = -1e30f, l_i = 0.f;
    for (int j = 0; j < kS; j++) {
        const int blk = j >> 6, jr = j & 63;
        const size_t toff = ((size_t)bh * 16 + blk) * 4096;
        float s = 0.f, qv = 0.f;
        for (int d = 0; d < 64; d++) {
            uint32_t o = sw128((uint32_t)(jr * 128 + d * 2));
            float kr = __bfloat162float(*(const __nv_bfloat16*)((const char*)(krh + toff) + o))
                     + __bfloat162float(*(const __nv_bfloat16*)((const char*)(krl + toff) + o));
            float vr = __bfloat162float(*(const __nv_bfloat16*)((const char*)(vrh + toff) + o));
            s += q1r[d] * kr; qv += q2r[d] * vr;
        }
        if (mask[(size_t)b * kS * kS + (size_t)(q0 + t) * kS + j] == 0) s = -1.0e9f;
        float mnew = fmaxf(m_i, s);
        float scv = __expf(m_i - mnew), p = __expf(s - mnew);
        for (int d = 0; d < 64; d++) {
            uint32_t o = sw128((uint32_t)(d * 128 + jr * 2));
            float kv = __bfloat162float(*(const __nv_bfloat16*)((const char*)(kth + toff) + o))
                     + __bfloat162float(*(const __nv_bfloat16*)((const char*)(ktl + toff) + o));
            out[d] = out[d] * scv + p * qv * kv;
        }
        l_i = l_i * scv + p;
        m_i = mnew;
    }
    const float inv = 1.0f / l_i;
    for (int d = 0; d < 64; d++)
        outg[((size_t)b * kS + q0 + t) * kDM + h * 64 + d] = out[d] * inv;
#endif
}

// ---------------------------------------------------------------------------
extern "C" void kernel_launch(void* const* d_in, const int* in_sizes, int n_in,
                              void* d_out, int out_size)
{
    (void)in_sizes; (void)n_in; (void)out_size;
    const float* query = (const float*)d_in[0];
    const float* key_  = (const float*)d_in[1];
    const float* value = (const float*)d_in[2];
    const int*   mask  = (const int*)  d_in[3];
    const float* Wq  = (const float*)d_in[4];  const float* bq  = (const float*)d_in[5];
    const float* Wk  = (const float*)d_in[6];  const float* bk  = (const float*)d_in[7];
    const float* Wv  = (const float*)d_in[8];  const float* bv  = (const float*)d_in[9];
    const float* Wo  = (const float*)d_in[10]; const float* bo  = (const float*)d_in[11];
    const float* Wkl = (const float*)d_in[12]; const float* bkl = (const float*)d_in[13];
    const float* Wql = (const float*)d_in[14]; const float* bql = (const float*)d_in[15];
    const float* Wq2 = (const float*)d_in[16]; const float* bq2 = (const float*)d_in[17];
    const float* Wvl = (const float*)d_in[18]; const float* bvl = (const float*)d_in[19];
    const float* Wel = (const float*)d_in[20]; const float* bel = (const float*)d_in[21];

    float *qh, *kh, *vh, *att;
    __nv_bfloat16 *krh, *krl, *vrh, *kth, *ktl, *q1h, *q1l, *q2h, *q2l;
    cudaGetSymbolAddress((void**)&qh,  g_qh);
    cudaGetSymbolAddress((void**)&kh,  g_kh);
    cudaGetSymbolAddress((void**)&vh,  g_vh);
    cudaGetSymbolAddress((void**)&att, g_att);
    cudaGetSymbolAddress((void**)&krh, g_krh);
    cudaGetSymbolAddress((void**)&krl, g_krl);
    cudaGetSymbolAddress((void**)&vrh, g_vrh);
    cudaGetSymbolAddress((void**)&kth, g_kth);
    cudaGetSymbolAddress((void**)&ktl, g_ktl);
    cudaGetSymbolAddress((void**)&q1h, g_q1h);
    cudaGetSymbolAddress((void**)&q1l, g_q1l);
    cudaGetSymbolAddress((void**)&q2h, g_q2h);
    cudaGetSymbolAddress((void**)&q2l, g_q2l);

    const int GEMM_SMEM = 66560;
    cudaFuncSetAttribute(tc_gemm, cudaFuncAttributeMaxDynamicSharedMemorySize, GEMM_SMEM);

    dim3 gg(8, 32);

    tc_gemm<<<gg, 256, GEMM_SMEM>>>(query, Wq, bq, qh, 1);
    tc_gemm<<<gg, 256, GEMM_SMEM>>>(key_,  Wk, bk, kh, 1);
    tc_gemm<<<gg, 256, GEMM_SMEM>>>(value, Wv, bv, vh, 1);

    const int CK_SMEM = 4 * 4096 * 4;
    const int FQ_SMEM = (4096 + 64*65 + 3*4096 + 4096) * 4;
    cudaFuncSetAttribute(conv_kv, cudaFuncAttributeMaxDynamicSharedMemorySize, CK_SMEM);
    cudaFuncSetAttribute(fused_q, cudaFuncAttributeMaxDynamicSharedMemorySize, FQ_SMEM);
    conv_kv<<<1024, 256, CK_SMEM>>>(kh, vh, Wkl, bkl, Wvl, bvl, krh, krl, vrh, kth, ktl);
    fused_q<<<1024, 256, FQ_SMEM>>>(qh, Wql, bql, Wel, bel, Wq2, bq2, q1h, q1l, q2h, q2l);

    const int ATT_SMEM = 114688 + 1024;   // 2 stages (80KB) + P hi/lo (32KB) + align
    cudaFuncSetAttribute(attn_tc, cudaFuncAttributeMaxDynamicSharedMemorySize, ATT_SMEM);
    attn_tc<<<dim3(8, 64), 128, ATT_SMEM>>>(q1h, q1l, q2h, q2l,
                                            krh, krl, vrh, kth, ktl, mask, att);

    tc_gemm<<<gg, 256, GEMM_SMEM>>>(att, Wo, bo, (float*)d_out, 0);
}

// round 10
// speedup vs baseline: 4.3842x; 1.1134x over previous
#include <cuda_runtime.h>
#include <cuda_bf16.h>
#include <cstdint>

static constexpr int kB  = 4;
static constexpr int kS  = 1024;
static constexpr int kDM = 1024;
static constexpr int kH  = 16;
static constexpr int kDK = 64;
static constexpr int kBH = kB * kH;   // 64

// ---------------- scratch (static device globals; no allocation) ----------------
__device__ float g_qh [kBH * kS * kDK];
__device__ float g_kh [kBH * kS * kDK];
__device__ float g_vh [kBH * kS * kDK];
__device__ float g_att[kB * kS * kDM];

// bf16 tile buffers (SW128 tile-image layout, [bh][blk16][4096])
__device__ __nv_bfloat16 g_krh[kBH * 16 * 4096];
__device__ __nv_bfloat16 g_krl[kBH * 16 * 4096];
__device__ __nv_bfloat16 g_vrh[kBH * 16 * 4096];
__device__ __nv_bfloat16 g_kth[kBH * 16 * 4096];
__device__ __nv_bfloat16 g_ktl[kBH * 16 * 4096];
// bf16 linear [bh][s][d]
__device__ __nv_bfloat16 g_q1h[kBH * kS * kDK];
__device__ __nv_bfloat16 g_q1l[kBH * kS * kDK];
__device__ __nv_bfloat16 g_q2h[kBH * kS * kDK];
__device__ __nv_bfloat16 g_q2l[kBH * kS * kDK];

// ---------------------------------------------------------------------------
// helpers
// ---------------------------------------------------------------------------
__device__ __forceinline__ uint32_t smem_u32(const void* p) {
    uint32_t a;
    asm("{ .reg .u64 t; cvta.to.shared.u64 t, %1; cvt.u32.u64 %0, t; }" : "=r"(a) : "l"(p));
    return a;
}
__device__ __forceinline__ uint32_t pack_bf2(__nv_bfloat16 a, __nv_bfloat16 b) {
    __nv_bfloat162 t = __halves2bfloat162(a, b);
    return *reinterpret_cast<uint32_t*>(&t);
}
__device__ __forceinline__ uint32_t sw128(uint32_t o) { return o ^ ((o >> 3) & 0x70); }

#if defined(__CUDA_ARCH_FEAT_SM103_ALL) || !defined(__CUDA_ARCH__)
#define HAS_TCGEN05 1
#else
#define HAS_TCGEN05 0
#endif

#if HAS_TCGEN05
__device__ __forceinline__ void mbar_wait(uint32_t mbar, uint32_t parity) {
    asm volatile(
        "{\n\t.reg .pred P;\n\t"
        "LW%=:\n\t"
        "mbarrier.try_wait.parity.acquire.cta.shared::cta.b64 P, [%0], %1;\n\t"
        "@!P bra LW%=;\n\t}"
        :: "r"(mbar), "r"(parity) : "memory");
}

static constexpr uint32_t GE_IDESC =           // M=128, N=128
    (1u << 4) | (1u << 7) | (1u << 10) | ((128u / 8) << 17) | ((128u / 16) << 24);
static constexpr uint32_t AT_IDESC =           // M=128, N=64
    (1u << 4) | (1u << 7) | (1u << 10) | ((64u / 8) << 17) | ((128u / 16) << 24);

static constexpr uint64_t DESC_SW128 =
    (2ull << 61) | (1ull << 46) | (64ull << 32) | (1ull << 16);

__device__ __forceinline__ uint64_t mk_desc(uint32_t addr) {
    return DESC_SW128 | (uint64_t)((addr >> 4) & 0x3FFF);
}

__device__ __forceinline__ void mma_ss(uint32_t d, uint64_t ad, uint64_t bd,
                                       uint32_t idesc, bool en) {
    uint32_t e = en ? 1u : 0u;
    asm volatile(
        "{\n\t.reg .pred p;\n\t"
        "setp.ne.u32 p, %5, 0;\n\t"
        "tcgen05.mma.cta_group::1.kind::f16 [%0], %1, %2, %3, {%4, %4, %4, %4}, p;\n\t}"
        :: "r"(d), "l"(ad), "l"(bd), "r"(idesc), "r"(0u), "r"(e) : "memory");
}
__device__ __forceinline__ void mma_ts(uint32_t d, uint32_t at, uint64_t bd,
                                       uint32_t idesc, bool en) {
    uint32_t e = en ? 1u : 0u;
    asm volatile(
        "{\n\t.reg .pred p;\n\t"
        "setp.ne.u32 p, %5, 0;\n\t"
        "tcgen05.mma.cta_group::1.kind::f16 [%0], [%1], %2, %3, {%4, %4, %4, %4}, p;\n\t}"
        :: "r"(d), "r"(at), "l"(bd), "r"(idesc), "r"(0u), "r"(e) : "memory");
}

__device__ __forceinline__ void bulk_cp(uint32_t smem_dst, const void* gsrc,
                                        uint32_t bytes, uint32_t mbar) {
    asm volatile(
        "cp.async.bulk.shared::cta.global.mbarrier::complete_tx::bytes [%0], [%1], %2, [%3];"
        :: "r"(smem_dst), "l"(gsrc), "r"(bytes), "r"(mbar) : "memory");
}
__device__ __forceinline__ void mbar_expect(uint32_t mbar, uint32_t bytes) {
    asm volatile("mbarrier.arrive.expect_tx.shared.b64 _, [%0], %1;"
                 :: "r"(mbar), "r"(bytes) : "memory");
}

#define LDTM_X32(r, addr) \
    asm volatile( \
        "tcgen05.ld.sync.aligned.32x32b.x32.b32 " \
        "{%0, %1, %2, %3, %4, %5, %6, %7, " \
        " %8, %9, %10, %11, %12, %13, %14, %15, " \
        " %16, %17, %18, %19, %20, %21, %22, %23, " \
        " %24, %25, %26, %27, %28, %29, %30, %31}, [%32];" \
        : "=r"((r)[0]),  "=r"((r)[1]),  "=r"((r)[2]),  "=r"((r)[3]), \
          "=r"((r)[4]),  "=r"((r)[5]),  "=r"((r)[6]),  "=r"((r)[7]), \
          "=r"((r)[8]),  "=r"((r)[9]),  "=r"((r)[10]), "=r"((r)[11]), \
          "=r"((r)[12]), "=r"((r)[13]), "=r"((r)[14]), "=r"((r)[15]), \
          "=r"((r)[16]), "=r"((r)[17]), "=r"((r)[18]), "=r"((r)[19]), \
          "=r"((r)[20]), "=r"((r)[21]), "=r"((r)[22]), "=r"((r)[23]), \
          "=r"((r)[24]), "=r"((r)[25]), "=r"((r)[26]), "=r"((r)[27]), \
          "=r"((r)[28]), "=r"((r)[29]), "=r"((r)[30]), "=r"((r)[31]) \
        : "r"(addr))

#define TSTM_X32(addr, r) \
    asm volatile( \
        "tcgen05.st.sync.aligned.32x32b.x32.b32 [%0], " \
        "{%1, %2, %3, %4, %5, %6, %7, %8, " \
        " %9, %10, %11, %12, %13, %14, %15, %16, " \
        " %17, %18, %19, %20, %21, %22, %23, %24, " \
        " %25, %26, %27, %28, %29, %30, %31, %32};" \
        :: "r"(addr), \
           "r"((r)[0]),  "r"((r)[1]),  "r"((r)[2]),  "r"((r)[3]), \
           "r"((r)[4]),  "r"((r)[5]),  "r"((r)[6]),  "r"((r)[7]), \
           "r"((r)[8]),  "r"((r)[9]),  "r"((r)[10]), "r"((r)[11]), \
           "r"((r)[12]), "r"((r)[13]), "r"((r)[14]), "r"((r)[15]), \
           "r"((r)[16]), "r"((r)[17]), "r"((r)[18]), "r"((r)[19]), \
           "r"((r)[20]), "r"((r)[21]), "r"((r)[22]), "r"((r)[23]), \
           "r"((r)[24]), "r"((r)[25]), "r"((r)[26]), "r"((r)[27]), \
           "r"((r)[28]), "r"((r)[29]), "r"((r)[30]), "r"((r)[31]) \
        : "memory")
#endif  // HAS_TCGEN05

// convert float4 -> bf16 hi + bf16 residual, store 8B to each smem tile
__device__ __forceinline__ void store_hilo(float4 v, uint32_t hoff, uint32_t loff) {
    __nv_bfloat16 h0 = __float2bfloat16(v.x), h1 = __float2bfloat16(v.y);
    __nv_bfloat16 h2 = __float2bfloat16(v.z), h3 = __float2bfloat16(v.w);
    float r0 = v.x - __bfloat162float(h0), r1 = v.y - __bfloat162float(h1);
    float r2 = v.z - __bfloat162float(h2), r3 = v.w - __bfloat162float(h3);
    uint32_t hp0 = pack_bf2(h0, h1), hp1 = pack_bf2(h2, h3);
    uint32_t lp0 = pack_bf2(__float2bfloat16(r0), __float2bfloat16(r1));
    uint32_t lp1 = pack_bf2(__float2bfloat16(r2), __float2bfloat16(r3));
    asm volatile("st.shared.v2.b32 [%0], {%1, %2};" :: "r"(hoff), "r"(hp0), "r"(hp1) : "memory");
    asm volatile("st.shared.v2.b32 [%0], {%1, %2};" :: "r"(loff), "r"(lp0), "r"(lp1) : "memory");
}

// pack 8 floats -> uint4 of bf16 hi; and uint4 of residual lo
__device__ __forceinline__ uint4 pack_hi8(const float* f) {
    uint4 u;
    u.x = pack_bf2(__float2bfloat16(f[0]), __float2bfloat16(f[1]));
    u.y = pack_bf2(__float2bfloat16(f[2]), __float2bfloat16(f[3]));
    u.z = pack_bf2(__float2bfloat16(f[4]), __float2bfloat16(f[5]));
    u.w = pack_bf2(__float2bfloat16(f[6]), __float2bfloat16(f[7]));
    return u;
}
__device__ __forceinline__ uint4 pack_lo8(const float* f) {
    float r[8];
    #pragma unroll
    for (int i = 0; i < 8; i++)
        r[i] = f[i] - __bfloat162float(__float2bfloat16(f[i]));
    return pack_hi8(r);
}

// ---------------------------------------------------------------------------
// tc_gemm: C = A*W^T + bias, tcgen05 hi/lo
// ---------------------------------------------------------------------------
__global__ __launch_bounds__(256)
void tc_gemm(const float* __restrict__ A, const float* __restrict__ W,
             const float* __restrict__ bias, float* __restrict__ out, int mode)
{
    extern __shared__ char dsm[];
    const int t   = threadIdx.x;
    const int m0  = blockIdx.y * 128;
    const int n0  = blockIdx.x * 128;

#if HAS_TCGEN05
    __shared__ uint32_t s_tmem;
    __shared__ __align__(8) uint64_t s_mbar;

    const uint32_t base = (smem_u32(dsm) + 1023u) & ~1023u;
    const uint32_t ah = base, al = base + 16384, bhs = base + 32768, bls = base + 49152;
    const int wid = t >> 5;

    if (wid == 0) {
        asm volatile("tcgen05.alloc.cta_group::1.sync.aligned.shared::cta.b32 [%0], %1;"
                     :: "r"(smem_u32(&s_tmem)), "r"(128u) : "memory");
        asm volatile("tcgen05.relinquish_alloc_permit.cta_group::1.sync.aligned;");
    }
    if (t == 0)
        asm volatile("mbarrier.init.shared.b64 [%0], 1;" :: "r"(smem_u32(&s_mbar)) : "memory");
    __syncthreads();
    const uint32_t tmem = s_tmem;
    const uint32_t mbar = smem_u32(&s_mbar);

    const int ty = t >> 4, c4 = t & 15;
    const float* Ap = A + (size_t)(m0 + ty) * 1024 + c4 * 4;
    const float* Wp = W + (size_t)(n0 + ty) * 1024 + c4 * 4;

    int chunk = 0;
    for (int k0 = 0; k0 < 1024; k0 += 64, ++chunk) {
        float4 av[8], wv[8];
        #pragma unroll
        for (int i = 0; i < 8; i++) {
            av[i] = *(const float4*)(Ap + (size_t)(16 * i) * 1024 + k0);
            wv[i] = *(const float4*)(Wp + (size_t)(16 * i) * 1024 + k0);
        }
        if (chunk > 0) mbar_wait(mbar, (chunk - 1) & 1);
        #pragma unroll
        for (int i = 0; i < 8; i++) {
            uint32_t off = sw128((uint32_t)((ty + 16 * i) * 128 + c4 * 8));
            store_hilo(av[i], ah + off, al + off);
            store_hilo(wv[i], bhs + off, bls + off);
        }
        asm volatile("fence.proxy.async.shared::cta;" ::: "memory");
        __syncthreads();
        if (t == 0) {
            const uint64_t dah = mk_desc(ah),  dal = mk_desc(al);
            const uint64_t dbh = mk_desc(bhs), dbl = mk_desc(bls);
            #pragma unroll
            for (int ks = 0; ks < 4; ks++) {
                mma_ss(tmem, dah + 2 * ks, dbh + 2 * ks, GE_IDESC, !(chunk == 0 && ks == 0));
                mma_ss(tmem, dah + 2 * ks, dbl + 2 * ks, GE_IDESC, true);
                mma_ss(tmem, dal + 2 * ks, dbh + 2 * ks, GE_IDESC, true);
            }
            asm volatile(
                "tcgen05.commit.cta_group::1.mbarrier::arrive::one.shared::cluster.b64 [%0];"
                :: "r"(mbar) : "memory");
        }
    }
    mbar_wait(mbar, (16 - 1) & 1);
    __syncthreads();
    asm volatile("tcgen05.fence::after_thread_sync;" ::: "memory");

    if (wid < 4) {
        const int lane = t & 31;
        const int gr = m0 + wid * 32 + lane;
        for (int cb = 0; cb < 128; cb += 32) {
            uint32_t regs[32];
            LDTM_X32(regs, tmem + cb);
            asm volatile("tcgen05.wait::ld.sync.aligned;" ::: "memory");
            if (mode == 0) {
                float* op = out + (size_t)gr * 1024 + n0 + cb;
                #pragma unroll
                for (int c = 0; c < 32; c++)
                    op[c] = __uint_as_float(regs[c]) + bias[n0 + cb + c];
            } else {
                const int b = gr >> 10, s = gr & 1023;
                #pragma unroll
                for (int c = 0; c < 32; c++) {
                    const int gc = n0 + cb + c;
                    const int h = gc >> 6, d = gc & 63;
                    out[(((size_t)(b * kH + h)) * kS + s) * kDK + d] =
                        __uint_as_float(regs[c]) + bias[gc];
                }
            }
        }
    }
    __syncthreads();
    if (wid == 0)
        asm volatile("tcgen05.dealloc.cta_group::1.sync.aligned.b32 %0, %1;"
                     :: "r"(tmem), "r"(128u));
#else
    float* As = (float*)dsm;
    float* Bs = As + 16 * 128;
    const int tx = t & 15, ty = t >> 4;
    const int lm = t & 127;
    const int kb = (t >> 7) * 8;
    float acc[8][8];
    #pragma unroll
    for (int i = 0; i < 8; i++)
        #pragma unroll
        for (int j = 0; j < 8; j++) acc[i][j] = 0.f;
    for (int k0 = 0; k0 < 1024; k0 += 16) {
        const float4* Ag = (const float4*)(A + (size_t)(m0 + lm) * 1024 + k0 + kb);
        const float4* Wg = (const float4*)(W + (size_t)(n0 + lm) * 1024 + k0 + kb);
        float4 a0 = Ag[0], a1 = Ag[1];
        float4 b0 = Wg[0], b1 = Wg[1];
        As[(kb+0)*128+lm]=a0.x; As[(kb+1)*128+lm]=a0.y; As[(kb+2)*128+lm]=a0.z; As[(kb+3)*128+lm]=a0.w;
        As[(kb+4)*128+lm]=a1.x; As[(kb+5)*128+lm]=a1.y; As[(kb+6)*128+lm]=a1.z; As[(kb+7)*128+lm]=a1.w;
        Bs[(kb+0)*128+lm]=b0.x; Bs[(kb+1)*128+lm]=b0.y; Bs[(kb+2)*128+lm]=b0.z; Bs[(kb+3)*128+lm]=b0.w;
        Bs[(kb+4)*128+lm]=b1.x; Bs[(kb+5)*128+lm]=b1.y; Bs[(kb+6)*128+lm]=b1.z; Bs[(kb+7)*128+lm]=b1.w;
        __syncthreads();
        #pragma unroll
        for (int kk = 0; kk < 16; kk++) {
            float af[8], bf[8];
            #pragma unroll
            for (int i = 0; i < 8; i++) af[i] = As[kk*128 + ty + 16*i];
            #pragma unroll
            for (int j = 0; j < 8; j++) bf[j] = Bs[kk*128 + tx + 16*j];
            #pragma unroll
            for (int i = 0; i < 8; i++)
                #pragma unroll
                for (int j = 0; j < 8; j++) acc[i][j] += af[i] * bf[j];
        }
        __syncthreads();
    }
    #pragma unroll
    for (int i = 0; i < 8; i++) {
        const int r = m0 + ty + 16*i;
        #pragma unroll
        for (int j = 0; j < 8; j++) {
            const int c = n0 + tx + 16*j;
            float v = acc[i][j] + bias[c];
            if (mode == 0) out[(size_t)r * 1024 + c] = v;
            else {
                int b = r >> 10, s = r & 1023, h = c >> 6, d = c & 63;
                out[(((size_t)(b * kH + h)) * kS + s) * kDK + d] = v;
            }
        }
    }
#endif
}

// ---------------------------------------------------------------------------
// conv_kv: kr tiles (hi/lo), vr tiles (hi), kT tiles (hi/lo)
// ---------------------------------------------------------------------------
__global__ __launch_bounds__(256)
void conv_kv(const float* __restrict__ Kh, const float* __restrict__ Vh,
             const float* __restrict__ Wkl, const float* __restrict__ bkl,
             const float* __restrict__ Wvl, const float* __restrict__ bvl,
             __nv_bfloat16* __restrict__ krh, __nv_bfloat16* __restrict__ krl,
             __nv_bfloat16* __restrict__ vrh,
             __nv_bfloat16* __restrict__ kth, __nv_bfloat16* __restrict__ ktl)
{
    extern __shared__ float fs[];
    float* W1 = fs;
    float* W2 = W1 + 4096;
    float* Xs = W2 + 4096;
    float* St = Xs + 4096;

    const int t  = threadIdx.x;
    const int tx = t & 15, ty = t >> 4;
    const int r0 = blockIdx.x * 64;
    const int lr = t & 63;
    const int kb = (t >> 6) * 16;
    const int bh = r0 >> 10, blkid = (r0 >> 6) & 15;
    const size_t tbase = ((size_t)bh * 16 + blkid) * 4096;
    const int wr = t >> 2, wq = t & 3;

    #pragma unroll
    for (int q = 0; q < 4; q++) {
        float4 w1 = *(const float4*)(Wkl + (size_t)lr * 64 + kb + 4*q);
        float4 w2 = *(const float4*)(Wvl + (size_t)lr * 64 + kb + 4*q);
        W1[(kb+4*q+0)*64+lr]=w1.x; W1[(kb+4*q+1)*64+lr]=w1.y; W1[(kb+4*q+2)*64+lr]=w1.z; W1[(kb+4*q+3)*64+lr]=w1.w;
        W2[(kb+4*q+0)*64+lr]=w2.x; W2[(kb+4*q+1)*64+lr]=w2.y; W2[(kb+4*q+2)*64+lr]=w2.z; W2[(kb+4*q+3)*64+lr]=w2.w;
    }

    // ---- pass 0: Kh -> kT tiles + kr tiles ----
    #pragma unroll
    for (int q = 0; q < 4; q++) {
        float4 x = *(const float4*)(Kh + (size_t)(r0 + lr) * 64 + kb + 4*q);
        Xs[(kb+4*q+0)*64+lr]=x.x; Xs[(kb+4*q+1)*64+lr]=x.y;
        Xs[(kb+4*q+2)*64+lr]=x.z; Xs[(kb+4*q+3)*64+lr]=x.w;
    }
    __syncthreads();

    {
        const int d = t & 63, seg = t >> 6;
        float f[16];
        #pragma unroll
        for (int i = 0; i < 16; i++) f[i] = Xs[d * 64 + seg * 16 + i];
        uint32_t o0 = (uint32_t)(d * 128 + seg * 32);
        uint32_t s0 = sw128(o0), s1 = sw128(o0 + 16);
        char* th = (char*)(kth + tbase);
        char* tl = (char*)(ktl + tbase);
        *(uint4*)(th + s0) = pack_hi8(f);     *(uint4*)(th + s1) = pack_hi8(f + 8);
        *(uint4*)(tl + s0) = pack_lo8(f);     *(uint4*)(tl + s1) = pack_lo8(f + 8);
    }

    {
        float acc[4][4];
        #pragma unroll
        for (int i = 0; i < 4; i++)
            #pragma unroll
            for (int j = 0; j < 4; j++) acc[i][j] = 0.f;
        #pragma unroll 16
        for (int kk = 0; kk < 64; kk++) {
            float af[4], bf[4];
            #pragma unroll
            for (int i = 0; i < 4; i++) af[i] = Xs[kk*64 + ty + 16*i];
            #pragma unroll
            for (int j = 0; j < 4; j++) bf[j] = W1[kk*64 + tx + 16*j];
            #pragma unroll
            for (int i = 0; i < 4; i++)
                #pragma unroll
                for (int j = 0; j < 4; j++) acc[i][j] += af[i] * bf[j];
        }
        #pragma unroll
        for (int i = 0; i < 4; i++)
            #pragma unroll
            for (int j = 0; j < 4; j++)
                St[(ty + 16*i) * 64 + tx + 16*j] = fmaxf(acc[i][j] + bkl[tx + 16*j], 0.f);
    }
    __syncthreads();
    {
        float f[16];
        #pragma unroll
        for (int i = 0; i < 16; i++) f[i] = St[wr * 64 + wq * 16 + i];
        uint32_t o0 = (uint32_t)(wr * 128 + wq * 32);
        uint32_t s0 = sw128(o0), s1 = sw128(o0 + 16);
        char* th = (char*)(krh + tbase);
        char* tl = (char*)(krl + tbase);
        *(uint4*)(th + s0) = pack_hi8(f);     *(uint4*)(th + s1) = pack_hi8(f + 8);
        *(uint4*)(tl + s0) = pack_lo8(f);     *(uint4*)(tl + s1) = pack_lo8(f + 8);
    }
    __syncthreads();

    // ---- pass 1: Vh -> vrh tiles ----
    #pragma unroll
    for (int q = 0; q < 4; q++) {
        float4 x = *(const float4*)(Vh + (size_t)(r0 + lr) * 64 + kb + 4*q);
        Xs[(kb+4*q+0)*64+lr]=x.x; Xs[(kb+4*q+1)*64+lr]=x.y;
        Xs[(kb+4*q+2)*64+lr]=x.z; Xs[(kb+4*q+3)*64+lr]=x.w;
    }
    __syncthreads();
    {
        float acc[4][4];
        #pragma unroll
        for (int i = 0; i < 4; i++)
            #pragma unroll
            for (int j = 0; j < 4; j++) acc[i][j] = 0.f;
        #pragma unroll 16
        for (int kk = 0; kk < 64; kk++) {
            float af[4], bf[4];
            #pragma unroll
            for (int i = 0; i < 4; i++) af[i] = Xs[kk*64 + ty + 16*i];
            #pragma unroll
            for (int j = 0; j < 4; j++) bf[j] = W2[kk*64 + tx + 16*j];
            #pragma unroll
            for (int i = 0; i < 4; i++)
                #pragma unroll
                for (int j = 0; j < 4; j++) acc[i][j] += af[i] * bf[j];
        }
        #pragma unroll
        for (int i = 0; i < 4; i++)
            #pragma unroll
            for (int j = 0; j < 4; j++)
                St[(ty + 16*i) * 64 + tx + 16*j] = fmaxf(acc[i][j] + bvl[tx + 16*j], 0.f);
    }
    __syncthreads();
    {
        float f[16];
        #pragma unroll
        for (int i = 0; i < 16; i++) f[i] = St[wr * 64 + wq * 16 + i];
        uint32_t o0 = (uint32_t)(wr * 128 + wq * 32);
        uint32_t s0 = sw128(o0), s1 = sw128(o0 + 16);
        char* th = (char*)(vrh + tbase);
        *(uint4*)(th + s0) = pack_hi8(f);     *(uint4*)(th + s1) = pack_hi8(f + 8);
    }
}

// ---------------------------------------------------------------------------
// fused_q: q1 -> q1h/q1l, q2 -> q2h/q2l (linear bf16)
// ---------------------------------------------------------------------------
__global__ __launch_bounds__(256)
void fused_q(const float* __restrict__ X,
             const float* __restrict__ Wql, const float* __restrict__ bql,
             const float* __restrict__ Wel, const float* __restrict__ bel,
             const float* __restrict__ Wq2, const float* __restrict__ bq2,
             __nv_bfloat16* __restrict__ q1h, __nv_bfloat16* __restrict__ q1l,
             __nv_bfloat16* __restrict__ q2h, __nv_bfloat16* __restrict__ q2l)
{
    extern __shared__ float fs[];
    float* Xs = fs;
    float* Ys = Xs + 4096;
    float* W1 = Ys + 64 * 65;
    float* W2 = W1 + 4096;
    float* W3 = W2 + 4096;
    float* St = W3 + 4096;

    const int t  = threadIdx.x;
    const int tx = t & 15, ty = t >> 4;
    const int r0 = blockIdx.x * 64;
    const int lr = t & 63;
    const int kb = (t >> 6) * 16;
    const int wr = t >> 2, wq = t & 3;

    #pragma unroll
    for (int q = 0; q < 4; q++) {
        float4 w1 = *(const float4*)(Wql + (size_t)lr * 64 + kb + 4*q);
        float4 w2 = *(const float4*)(Wel + (size_t)lr * 64 + kb + 4*q);
        float4 w3 = *(const float4*)(Wq2 + (size_t)lr * 64 + kb + 4*q);
        W1[(kb+4*q+0)*64+lr]=w1.x; W1[(kb+4*q+1)*64+lr]=w1.y; W1[(kb+4*q+2)*64+lr]=w1.z; W1[(kb+4*q+3)*64+lr]=w1.w;
        W2[(kb+4*q+0)*64+lr]=w2.x; W2[(kb+4*q+1)*64+lr]=w2.y; W2[(kb+4*q+2)*64+lr]=w2.z; W2[(kb+4*q+3)*64+lr]=w2.w;
        W3[(kb+4*q+0)*64+lr]=w3.x; W3[(kb+4*q+1)*64+lr]=w3.y; W3[(kb+4*q+2)*64+lr]=w3.z; W3[(kb+4*q+3)*64+lr]=w3.w;
        float4 x = *(const float4*)(X + (size_t)(r0 + lr) * 64 + kb + 4*q);
        Xs[(kb+4*q+0)*64+lr]=x.x; Xs[(kb+4*q+1)*64+lr]=x.y; Xs[(kb+4*q+2)*64+lr]=x.z; Xs[(kb+4*q+3)*64+lr]=x.w;
    }
    __syncthreads();

    // stage 1: q1a -> Ys
    {
        float acc[4][4];
        #pragma unroll
        for (int i = 0; i < 4; i++)
            #pragma unroll
            for (int j = 0; j < 4; j++) acc[i][j] = 0.f;
        #pragma unroll 16
        for (int kk = 0; kk < 64; kk++) {
            float af[4], bf[4];
            #pragma unroll
            for (int i = 0; i < 4; i++) af[i] = Xs[kk*64 + ty + 16*i];
            #pragma unroll
            for (int j = 0; j < 4; j++) bf[j] = W1[kk*64 + tx + 16*j];
            #pragma unroll
            for (int i = 0; i < 4; i++)
                #pragma unroll
                for (int j = 0; j < 4; j++) acc[i][j] += af[i] * bf[j];
        }
        #pragma unroll
        for (int i = 0; i < 4; i++)
            #pragma unroll
            for (int j = 0; j < 4; j++)
                Ys[(tx + 16*j) * 65 + ty + 16*i] = fmaxf(acc[i][j] + bql[tx + 16*j], 0.f);
    }

    // q2 -> St -> q2h/q2l
    {
        float acc[4][4];
        #pragma unroll
        for (int i = 0; i < 4; i++)
            #pragma unroll
            for (int j = 0; j < 4; j++) acc[i][j] = 0.f;
        #pragma unroll 16
        for (int kk = 0; kk < 64; kk++) {
            float af[4], bf[4];
            #pragma unroll
            for (int i = 0; i < 4; i++) af[i] = Xs[kk*64 + ty + 16*i];
            #pragma unroll
            for (int j = 0; j < 4; j++) bf[j] = W3[kk*64 + tx + 16*j];
            #pragma unroll
            for (int i = 0; i < 4; i++)
                #pragma unroll
                for (int j = 0; j < 4; j++) acc[i][j] += af[i] * bf[j];
        }
        __syncthreads();
        #pragma unroll
        for (int i = 0; i < 4; i++)
            #pragma unroll
            for (int j = 0; j < 4; j++)
                St[(ty + 16*i) * 64 + tx + 16*j] = fmaxf(acc[i][j] + bq2[tx + 16*j], 0.f);
    }
    __syncthreads();
    {
        float f[16];
        #pragma unroll
        for (int i = 0; i < 16; i++) f[i] = St[wr * 64 + wq * 16 + i];
        uint4* dh = (uint4*)(q2h + (size_t)(r0 + wr) * 64 + wq * 16);
        uint4* dl = (uint4*)(q2l + (size_t)(r0 + wr) * 64 + wq * 16);
        dh[0] = pack_hi8(f); dh[1] = pack_hi8(f + 8);
        dl[0] = pack_lo8(f); dl[1] = pack_lo8(f + 8);
    }
    __syncthreads();

    // q1 from Ys -> St -> q1h/q1l
    {
        float acc[4][4];
        #pragma unroll
        for (int i = 0; i < 4; i++)
            #pragma unroll
            for (int j = 0; j < 4; j++) acc[i][j] = 0.f;
        #pragma unroll 16
        for (int kk = 0; kk < 64; kk++) {
            float af[4], bf[4];
            #pragma unroll
            for (int i = 0; i < 4; i++) af[i] = Ys[kk*65 + ty + 16*i];
            #pragma unroll
            for (int j = 0; j < 4; j++) bf[j] = W2[kk*64 + tx + 16*j];
            #pragma unroll
            for (int i = 0; i < 4; i++)
                #pragma unroll
                for (int j = 0; j < 4; j++) acc[i][j] += af[i] * bf[j];
        }
        #pragma unroll
        for (int i = 0; i < 4; i++)
            #pragma unroll
            for (int j = 0; j < 4; j++)
                St[(ty + 16*i) * 64 + tx + 16*j] = fmaxf(acc[i][j] + bel[tx + 16*j], 0.f);
    }
    __syncthreads();
    {
        float f[16];
        #pragma unroll
        for (int i = 0; i < 16; i++) f[i] = St[wr * 64 + wq * 16 + i];
        uint4* dh = (uint4*)(q1h + (size_t)(r0 + wr) * 64 + wq * 16);
        uint4* dl = (uint4*)(q1l + (size_t)(r0 + wr) * 64 + wq * 16);
        dh[0] = pack_hi8(f); dh[1] = pack_hi8(f + 8);
        dl[0] = pack_lo8(f); dl[1] = pack_lo8(f + 8);
    }
}

// ---------------------------------------------------------------------------
// attn v5: pipelined tcgen05 attention; Ph aliased into the dead krh/krl
// region of the current stage -> smem 99KB -> guaranteed 2 CTAs/SM.
// TMEM (256): Q1H@0 Q1L@32 Q2H@64 Q2L@96 | TQV@128 | TS/TPK@192
// smem: 2 stages x {krh,krl,vrh,kth,ktl} (40KB) + Pl 16KB = 96KB
// (Ph lives at stg[st]+0..16KB: krh/krl are dead between S(i) completion
//  and the stage refill, which happens only after the PK wait.)
// ---------------------------------------------------------------------------
__global__ __launch_bounds__(128, 2)
void attn_tc(const __nv_bfloat16* __restrict__ q1h, const __nv_bfloat16* __restrict__ q1l,
             const __nv_bfloat16* __restrict__ q2h, const __nv_bfloat16* __restrict__ q2l,
             const __nv_bfloat16* __restrict__ krh, const __nv_bfloat16* __restrict__ krl,
             const __nv_bfloat16* __restrict__ vrh,
             const __nv_bfloat16* __restrict__ kth, const __nv_bfloat16* __restrict__ ktl,
             const int* __restrict__ mask, float* __restrict__ outg)
{
    const int t  = threadIdx.x;
    const int bh = blockIdx.y;
    const int q0 = blockIdx.x * 128;
    const int b  = bh >> 4, h = bh & 15;

#if HAS_TCGEN05
    extern __shared__ char dsm[];
    __shared__ uint32_t s_tmem;
    __shared__ __align__(8) uint64_t s_mb[4];   // 0:sq 1:pk 2:ld0 3:ld1

    const uint32_t base = (smem_u32(dsm) + 1023u) & ~1023u;
    const uint32_t stg[2] = { base, base + 40960 };
    const uint32_t Pl = base + 81920;

    const int wid = t >> 5;
    if (wid == 0) {
        asm volatile("tcgen05.alloc.cta_group::1.sync.aligned.shared::cta.b32 [%0], %1;"
                     :: "r"(smem_u32(&s_tmem)), "r"(256u) : "memory");
        asm volatile("tcgen05.relinquish_alloc_permit.cta_group::1.sync.aligned;");
    }
    if (t == 0) {
        #pragma unroll
        for (int i = 0; i < 4; i++)
            asm volatile("mbarrier.init.shared.b64 [%0], 1;"
                         :: "r"(smem_u32(&s_mb[i])) : "memory");
    }
    __syncthreads();
    const uint32_t tmem = s_tmem;
    const uint32_t mb_sq = smem_u32(&s_mb[0]), mb_pk = smem_u32(&s_mb[1]);
    const uint32_t mb_ld[2] = { smem_u32(&s_mb[2]), smem_u32(&s_mb[3]) };
    const uint32_t Q1H = tmem, Q1L = tmem + 32, Q2H = tmem + 64, Q2L = tmem + 96;
    const uint32_t TQV = tmem + 128, TS = tmem + 192;
    const uint32_t warp_off = (uint32_t)(t >> 5) << 21;

    const size_t tb = (size_t)bh * 16;

    // kick off bulk loads for blk 0 and 1
    if (t == 0) {
        asm volatile("fence.proxy.async.shared::cta;" ::: "memory");
        #pragma unroll
        for (int s = 0; s < 2; s++) {
            mbar_expect(mb_ld[s], 40960);
            const size_t off = (tb + s) * 4096;
            bulk_cp(stg[s] + 0,     (const char*)(krh + off), 8192, mb_ld[s]);
            bulk_cp(stg[s] + 8192,  (const char*)(krl + off), 8192, mb_ld[s]);
            bulk_cp(stg[s] + 16384, (const char*)(vrh + off), 8192, mb_ld[s]);
            bulk_cp(stg[s] + 24576, (const char*)(kth + off), 8192, mb_ld[s]);
            bulk_cp(stg[s] + 32768, (const char*)(ktl + off), 8192, mb_ld[s]);
        }
    }

    // upload q rows (row t) to TMEM: q1h/q1l/q2h/q2l
    {
        uint32_t r[32];
        const uint4* p = (const uint4*)(q1h + ((size_t)bh * kS + q0 + t) * kDK);
        #pragma unroll
        for (int i = 0; i < 8; i++) { uint4 v = p[i];
            r[4*i]=v.x; r[4*i+1]=v.y; r[4*i+2]=v.z; r[4*i+3]=v.w; }
        TSTM_X32(Q1H + warp_off, r);
        p = (const uint4*)(q1l + ((size_t)bh * kS + q0 + t) * kDK);
        #pragma unroll
        for (int i = 0; i < 8; i++) { uint4 v = p[i];
            r[4*i]=v.x; r[4*i+1]=v.y; r[4*i+2]=v.z; r[4*i+3]=v.w; }
        TSTM_X32(Q1L + warp_off, r);
        p = (const uint4*)(q2h + ((size_t)bh * kS + q0 + t) * kDK);
        #pragma unroll
        for (int i = 0; i < 8; i++) { uint4 v = p[i];
            r[4*i]=v.x; r[4*i+1]=v.y; r[4*i+2]=v.z; r[4*i+3]=v.w; }
        TSTM_X32(Q2H + warp_off, r);
        p = (const uint4*)(q2l + ((size_t)bh * kS + q0 + t) * kDK);
        #pragma unroll
        for (int i = 0; i < 8; i++) { uint4 v = p[i];
            r[4*i]=v.x; r[4*i+1]=v.y; r[4*i+2]=v.z; r[4*i+3]=v.w; }
        TSTM_X32(Q2L + warp_off, r);
        asm volatile("tcgen05.wait::st.sync.aligned;" ::: "memory");
    }
    asm volatile("tcgen05.fence::before_thread_sync;" ::: "memory");
    __syncthreads();

    // issue S/QV for blk 0
    if (t == 0) {
        asm volatile("tcgen05.fence::after_thread_sync;" ::: "memory");
        mbar_wait(mb_ld[0], 0);
        const uint64_t dkh = mk_desc(stg[0]), dkl = mk_desc(stg[0] + 8192);
        const uint64_t dvh = mk_desc(stg[0] + 16384);
        #pragma unroll
        for (int ks = 0; ks < 4; ks++) {
            mma_ts(TS,  Q1H + ks*8, dkh + 2*ks, AT_IDESC, ks > 0);
            mma_ts(TS,  Q1H + ks*8, dkl + 2*ks, AT_IDESC, true);
            mma_ts(TS,  Q1L + ks*8, dkh + 2*ks, AT_IDESC, true);
            mma_ts(TQV, Q2H + ks*8, dvh + 2*ks, AT_IDESC, ks > 0);
            mma_ts(TQV, Q2L + ks*8, dvh + 2*ks, AT_IDESC, true);
        }
        asm volatile(
            "tcgen05.commit.cta_group::1.mbarrier::arrive::one.shared::cluster.b64 [%0];"
            :: "r"(mb_sq) : "memory");
    }

    float out[64];
    #pragma unroll
    for (int c = 0; c < 64; c++) out[c] = 0.f;
    float m_i = -1e30f, l_i = 0.f;

    for (int blk = 0; blk < 16; blk++) {
        const int st = blk & 1;
        const int k0 = blk * 64;
        const uint32_t Ph = stg[st];   // aliases dead krh/krl of current stage

        mbar_wait(mb_sq, blk & 1);
        asm volatile("tcgen05.fence::after_thread_sync;" ::: "memory");

        uint32_t sr[64];
        LDTM_X32(sr, TS);
        LDTM_X32(sr + 32, TS + 32);
        asm volatile("tcgen05.wait::ld.sync.aligned;" ::: "memory");

        // mask
        const int4* mp = (const int4*)(mask + (size_t)b * kS * kS + (size_t)(q0 + t) * kS + k0);
        #pragma unroll
        for (int j4 = 0; j4 < 16; j4++) {
            int4 mv = mp[j4];
            if (mv.x == 0) sr[4*j4+0] = __float_as_uint(-1.0e9f);
            if (mv.y == 0) sr[4*j4+1] = __float_as_uint(-1.0e9f);
            if (mv.z == 0) sr[4*j4+2] = __float_as_uint(-1.0e9f);
            if (mv.w == 0) sr[4*j4+3] = __float_as_uint(-1.0e9f);
        }

        float rmax = -1e30f;
        #pragma unroll
        for (int j = 0; j < 64; j++) rmax = fmaxf(rmax, __uint_as_float(sr[j]));
        const float mnew = fmaxf(m_i, rmax);
        const float sc   = __expf(m_i - mnew);
        float rsum = 0.f;

        #pragma unroll
        for (int half = 0; half < 2; half++) {
            uint32_t qr[32];
            LDTM_X32(qr, TQV + 32 * half);
            asm volatile("tcgen05.wait::ld.sync.aligned;" ::: "memory");
            #pragma unroll
            for (int j = 0; j < 32; j++) {
                float p = __expf(__uint_as_float(sr[32*half + j]) - mnew);
                rsum += p;
                sr[32*half + j] = __float_as_uint(p * __uint_as_float(qr[j]));
            }
        }
        m_i = mnew;
        l_i = l_i * sc + rsum;

        // P hi/lo -> smem (Ph aliased into stage, Pl standalone)
        #pragma unroll
        for (int c = 0; c < 8; c++) {
            float f[8];
            #pragma unroll
            for (int j = 0; j < 8; j++) f[j] = __uint_as_float(sr[8*c + j]);
            uint4 uh = pack_hi8(f);
            uint4 ul = pack_lo8(f);
            uint32_t off = sw128((uint32_t)(t * 128 + c * 16));
            asm volatile("st.shared.v4.b32 [%0], {%1,%2,%3,%4};"
                         :: "r"(Ph + off), "r"(uh.x), "r"(uh.y), "r"(uh.z), "r"(uh.w) : "memory");
            asm volatile("st.shared.v4.b32 [%0], {%1,%2,%3,%4};"
                         :: "r"(Pl + off), "r"(ul.x), "r"(ul.y), "r"(ul.z), "r"(ul.w) : "memory");
        }
        #pragma unroll
        for (int c = 0; c < 64; c++) out[c] *= sc;

        asm volatile("tcgen05.fence::before_thread_sync;" ::: "memory");
        asm volatile("fence.proxy.async.shared::cta;" ::: "memory");
        __syncthreads();

        if (t == 0) {
            asm volatile("tcgen05.fence::after_thread_sync;" ::: "memory");
            const uint64_t dPh = mk_desc(Ph), dPl = mk_desc(Pl);
            const uint64_t dth = mk_desc(stg[st] + 24576), dtl = mk_desc(stg[st] + 32768);
            #pragma unroll
            for (int ks = 0; ks < 4; ks++) {
                mma_ss(TS, dPh + 2*ks, dth + 2*ks, AT_IDESC, ks > 0);
                mma_ss(TS, dPh + 2*ks, dtl + 2*ks, AT_IDESC, true);
                mma_ss(TS, dPl + 2*ks, dth + 2*ks, AT_IDESC, true);
            }
            asm volatile(
                "tcgen05.commit.cta_group::1.mbarrier::arrive::one.shared::cluster.b64 [%0];"
                :: "r"(mb_pk) : "memory");
        }
        mbar_wait(mb_pk, blk & 1);
        asm volatile("tcgen05.fence::after_thread_sync;" ::: "memory");

        uint32_t pr[64];
        LDTM_X32(pr, TS);
        LDTM_X32(pr + 32, TS + 32);
        asm volatile("tcgen05.wait::ld.sync.aligned;" ::: "memory");
        asm volatile("tcgen05.fence::before_thread_sync;" ::: "memory");
        __syncthreads();

        if (t == 0) {
            // refill this stage for blk+2 (overwrites Ph area — PK is done)
            if (blk + 2 < 16) {
                mbar_expect(mb_ld[st], 40960);
                const size_t off = (tb + blk + 2) * 4096;
                bulk_cp(stg[st] + 0,     (const char*)(krh + off), 8192, mb_ld[st]);
                bulk_cp(stg[st] + 8192,  (const char*)(krl + off), 8192, mb_ld[st]);
                bulk_cp(stg[st] + 16384, (const char*)(vrh + off), 8192, mb_ld[st]);
                bulk_cp(stg[st] + 24576, (const char*)(kth + off), 8192, mb_ld[st]);
                bulk_cp(stg[st] + 32768, (const char*)(ktl + off), 8192, mb_ld[st]);
            }
            // issue S/QV for blk+1
            if (blk + 1 < 16) {
                asm volatile("tcgen05.fence::after_thread_sync;" ::: "memory");
                mbar_wait(mb_ld[1 - st], ((blk + 1) >> 1) & 1);
                const uint32_t sb = stg[1 - st];
                const uint64_t dkh = mk_desc(sb), dkl = mk_desc(sb + 8192);
                const uint64_t dvh = mk_desc(sb + 16384);
                #pragma unroll
                for (int ks = 0; ks < 4; ks++) {
                    mma_ts(TS,  Q1H + ks*8, dkh + 2*ks, AT_IDESC, ks > 0);
                    mma_ts(TS,  Q1H + ks*8, dkl + 2*ks, AT_IDESC, true);
                    mma_ts(TS,  Q1L + ks*8, dkh + 2*ks, AT_IDESC, true);
                    mma_ts(TQV, Q2H + ks*8, dvh + 2*ks, AT_IDESC, ks > 0);
                    mma_ts(TQV, Q2L + ks*8, dvh + 2*ks, AT_IDESC, true);
                }
                asm volatile(
                    "tcgen05.commit.cta_group::1.mbarrier::arrive::one.shared::cluster.b64 [%0];"
                    :: "r"(mb_sq) : "memory");
            }
        }

        #pragma unroll
        for (int j = 0; j < 64; j++) out[j] += __uint_as_float(pr[j]);
    }

    const float inv = 1.0f / l_i;
    float4* op = (float4*)(outg + ((size_t)b * kS + q0 + t) * kDM + h * 64);
    #pragma unroll
    for (int c4 = 0; c4 < 16; c4++) {
        float4 v;
        v.x = out[4*c4+0] * inv; v.y = out[4*c4+1] * inv;
        v.z = out[4*c4+2] * inv; v.w = out[4*c4+3] * inv;
        op[c4] = v;
    }
    __syncthreads();
    if (wid == 0)
        asm volatile("tcgen05.dealloc.cta_group::1.sync.aligned.b32 %0, %1;"
                     :: "r"(tmem), "r"(256u));

#else  // ------- FFMA fallback (never runs on GB300) -------
    float q1r[64], q2r[64], out[64];
    for (int d = 0; d < 64; d++) {
        size_t idx = ((size_t)bh * kS + q0 + t) * kDK + d;
        q1r[d] = __bfloat162float(q1h[idx]) + __bfloat162float(q1l[idx]);
        q2r[d] = __bfloat162float(q2h[idx]) + __bfloat162float(q2l[idx]);
        out[d] = 0.f;
    }
    float m_i = -1e30f, l_i = 0.f;
    for (int j = 0; j < kS; j++) {
        const int blk = j >> 6, jr = j & 63;
        const size_t toff = ((size_t)bh * 16 + blk) * 4096;
        float s = 0.f, qv = 0.f;
        for (int d = 0; d < 64; d++) {
            uint32_t o = sw128((uint32_t)(jr * 128 + d * 2));
            float kr = __bfloat162float(*(const __nv_bfloat16*)((const char*)(krh + toff) + o))
                     + __bfloat162float(*(const __nv_bfloat16*)((const char*)(krl + toff) + o));
            float vr = __bfloat162float(*(const __nv_bfloat16*)((const char*)(vrh + toff) + o));
            s += q1r[d] * kr; qv += q2r[d] * vr;
        }
        if (mask[(size_t)b * kS * kS + (size_t)(q0 + t) * kS + j] == 0) s = -1.0e9f;
        float mnew = fmaxf(m_i, s);
        float scv = __expf(m_i - mnew), p = __expf(s - mnew);
        for (int d = 0; d < 64; d++) {
            uint32_t o = sw128((uint32_t)(d * 128 + jr * 2));
            float kv = __bfloat162float(*(const __nv_bfloat16*)((const char*)(kth + toff) + o))
                     + __bfloat162float(*(const __nv_bfloat16*)((const char*)(ktl + toff) + o));
            out[d] = out[d] * scv + p * qv * kv;
        }
        l_i = l_i * scv + p;
        m_i = mnew;
    }
    const float inv = 1.0f / l_i;
    for (int d = 0; d < 64; d++)
        outg[((size_t)b * kS + q0 + t) * kDM + h * 64 + d] = out[d] * inv;
#endif
}

// ---------------------------------------------------------------------------
extern "C" void kernel_launch(void* const* d_in, const int* in_sizes, int n_in,
                              void* d_out, int out_size)
{
    (void)in_sizes; (void)n_in; (void)out_size;
    const float* query = (const float*)d_in[0];
    const float* key_  = (const float*)d_in[1];
    const float* value = (const float*)d_in[2];
    const int*   mask  = (const int*)  d_in[3];
    const float* Wq  = (const float*)d_in[4];  const float* bq  = (const float*)d_in[5];
    const float* Wk  = (const float*)d_in[6];  const float* bk  = (const float*)d_in[7];
    const float* Wv  = (const float*)d_in[8];  const float* bv  = (const float*)d_in[9];
    const float* Wo  = (const float*)d_in[10]; const float* bo  = (const float*)d_in[11];
    const float* Wkl = (const float*)d_in[12]; const float* bkl = (const float*)d_in[13];
    const float* Wql = (const float*)d_in[14]; const float* bql = (const float*)d_in[15];
    const float* Wq2 = (const float*)d_in[16]; const float* bq2 = (const float*)d_in[17];
    const float* Wvl = (const float*)d_in[18]; const float* bvl = (const float*)d_in[19];
    const float* Wel = (const float*)d_in[20]; const float* bel = (const float*)d_in[21];

    float *qh, *kh, *vh, *att;
    __nv_bfloat16 *krh, *krl, *vrh, *kth, *ktl, *q1h, *q1l, *q2h, *q2l;
    cudaGetSymbolAddress((void**)&qh,  g_qh);
    cudaGetSymbolAddress((void**)&kh,  g_kh);
    cudaGetSymbolAddress((void**)&vh,  g_vh);
    cudaGetSymbolAddress((void**)&att, g_att);
    cudaGetSymbolAddress((void**)&krh, g_krh);
    cudaGetSymbolAddress((void**)&krl, g_krl);
    cudaGetSymbolAddress((void**)&vrh, g_vrh);
    cudaGetSymbolAddress((void**)&kth, g_kth);
    cudaGetSymbolAddress((void**)&ktl, g_ktl);
    cudaGetSymbolAddress((void**)&q1h, g_q1h);
    cudaGetSymbolAddress((void**)&q1l, g_q1l);
    cudaGetSymbolAddress((void**)&q2h, g_q2h);
    cudaGetSymbolAddress((void**)&q2l, g_q2l);

    const int GEMM_SMEM = 66560;
    cudaFuncSetAttribute(tc_gemm, cudaFuncAttributeMaxDynamicSharedMemorySize, GEMM_SMEM);

    dim3 gg(8, 32);

    tc_gemm<<<gg, 256, GEMM_SMEM>>>(query, Wq, bq, qh, 1);
    tc_gemm<<<gg, 256, GEMM_SMEM>>>(key_,  Wk, bk, kh, 1);
    tc_gemm<<<gg, 256, GEMM_SMEM>>>(value, Wv, bv, vh, 1);

    const int CK_SMEM = 4 * 4096 * 4;
    const int FQ_SMEM = (4096 + 64*65 + 3*4096 + 4096) * 4;
    cudaFuncSetAttribute(conv_kv, cudaFuncAttributeMaxDynamicSharedMemorySize, CK_SMEM);
    cudaFuncSetAttribute(fused_q, cudaFuncAttributeMaxDynamicSharedMemorySize, FQ_SMEM);
    conv_kv<<<1024, 256, CK_SMEM>>>(kh, vh, Wkl, bkl, Wvl, bvl, krh, krl, vrh, kth, ktl);
    fused_q<<<1024, 256, FQ_SMEM>>>(qh, Wql, bql, Wel, bel, Wq2, bq2, q1h, q1l, q2h, q2l);

    const int ATT_SMEM = 99328;   // 2 stages (80KB) + Pl (16KB) + align; Ph aliased
    cudaFuncSetAttribute(attn_tc, cudaFuncAttributeMaxDynamicSharedMemorySize, ATT_SMEM);
    attn_tc<<<dim3(8, 64), 128, ATT_SMEM>>>(q1h, q1l, q2h, q2l,
                                            krh, krl, vrh, kth, ktl, mask, att);

    tc_gemm<<<gg, 256, GEMM_SMEM>>>(att, Wo, bo, (float*)d_out, 0);
}